// round 3
// baseline (speedup 1.0000x reference)
#include <cuda_runtime.h>
#include <math.h>

#define Bv 2
#define Tv 2048
#define Cv 1024
#define Hv 16
#define DHv 64
#define Mv (Bv*Tv)       // 4096 rows
#define NCHUNK 32        // T / 64
#define Lv 64            // chunk length

// ---------------- scratch (static device memory; no allocs) ----------------
__device__ float g_q[Mv*Cv];
__device__ float g_k[Mv*Cv];
__device__ float g_v[Mv*Cv];
__device__ float g_G[Bv*Hv*NCHUNK*DHv*DHv];   // per-chunk local states
__device__ float g_S[Bv*Hv*NCHUNK*DHv*DHv];   // scanned prefix states
__device__ float g_att[Mv*Cv];                // normalized retention output

// ---------------- SGEMM: C[M,N] = A[M,K] * B[N,K]^T (all row-major) --------
#define BMg 128
#define BNg 128
#define BKg 16

__global__ __launch_bounds__(256, 2)
void sgemm_nt(const float* __restrict__ A, const float* __restrict__ B,
              float* __restrict__ C, int M, int N, int K)
{
    __shared__ float As[BKg][BMg];
    __shared__ float Bs[BKg][BNg];
    const int tid  = threadIdx.x;
    const int trow = tid >> 4;    // 0..15
    const int tcol = tid & 15;    // 0..15
    const int lrow = tid >> 2;    // 0..63
    const int lq   = tid & 3;     // 0..3

    const float* Ab = A + (size_t)blockIdx.y * BMg * K;
    const float* Bb = B + (size_t)blockIdx.x * BNg * K;

    float acc[8][8];
    #pragma unroll
    for (int i = 0; i < 8; ++i)
        #pragma unroll
        for (int j = 0; j < 8; ++j) acc[i][j] = 0.f;

    for (int k0 = 0; k0 < K; k0 += BKg) {
        #pragma unroll
        for (int r = 0; r < 2; ++r) {
            int row = lrow + r*64;
            float4 va = *(const float4*)(Ab + (size_t)row*K + k0 + lq*4);
            As[lq*4+0][row] = va.x; As[lq*4+1][row] = va.y;
            As[lq*4+2][row] = va.z; As[lq*4+3][row] = va.w;
            float4 vb = *(const float4*)(Bb + (size_t)row*K + k0 + lq*4);
            Bs[lq*4+0][row] = vb.x; Bs[lq*4+1][row] = vb.y;
            Bs[lq*4+2][row] = vb.z; Bs[lq*4+3][row] = vb.w;
        }
        __syncthreads();
        #pragma unroll
        for (int kk = 0; kk < BKg; ++kk) {
            float a[8], b[8];
            *(float4*)&a[0] = *(const float4*)&As[kk][trow*8];
            *(float4*)&a[4] = *(const float4*)&As[kk][trow*8+4];
            *(float4*)&b[0] = *(const float4*)&Bs[kk][tcol*8];
            *(float4*)&b[4] = *(const float4*)&Bs[kk][tcol*8+4];
            #pragma unroll
            for (int i = 0; i < 8; ++i)
                #pragma unroll
                for (int j = 0; j < 8; ++j)
                    acc[i][j] = fmaf(a[i], b[j], acc[i][j]);
        }
        __syncthreads();
    }
    float* Cb = C + (size_t)(blockIdx.y*BMg + trow*8) * N + blockIdx.x*BNg + tcol*8;
    #pragma unroll
    for (int i = 0; i < 8; ++i) {
        *(float4*)(Cb + (size_t)i*N)     = make_float4(acc[i][0],acc[i][1],acc[i][2],acc[i][3]);
        *(float4*)(Cb + (size_t)i*N + 4) = make_float4(acc[i][4],acc[i][5],acc[i][6],acc[i][7]);
    }
}

// ---------------- RoPE on q,k in-place ([B,T,H,DH] == [M, C]) --------------
__global__ void rope_kernel()
{
    int idx = blockIdx.x*blockDim.x + threadIdx.x;   // B*T*H*32 pairs
    if (idx >= Bv*Tv*Hv*32) return;
    int d  = idx & 31;
    int h  = (idx >> 5) & (Hv-1);
    int bt = idx >> 9;
    int t  = bt & (Tv-1);
    // inv_freq = 10000^{-d/32}
    float inv = exp2f(-(float)d * (13.287712379549449f / 32.0f));
    float ang = (float)t * inv;
    float s, c;
    sincosf(ang, &s, &c);
    size_t base = (size_t)bt*Cv + h*DHv + d;
    float q1 = g_q[base], q2 = g_q[base+32];
    g_q[base]    = q1*c - q2*s;
    g_q[base+32] = q2*c + q1*s;
    float k1 = g_k[base], k2 = g_k[base+32];
    g_k[base]    = k1*c - k2*s;
    g_k[base+32] = k2*c + k1*s;
}

// ---------------- Pass 1: per-chunk local state G_c = sum_j g^{L-j} k_j v_j^T
__global__ __launch_bounds__(256)
void ret_pass1()
{
    __shared__ float sK[64*64];   // [j][dk], pre-scaled by gamma^{64-j}
    __shared__ float sV[64*64];   // [j][dv]
    const int blk = blockIdx.x;               // (b*16 + h)*32 + c
    const int c   = blk & 31;
    const int h   = (blk >> 5) & 15;
    const int b   = blk >> 9;
    const int tid = threadIdx.x;
    const float gamma = 1.0f - exp2f(-5.0f - (float)h);
    const float lg = log2f(gamma);
    const size_t rowbase = ((size_t)(b*Tv + c*64))*Cv + (size_t)h*64;
    const int fq = tid & 15;
    for (int r = tid >> 4; r < 64; r += 16) {
        float w = exp2f((float)(64 - r) * lg);
        float4 kv = *(const float4*)(g_k + rowbase + (size_t)r*Cv + fq*4);
        kv.x *= w; kv.y *= w; kv.z *= w; kv.w *= w;
        *(float4*)&sK[r*64 + fq*4] = kv;
        *(float4*)&sV[r*64 + fq*4] = *(const float4*)(g_v + rowbase + (size_t)r*Cv + fq*4);
    }
    __syncthreads();
    const int dk  = tid >> 2;
    const int dvb = (tid & 3) * 16;
    float acc[16];
    #pragma unroll
    for (int u = 0; u < 16; ++u) acc[u] = 0.f;
    #pragma unroll 8
    for (int j = 0; j < 64; ++j) {
        float kv = sK[j*64 + dk];
        const float4* vp = (const float4*)&sV[j*64 + dvb];
        float4 v0 = vp[0], v1 = vp[1], v2 = vp[2], v3 = vp[3];
        acc[0]  = fmaf(kv, v0.x, acc[0]);  acc[1]  = fmaf(kv, v0.y, acc[1]);
        acc[2]  = fmaf(kv, v0.z, acc[2]);  acc[3]  = fmaf(kv, v0.w, acc[3]);
        acc[4]  = fmaf(kv, v1.x, acc[4]);  acc[5]  = fmaf(kv, v1.y, acc[5]);
        acc[6]  = fmaf(kv, v1.z, acc[6]);  acc[7]  = fmaf(kv, v1.w, acc[7]);
        acc[8]  = fmaf(kv, v2.x, acc[8]);  acc[9]  = fmaf(kv, v2.y, acc[9]);
        acc[10] = fmaf(kv, v2.z, acc[10]); acc[11] = fmaf(kv, v2.w, acc[11]);
        acc[12] = fmaf(kv, v3.x, acc[12]); acc[13] = fmaf(kv, v3.y, acc[13]);
        acc[14] = fmaf(kv, v3.z, acc[14]); acc[15] = fmaf(kv, v3.w, acc[15]);
    }
    float* Gp = g_G + ((size_t)blk*64 + dk)*64 + dvb;
    #pragma unroll
    for (int u = 0; u < 16; u += 4)
        *(float4*)(Gp + u) = make_float4(acc[u], acc[u+1], acc[u+2], acc[u+3]);
}

// ---------------- Pass 2: sequential scan of states per (b,h) --------------
__global__ void ret_pass2()
{
    const int bh  = blockIdx.x;    // 32 blocks
    const int tid = threadIdx.x;   // 256
    const int h   = bh & 15;
    const float gamma = 1.0f - exp2f(-5.0f - (float)h);
    const float gL = exp2f(64.0f * log2f(gamma));
    float s[16];
    #pragma unroll
    for (int u = 0; u < 16; ++u) s[u] = 0.f;
    for (int c = 0; c < NCHUNK; ++c) {
        size_t base = ((size_t)bh*NCHUNK + c)*4096;
        #pragma unroll
        for (int u = 0; u < 16; ++u) {
            size_t e = base + (size_t)u*256 + tid;
            g_S[e] = s[u];                       // state BEFORE chunk c
            s[u] = fmaf(gL, s[u], g_G[e]);
        }
    }
}

// ---------------- Pass 3: intra-chunk + cross + fused GroupNorm ------------
__global__ __launch_bounds__(256)
void ret_pass3(const float* __restrict__ gnw, const float* __restrict__ gnb)
{
    __shared__ float sQt[64*64];  // Q^T * 0.125   [d][i]
    __shared__ float sT[64*64];   // K^T [d][j], then S [dk][dv]
    __shared__ float sA[64*64];   // A^T [j][i]
    const int blk = blockIdx.x;
    const int c   = blk & 31;
    const int h   = (blk >> 5) & 15;
    const int b   = blk >> 9;
    const int tid = threadIdx.x;
    const float gamma = 1.0f - exp2f(-5.0f - (float)h);
    const float lg = log2f(gamma);
    const size_t rowbase = ((size_t)(b*Tv + c*64))*Cv + (size_t)h*64;
    const int fq = tid & 15;

    for (int r = tid >> 4; r < 64; r += 16) {
        float4 qv = *(const float4*)(g_q + rowbase + (size_t)r*Cv + fq*4);
        float4 kv = *(const float4*)(g_k + rowbase + (size_t)r*Cv + fq*4);
        int d0 = fq*4;
        sQt[(d0+0)*64 + r] = 0.125f*qv.x;
        sQt[(d0+1)*64 + r] = 0.125f*qv.y;
        sQt[(d0+2)*64 + r] = 0.125f*qv.z;
        sQt[(d0+3)*64 + r] = 0.125f*qv.w;
        sT[(d0+0)*64 + r] = kv.x;
        sT[(d0+1)*64 + r] = kv.y;
        sT[(d0+2)*64 + r] = kv.z;
        sT[(d0+3)*64 + r] = kv.w;
    }
    __syncthreads();

    const int i  = tid >> 2;          // local token (row)
    const int jb = (tid & 3) * 16;    // col block (16 cols)

    // A[i][j] = 0.125 * (q_i . k_j) * gamma^{i-j}  (causal)
    float a[16];
    #pragma unroll
    for (int u = 0; u < 16; ++u) a[u] = 0.f;
    #pragma unroll 8
    for (int d = 0; d < 64; ++d) {
        float qv = sQt[d*64 + i];
        const float4* tp = (const float4*)&sT[d*64 + jb];
        float4 t0 = tp[0], t1 = tp[1], t2 = tp[2], t3 = tp[3];
        a[0]  = fmaf(qv, t0.x, a[0]);  a[1]  = fmaf(qv, t0.y, a[1]);
        a[2]  = fmaf(qv, t0.z, a[2]);  a[3]  = fmaf(qv, t0.w, a[3]);
        a[4]  = fmaf(qv, t1.x, a[4]);  a[5]  = fmaf(qv, t1.y, a[5]);
        a[6]  = fmaf(qv, t1.z, a[6]);  a[7]  = fmaf(qv, t1.w, a[7]);
        a[8]  = fmaf(qv, t2.x, a[8]);  a[9]  = fmaf(qv, t2.y, a[9]);
        a[10] = fmaf(qv, t2.z, a[10]); a[11] = fmaf(qv, t2.w, a[11]);
        a[12] = fmaf(qv, t3.x, a[12]); a[13] = fmaf(qv, t3.y, a[13]);
        a[14] = fmaf(qv, t3.z, a[14]); a[15] = fmaf(qv, t3.w, a[15]);
    }
    #pragma unroll
    for (int u = 0; u < 16; ++u) {
        int j = jb + u;
        float dec = (j <= i) ? exp2f((float)(i - j) * lg) : 0.f;
        sA[j*64 + i] = a[u] * dec;     // store A^T
    }
    __syncthreads();

    // load S_c (state before this chunk) into sT
    const float* Sp = g_S + (size_t)blk*4096;
    for (int e = tid*4; e < 4096; e += 1024)
        *(float4*)&sT[e] = *(const float4*)&Sp[e];
    __syncthreads();

    // cross term: gamma^i * (q_i @ S)
    const int dvb = jb;
    float o[16];
    #pragma unroll
    for (int u = 0; u < 16; ++u) o[u] = 0.f;
    #pragma unroll 8
    for (int d = 0; d < 64; ++d) {
        float qv = sQt[d*64 + i];
        const float4* sp = (const float4*)&sT[d*64 + dvb];
        float4 s0 = sp[0], s1 = sp[1], s2 = sp[2], s3 = sp[3];
        o[0]  = fmaf(qv, s0.x, o[0]);  o[1]  = fmaf(qv, s0.y, o[1]);
        o[2]  = fmaf(qv, s0.z, o[2]);  o[3]  = fmaf(qv, s0.w, o[3]);
        o[4]  = fmaf(qv, s1.x, o[4]);  o[5]  = fmaf(qv, s1.y, o[5]);
        o[6]  = fmaf(qv, s1.z, o[6]);  o[7]  = fmaf(qv, s1.w, o[7]);
        o[8]  = fmaf(qv, s2.x, o[8]);  o[9]  = fmaf(qv, s2.y, o[9]);
        o[10] = fmaf(qv, s2.z, o[10]); o[11] = fmaf(qv, s2.w, o[11]);
        o[12] = fmaf(qv, s3.x, o[12]); o[13] = fmaf(qv, s3.y, o[13]);
        o[14] = fmaf(qv, s3.z, o[14]); o[15] = fmaf(qv, s3.w, o[15]);
    }
    {
        float cd = exp2f((float)i * lg);
        #pragma unroll
        for (int u = 0; u < 16; ++u) o[u] *= cd;
    }
    __syncthreads();

    // load V into sQt (Q no longer needed)
    for (int r = tid >> 4; r < 64; r += 16)
        *(float4*)&sQt[r*64 + fq*4] = *(const float4*)(g_v + rowbase + (size_t)r*Cv + fq*4);
    __syncthreads();

    // o += A @ V
    #pragma unroll 8
    for (int s = 0; s < 64; ++s) {
        float av = sA[s*64 + i];
        const float4* vp = (const float4*)&sQt[s*64 + dvb];
        float4 v0 = vp[0], v1 = vp[1], v2 = vp[2], v3 = vp[3];
        o[0]  = fmaf(av, v0.x, o[0]);  o[1]  = fmaf(av, v0.y, o[1]);
        o[2]  = fmaf(av, v0.z, o[2]);  o[3]  = fmaf(av, v0.w, o[3]);
        o[4]  = fmaf(av, v1.x, o[4]);  o[5]  = fmaf(av, v1.y, o[5]);
        o[6]  = fmaf(av, v1.z, o[6]);  o[7]  = fmaf(av, v1.w, o[7]);
        o[8]  = fmaf(av, v2.x, o[8]);  o[9]  = fmaf(av, v2.y, o[9]);
        o[10] = fmaf(av, v2.z, o[10]); o[11] = fmaf(av, v2.w, o[11]);
        o[12] = fmaf(av, v3.x, o[12]); o[13] = fmaf(av, v3.y, o[13]);
        o[14] = fmaf(av, v3.z, o[14]); o[15] = fmaf(av, v3.w, o[15]);
    }

    // GroupNorm over DH=64 per (b,t,h): 4 lanes (tid&3) own the row
    float sum = 0.f;
    #pragma unroll
    for (int u = 0; u < 16; ++u) sum += o[u];
    sum += __shfl_xor_sync(0xffffffffu, sum, 1);
    sum += __shfl_xor_sync(0xffffffffu, sum, 2);
    float mean = sum * (1.0f/64.0f);
    float sq = 0.f;
    #pragma unroll
    for (int u = 0; u < 16; ++u) { float dd = o[u] - mean; sq = fmaf(dd, dd, sq); }
    sq += __shfl_xor_sync(0xffffffffu, sq, 1);
    sq += __shfl_xor_sync(0xffffffffu, sq, 2);
    float rstd = rsqrtf(sq * (1.0f/64.0f) + 1e-5f);

    float* op = g_att + ((size_t)(b*Tv + c*64 + i))*Cv + (size_t)h*64 + dvb;
    const float* wg = gnw + h*64 + dvb;
    const float* bg = gnb + h*64 + dvb;
    #pragma unroll
    for (int u = 0; u < 16; u += 4) {
        float4 r;
        r.x = fmaf((o[u+0]-mean)*rstd, wg[u+0], bg[u+0]);
        r.y = fmaf((o[u+1]-mean)*rstd, wg[u+1], bg[u+1]);
        r.z = fmaf((o[u+2]-mean)*rstd, wg[u+2], bg[u+2]);
        r.w = fmaf((o[u+3]-mean)*rstd, wg[u+3], bg[u+3]);
        *(float4*)(op + u) = r;
    }
}

// ---------------------------------------------------------------------------
extern "C" void kernel_launch(void* const* d_in, const int* in_sizes, int n_in,
                              void* d_out, int out_size)
{
    const float* x   = (const float*)d_in[0];
    const float* Wq  = (const float*)d_in[1];
    const float* Wk  = (const float*)d_in[2];
    const float* Wv  = (const float*)d_in[3];
    const float* Wo  = (const float*)d_in[4];
    const float* gnw = (const float*)d_in[5];
    const float* gnb = (const float*)d_in[6];
    float* out = (float*)d_out;

    float *q, *k, *v, *att;
    cudaGetSymbolAddress((void**)&q,   g_q);
    cudaGetSymbolAddress((void**)&k,   g_k);
    cudaGetSymbolAddress((void**)&v,   g_v);
    cudaGetSymbolAddress((void**)&att, g_att);

    dim3 ggrid(Cv/BNg, Mv/BMg);   // (8, 32)
    sgemm_nt<<<ggrid, 256>>>(x, Wq, q, Mv, Cv, Cv);
    sgemm_nt<<<ggrid, 256>>>(x, Wk, k, Mv, Cv, Cv);
    sgemm_nt<<<ggrid, 256>>>(x, Wv, v, Mv, Cv, Cv);
    rope_kernel<<<(Bv*Tv*Hv*32)/256, 256>>>();
    ret_pass1<<<Bv*Hv*NCHUNK, 256>>>();
    ret_pass2<<<Bv*Hv, 256>>>();
    ret_pass3<<<Bv*Hv*NCHUNK, 256>>>(gnw, gnb);
    sgemm_nt<<<ggrid, 256>>>(att, Wo, out, Mv, Cv, Cv);
}

// round 6
// speedup vs baseline: 1.9384x; 1.9384x over previous
#include <cuda_runtime.h>
#include <cuda_bf16.h>
#include <math.h>
#include <stdint.h>

#define Bv 2
#define Tv 2048
#define Cv 1024
#define Hv 16
#define DHv 64
#define Mv (Bv*Tv)       // 4096 rows
#define NCHUNK 32        // T / 64

// ---------------- scratch (static device memory; no allocs) ----------------
__device__ float g_q[Mv*Cv];
__device__ float g_k[Mv*Cv];
__device__ float g_v[Mv*Cv];
__device__ float g_G[Bv*Hv*NCHUNK*DHv*DHv];
__device__ float g_S[Bv*Hv*NCHUNK*DHv*DHv];
__device__ float g_att[Mv*Cv];

__device__ __align__(256) __nv_bfloat16 g_xh[Mv*Cv], g_xl[Mv*Cv];       // split x
__device__ __align__(256) __nv_bfloat16 g_ah[Mv*Cv], g_al[Mv*Cv];       // split att
__device__ __align__(256) __nv_bfloat16 g_wh[4][Cv*Cv], g_wl[4][Cv*Cv]; // split W

// ======================= helpers ===========================================
__device__ __forceinline__ uint32_t smem_to_u32(const void* p) {
    uint32_t a;
    asm("{ .reg .u64 t; cvta.to.shared.u64 t, %1; cvt.u32.u64 %0, t; }" : "=r"(a) : "l"(p));
    return a;
}
__device__ __forceinline__ void ldmatrix_x4(uint32_t* r, uint32_t addr) {
    asm volatile("ldmatrix.sync.aligned.m8n8.x4.shared.b16 {%0,%1,%2,%3}, [%4];"
                 : "=r"(r[0]), "=r"(r[1]), "=r"(r[2]), "=r"(r[3]) : "r"(addr));
}
__device__ __forceinline__ void mma16816(float* d, const uint32_t* a, uint32_t b0, uint32_t b1) {
    asm volatile(
        "mma.sync.aligned.m16n8k16.row.col.f32.bf16.bf16.f32 "
        "{%0,%1,%2,%3}, {%4,%5,%6,%7}, {%8,%9}, {%0,%1,%2,%3};"
        : "+f"(d[0]), "+f"(d[1]), "+f"(d[2]), "+f"(d[3])
        : "r"(a[0]), "r"(a[1]), "r"(a[2]), "r"(a[3]), "r"(b0), "r"(b1));
}

// =================== split fp32 -> bf16 hi/lo ==============================
__global__ void split_kernel(const float* __restrict__ s,
                             __nv_bfloat16* __restrict__ hi,
                             __nv_bfloat16* __restrict__ lo, int n4)
{
    int i = blockIdx.x*blockDim.x + threadIdx.x;
    if (i >= n4) return;
    float4 f = ((const float4*)s)[i];
    __nv_bfloat16 h0 = __float2bfloat16(f.x);
    __nv_bfloat16 h1 = __float2bfloat16(f.y);
    __nv_bfloat16 h2 = __float2bfloat16(f.z);
    __nv_bfloat16 h3 = __float2bfloat16(f.w);
    __nv_bfloat16 l0 = __float2bfloat16(f.x - __bfloat162float(h0));
    __nv_bfloat16 l1 = __float2bfloat16(f.y - __bfloat162float(h1));
    __nv_bfloat16 l2 = __float2bfloat16(f.z - __bfloat162float(h2));
    __nv_bfloat16 l3 = __float2bfloat16(f.w - __bfloat162float(h3));
    __nv_bfloat162* hp = (__nv_bfloat162*)(hi + (size_t)i*4);
    __nv_bfloat162* lp = (__nv_bfloat162*)(lo + (size_t)i*4);
    hp[0] = __nv_bfloat162(h0, h1); hp[1] = __nv_bfloat162(h2, h3);
    lp[0] = __nv_bfloat162(l0, l1); lp[1] = __nv_bfloat162(l2, l3);
}

// =================== split-bf16 mma.sync GEMM ==============================
// C[M,N] = A[M,K] * B[N,K]^T  via  Ahi*Bhi + Ahi*Blo + Alo*Bhi
// CTA tile 128x128, K-chunk 64 bf16 (128B swizzled rows), double-buffered
// cp.async pipeline. Warp grid 2(M) x 4(N): warp tile 64x32.
#define GTILE_SZ 16384          // 128 rows x 128 bytes
#define GBUF_SZ  (4*GTILE_SZ)   // Ahi, Alo, Bhi, Blo
#define GSMEM_TOTAL (2*GBUF_SZ) // 131072

__global__ __launch_bounds__(256, 1)
void gemm_split_mma(const __nv_bfloat16* __restrict__ Ah,
                    const __nv_bfloat16* __restrict__ Al,
                    const __nv_bfloat16* __restrict__ Bh,
                    const __nv_bfloat16* __restrict__ Bl,
                    float* __restrict__ C, int N, int K)
{
    extern __shared__ char smem[];
    const uint32_t sb = smem_to_u32(smem);
    const int tid  = threadIdx.x;
    const int lane = tid & 31;
    const int wid  = tid >> 5;
    const int wm   = wid & 1;     // 2 warps along M
    const int wn   = wid >> 1;    // 4 warps along N

    const size_t rowA0 = (size_t)blockIdx.y * 128;
    const size_t rowB0 = (size_t)blockIdx.x * 128;
    const __nv_bfloat16* tps[4] = { Ah + rowA0*K, Al + rowA0*K,
                                    Bh + rowB0*K, Bl + rowB0*K };

    // ---- cp.async chunk loader: 4 tiles of 128 rows x 64 bf16, swizzled ----
    auto load_chunk = [&](int k0, int b) {
        const uint32_t dst = sb + b * GBUF_SZ;
        #pragma unroll
        for (int t = 0; t < 4; ++t) {
            const __nv_bfloat16* gp = tps[t] + k0;
            const uint32_t td = dst + t * GTILE_SZ;
            #pragma unroll
            for (int i = 0; i < 4; ++i) {
                int v = tid + i * 256;          // 0..1023
                int row = v >> 3, colv = v & 7; // 8 x 16B per 128B row
                uint32_t boff = row * 128 + colv * 16;
                uint32_t sw = boff ^ ((boff >> 3) & 0x70);
                const void* src = gp + (size_t)row * K + colv * 8;
                asm volatile("cp.async.cg.shared.global [%0], [%1], 16;"
                             :: "r"(td + sw), "l"(src) : "memory");
            }
        }
        asm volatile("cp.async.commit_group;" ::: "memory");
    };

    float acc[4][4][4];
    #pragma unroll
    for (int mt = 0; mt < 4; ++mt)
        #pragma unroll
        for (int nt = 0; nt < 4; ++nt)
            #pragma unroll
            for (int u = 0; u < 4; ++u) acc[mt][nt][u] = 0.f;

    // per-lane ldmatrix geometry
    const int  a_r    = lane & 15;                          // row within 16
    const uint32_t a_hi = (uint32_t)(lane >> 4) * 16;       // k-half (bytes)
    const int  b_r    = (lane & 7) + ((lane >> 4) << 3);    // row within 16
    const uint32_t b_hi = (uint32_t)((lane >> 3) & 1) * 16; // k-half (bytes)

    load_chunk(0, 0);

    for (int c = 0; c < 16; ++c) {
        if (c + 1 < 16) {
            load_chunk((c + 1) * 64, (c + 1) & 1);
            asm volatile("cp.async.wait_group 1;" ::: "memory");
        } else {
            asm volatile("cp.async.wait_group 0;" ::: "memory");
        }
        __syncthreads();

        const uint32_t base = sb + (c & 1) * GBUF_SZ;
        const uint32_t aH = base, aL = base + GTILE_SZ;
        const uint32_t bH = base + 2*GTILE_SZ, bL = base + 3*GTILE_SZ;

        #pragma unroll
        for (int ks = 0; ks < 4; ++ks) {
            const uint32_t kb = ks * 32;   // 16 k * 2B
            uint32_t ah[4][4], al[4][4], bh[2][4], bl[2][4];
            #pragma unroll
            for (int mt = 0; mt < 4; ++mt) {
                int row = wm*64 + mt*16 + a_r;
                uint32_t off = (uint32_t)row*128 + (((kb + a_hi) ^ ((row & 7) << 4)));
                ldmatrix_x4(ah[mt], aH + off);
                ldmatrix_x4(al[mt], aL + off);
            }
            #pragma unroll
            for (int ntp = 0; ntp < 2; ++ntp) {
                int row = wn*32 + ntp*16 + b_r;
                uint32_t off = (uint32_t)row*128 + (((kb + b_hi) ^ ((row & 7) << 4)));
                ldmatrix_x4(bh[ntp], bH + off);
                ldmatrix_x4(bl[ntp], bL + off);
            }
            #pragma unroll
            for (int mt = 0; mt < 4; ++mt) {
                #pragma unroll
                for (int nt = 0; nt < 4; ++nt) {
                    uint32_t bh0 = bh[nt >> 1][(nt & 1)*2 + 0];
                    uint32_t bh1 = bh[nt >> 1][(nt & 1)*2 + 1];
                    uint32_t bl0 = bl[nt >> 1][(nt & 1)*2 + 0];
                    uint32_t bl1 = bl[nt >> 1][(nt & 1)*2 + 1];
                    mma16816(acc[mt][nt], ah[mt], bh0, bh1);
                    mma16816(acc[mt][nt], ah[mt], bl0, bl1);
                    mma16816(acc[mt][nt], al[mt], bh0, bh1);
                }
            }
        }
        __syncthreads();
    }

    // ---- epilogue: direct register -> global stores ----
    #pragma unroll
    for (int mt = 0; mt < 4; ++mt) {
        int r0 = (int)rowA0 + wm*64 + mt*16 + (lane >> 2);
        #pragma unroll
        for (int nt = 0; nt < 4; ++nt) {
            int col = (int)rowB0 + wn*32 + nt*8 + 2*(lane & 3);
            float2 v0 = make_float2(acc[mt][nt][0], acc[mt][nt][1]);
            float2 v1 = make_float2(acc[mt][nt][2], acc[mt][nt][3]);
            *(float2*)(C + (size_t)r0 * N + col)       = v0;
            *(float2*)(C + (size_t)(r0 + 8) * N + col) = v1;
        }
    }
}

// ---------------- RoPE on q,k in-place ([B,T,H,DH] == [M, C]) --------------
__global__ void rope_kernel()
{
    int idx = blockIdx.x*blockDim.x + threadIdx.x;
    if (idx >= Bv*Tv*Hv*32) return;
    int d  = idx & 31;
    int h  = (idx >> 5) & (Hv-1);
    int bt = idx >> 9;
    int t  = bt & (Tv-1);
    float inv = exp2f(-(float)d * (13.287712379549449f / 32.0f));
    float ang = (float)t * inv;
    float s, c;
    sincosf(ang, &s, &c);
    size_t base = (size_t)bt*Cv + h*DHv + d;
    float q1 = g_q[base], q2 = g_q[base+32];
    g_q[base]    = q1*c - q2*s;
    g_q[base+32] = q2*c + q1*s;
    float k1 = g_k[base], k2 = g_k[base+32];
    g_k[base]    = k1*c - k2*s;
    g_k[base+32] = k2*c + k1*s;
}

// ---------------- Pass 1: per-chunk local state ----------------------------
__global__ __launch_bounds__(256)
void ret_pass1()
{
    __shared__ float sK[64*64];
    __shared__ float sV[64*64];
    const int blk = blockIdx.x;
    const int c   = blk & 31;
    const int h   = (blk >> 5) & 15;
    const int b   = blk >> 9;
    const int tid = threadIdx.x;
    const float gamma = 1.0f - exp2f(-5.0f - (float)h);
    const float lg = log2f(gamma);
    const size_t rowbase = ((size_t)(b*Tv + c*64))*Cv + (size_t)h*64;
    const int fq = tid & 15;
    for (int r = tid >> 4; r < 64; r += 16) {
        float w = exp2f((float)(64 - r) * lg);
        float4 kv = *(const float4*)(g_k + rowbase + (size_t)r*Cv + fq*4);
        kv.x *= w; kv.y *= w; kv.z *= w; kv.w *= w;
        *(float4*)&sK[r*64 + fq*4] = kv;
        *(float4*)&sV[r*64 + fq*4] = *(const float4*)(g_v + rowbase + (size_t)r*Cv + fq*4);
    }
    __syncthreads();
    const int dk  = tid >> 2;
    const int dvb = (tid & 3) * 16;
    float acc[16];
    #pragma unroll
    for (int u = 0; u < 16; ++u) acc[u] = 0.f;
    #pragma unroll 8
    for (int j = 0; j < 64; ++j) {
        float kv = sK[j*64 + dk];
        const float4* vp = (const float4*)&sV[j*64 + dvb];
        float4 v0 = vp[0], v1 = vp[1], v2 = vp[2], v3 = vp[3];
        acc[0]  = fmaf(kv, v0.x, acc[0]);  acc[1]  = fmaf(kv, v0.y, acc[1]);
        acc[2]  = fmaf(kv, v0.z, acc[2]);  acc[3]  = fmaf(kv, v0.w, acc[3]);
        acc[4]  = fmaf(kv, v1.x, acc[4]);  acc[5]  = fmaf(kv, v1.y, acc[5]);
        acc[6]  = fmaf(kv, v1.z, acc[6]);  acc[7]  = fmaf(kv, v1.w, acc[7]);
        acc[8]  = fmaf(kv, v2.x, acc[8]);  acc[9]  = fmaf(kv, v2.y, acc[9]);
        acc[10] = fmaf(kv, v2.z, acc[10]); acc[11] = fmaf(kv, v2.w, acc[11]);
        acc[12] = fmaf(kv, v3.x, acc[12]); acc[13] = fmaf(kv, v3.y, acc[13]);
        acc[14] = fmaf(kv, v3.z, acc[14]); acc[15] = fmaf(kv, v3.w, acc[15]);
    }
    float* Gp = g_G + ((size_t)blk*64 + dk)*64 + dvb;
    #pragma unroll
    for (int u = 0; u < 16; u += 4)
        *(float4*)(Gp + u) = make_float4(acc[u], acc[u+1], acc[u+2], acc[u+3]);
}

// ---------------- Pass 2: sequential scan per (b,h) ------------------------
__global__ void ret_pass2()
{
    const int bh  = blockIdx.x;
    const int tid = threadIdx.x;
    const int h   = bh & 15;
    const float gamma = 1.0f - exp2f(-5.0f - (float)h);
    const float gL = exp2f(64.0f * log2f(gamma));
    float s[16];
    #pragma unroll
    for (int u = 0; u < 16; ++u) s[u] = 0.f;
    for (int c = 0; c < NCHUNK; ++c) {
        size_t base = ((size_t)bh*NCHUNK + c)*4096;
        #pragma unroll
        for (int u = 0; u < 16; ++u) {
            size_t e = base + (size_t)u*256 + tid;
            g_S[e] = s[u];
            s[u] = fmaf(gL, s[u], g_G[e]);
        }
    }
}

// ---------------- Pass 3: intra-chunk + cross + fused GroupNorm ------------
__global__ __launch_bounds__(256)
void ret_pass3(const float* __restrict__ gnw, const float* __restrict__ gnb)
{
    __shared__ float sQt[64*64];
    __shared__ float sT[64*64];
    __shared__ float sA[64*64];
    const int blk = blockIdx.x;
    const int c   = blk & 31;
    const int h   = (blk >> 5) & 15;
    const int b   = blk >> 9;
    const int tid = threadIdx.x;
    const float gamma = 1.0f - exp2f(-5.0f - (float)h);
    const float lg = log2f(gamma);
    const size_t rowbase = ((size_t)(b*Tv + c*64))*Cv + (size_t)h*64;
    const int fq = tid & 15;

    for (int r = tid >> 4; r < 64; r += 16) {
        float4 qv = *(const float4*)(g_q + rowbase + (size_t)r*Cv + fq*4);
        float4 kv = *(const float4*)(g_k + rowbase + (size_t)r*Cv + fq*4);
        int d0 = fq*4;
        sQt[(d0+0)*64 + r] = 0.125f*qv.x;
        sQt[(d0+1)*64 + r] = 0.125f*qv.y;
        sQt[(d0+2)*64 + r] = 0.125f*qv.z;
        sQt[(d0+3)*64 + r] = 0.125f*qv.w;
        sT[(d0+0)*64 + r] = kv.x;
        sT[(d0+1)*64 + r] = kv.y;
        sT[(d0+2)*64 + r] = kv.z;
        sT[(d0+3)*64 + r] = kv.w;
    }
    __syncthreads();

    const int i  = tid >> 2;
    const int jb = (tid & 3) * 16;

    float a[16];
    #pragma unroll
    for (int u = 0; u < 16; ++u) a[u] = 0.f;
    #pragma unroll 8
    for (int d = 0; d < 64; ++d) {
        float qv = sQt[d*64 + i];
        const float4* tp = (const float4*)&sT[d*64 + jb];
        float4 t0 = tp[0], t1 = tp[1], t2 = tp[2], t3 = tp[3];
        a[0]  = fmaf(qv, t0.x, a[0]);  a[1]  = fmaf(qv, t0.y, a[1]);
        a[2]  = fmaf(qv, t0.z, a[2]);  a[3]  = fmaf(qv, t0.w, a[3]);
        a[4]  = fmaf(qv, t1.x, a[4]);  a[5]  = fmaf(qv, t1.y, a[5]);
        a[6]  = fmaf(qv, t1.z, a[6]);  a[7]  = fmaf(qv, t1.w, a[7]);
        a[8]  = fmaf(qv, t2.x, a[8]);  a[9]  = fmaf(qv, t2.y, a[9]);
        a[10] = fmaf(qv, t2.z, a[10]); a[11] = fmaf(qv, t2.w, a[11]);
        a[12] = fmaf(qv, t3.x, a[12]); a[13] = fmaf(qv, t3.y, a[13]);
        a[14] = fmaf(qv, t3.z, a[14]); a[15] = fmaf(qv, t3.w, a[15]);
    }
    #pragma unroll
    for (int u = 0; u < 16; ++u) {
        int j = jb + u;
        float dec = (j <= i) ? exp2f((float)(i - j) * lg) : 0.f;
        sA[j*64 + i] = a[u] * dec;
    }
    __syncthreads();

    const float* Sp = g_S + (size_t)blk*4096;
    for (int e = tid*4; e < 4096; e += 1024)
        *(float4*)&sT[e] = *(const float4*)&Sp[e];
    __syncthreads();

    const int dvb = jb;
    float o[16];
    #pragma unroll
    for (int u = 0; u < 16; ++u) o[u] = 0.f;
    #pragma unroll 8
    for (int d = 0; d < 64; ++d) {
        float qv = sQt[d*64 + i];
        const float4* sp = (const float4*)&sT[d*64 + dvb];
        float4 s0 = sp[0], s1 = sp[1], s2 = sp[2], s3 = sp[3];
        o[0]  = fmaf(qv, s0.x, o[0]);  o[1]  = fmaf(qv, s0.y, o[1]);
        o[2]  = fmaf(qv, s0.z, o[2]);  o[3]  = fmaf(qv, s0.w, o[3]);
        o[4]  = fmaf(qv, s1.x, o[4]);  o[5]  = fmaf(qv, s1.y, o[5]);
        o[6]  = fmaf(qv, s1.z, o[6]);  o[7]  = fmaf(qv, s1.w, o[7]);
        o[8]  = fmaf(qv, s2.x, o[8]);  o[9]  = fmaf(qv, s2.y, o[9]);
        o[10] = fmaf(qv, s2.z, o[10]); o[11] = fmaf(qv, s2.w, o[11]);
        o[12] = fmaf(qv, s3.x, o[12]); o[13] = fmaf(qv, s3.y, o[13]);
        o[14] = fmaf(qv, s3.z, o[14]); o[15] = fmaf(qv, s3.w, o[15]);
    }
    {
        float cd = exp2f((float)i * lg);
        #pragma unroll
        for (int u = 0; u < 16; ++u) o[u] *= cd;
    }
    __syncthreads();

    for (int r = tid >> 4; r < 64; r += 16)
        *(float4*)&sQt[r*64 + fq*4] = *(const float4*)(g_v + rowbase + (size_t)r*Cv + fq*4);
    __syncthreads();

    #pragma unroll 8
    for (int s = 0; s < 64; ++s) {
        float av = sA[s*64 + i];
        const float4* vp = (const float4*)&sQt[s*64 + dvb];
        float4 v0 = vp[0], v1 = vp[1], v2 = vp[2], v3 = vp[3];
        o[0]  = fmaf(av, v0.x, o[0]);  o[1]  = fmaf(av, v0.y, o[1]);
        o[2]  = fmaf(av, v0.z, o[2]);  o[3]  = fmaf(av, v0.w, o[3]);
        o[4]  = fmaf(av, v1.x, o[4]);  o[5]  = fmaf(av, v1.y, o[5]);
        o[6]  = fmaf(av, v1.z, o[6]);  o[7]  = fmaf(av, v1.w, o[7]);
        o[8]  = fmaf(av, v2.x, o[8]);  o[9]  = fmaf(av, v2.y, o[9]);
        o[10] = fmaf(av, v2.z, o[10]); o[11] = fmaf(av, v2.w, o[11]);
        o[12] = fmaf(av, v3.x, o[12]); o[13] = fmaf(av, v3.y, o[13]);
        o[14] = fmaf(av, v3.z, o[14]); o[15] = fmaf(av, v3.w, o[15]);
    }

    float sum = 0.f;
    #pragma unroll
    for (int u = 0; u < 16; ++u) sum += o[u];
    sum += __shfl_xor_sync(0xffffffffu, sum, 1);
    sum += __shfl_xor_sync(0xffffffffu, sum, 2);
    float mean = sum * (1.0f/64.0f);
    float sq = 0.f;
    #pragma unroll
    for (int u = 0; u < 16; ++u) { float dd = o[u] - mean; sq = fmaf(dd, dd, sq); }
    sq += __shfl_xor_sync(0xffffffffu, sq, 1);
    sq += __shfl_xor_sync(0xffffffffu, sq, 2);
    float rstd = rsqrtf(sq * (1.0f/64.0f) + 1e-5f);

    float* op = g_att + ((size_t)(b*Tv + c*64 + i))*Cv + (size_t)h*64 + dvb;
    const float* wg = gnw + h*64 + dvb;
    const float* bg = gnb + h*64 + dvb;
    #pragma unroll
    for (int u = 0; u < 16; u += 4) {
        float4 r;
        r.x = fmaf((o[u+0]-mean)*rstd, wg[u+0], bg[u+0]);
        r.y = fmaf((o[u+1]-mean)*rstd, wg[u+1], bg[u+1]);
        r.z = fmaf((o[u+2]-mean)*rstd, wg[u+2], bg[u+2]);
        r.w = fmaf((o[u+3]-mean)*rstd, wg[u+3], bg[u+3]);
        *(float4*)(op + u) = r;
    }
}

// ---------------------------------------------------------------------------
extern "C" void kernel_launch(void* const* d_in, const int* in_sizes, int n_in,
                              void* d_out, int out_size)
{
    const float* x   = (const float*)d_in[0];
    const float* W[4] = { (const float*)d_in[1], (const float*)d_in[2],
                          (const float*)d_in[3], (const float*)d_in[4] };
    const float* gnw = (const float*)d_in[5];
    const float* gnb = (const float*)d_in[6];
    float* out = (float*)d_out;

    float *q, *k, *v, *att;
    cudaGetSymbolAddress((void**)&q,   g_q);
    cudaGetSymbolAddress((void**)&k,   g_k);
    cudaGetSymbolAddress((void**)&v,   g_v);
    cudaGetSymbolAddress((void**)&att, g_att);
    __nv_bfloat16 *xh, *xl, *ah, *al, *wh, *wl;
    cudaGetSymbolAddress((void**)&xh, g_xh);
    cudaGetSymbolAddress((void**)&xl, g_xl);
    cudaGetSymbolAddress((void**)&ah, g_ah);
    cudaGetSymbolAddress((void**)&al, g_al);
    cudaGetSymbolAddress((void**)&wh, g_wh);
    cudaGetSymbolAddress((void**)&wl, g_wl);

    cudaFuncSetAttribute(gemm_split_mma,
                         cudaFuncAttributeMaxDynamicSharedMemorySize, GSMEM_TOTAL);

    const int nx4 = (Mv*Cv)/4;
    const int nw4 = (Cv*Cv)/4;
    split_kernel<<<(nx4+255)/256, 256>>>(x, xh, xl, nx4);
    for (int i = 0; i < 4; ++i)
        split_kernel<<<(nw4+255)/256, 256>>>(W[i], wh + (size_t)i*Cv*Cv, wl + (size_t)i*Cv*Cv, nw4);

    dim3 ggrid(Cv/128, Mv/128);    // (8, 32)
    gemm_split_mma<<<ggrid, 256, GSMEM_TOTAL>>>(xh, xl, wh + 0*(size_t)Cv*Cv, wl + 0*(size_t)Cv*Cv, q, Cv, Cv);
    gemm_split_mma<<<ggrid, 256, GSMEM_TOTAL>>>(xh, xl, wh + 1*(size_t)Cv*Cv, wl + 1*(size_t)Cv*Cv, k, Cv, Cv);
    gemm_split_mma<<<ggrid, 256, GSMEM_TOTAL>>>(xh, xl, wh + 2*(size_t)Cv*Cv, wl + 2*(size_t)Cv*Cv, v, Cv, Cv);

    rope_kernel<<<(Bv*Tv*Hv*32)/256, 256>>>();
    ret_pass1<<<Bv*Hv*NCHUNK, 256>>>();
    ret_pass2<<<Bv*Hv, 256>>>();
    ret_pass3<<<Bv*Hv*NCHUNK, 256>>>(gnw, gnb);

    split_kernel<<<(nx4+255)/256, 256>>>(att, ah, al, nx4);
    gemm_split_mma<<<ggrid, 256, GSMEM_TOTAL>>>(ah, al, wh + 3*(size_t)Cv*Cv, wl + 3*(size_t)Cv*Cv, out, Cv, Cv);
}

// round 8
// speedup vs baseline: 2.4333x; 1.2553x over previous
#include <cuda_runtime.h>
#include <cuda_fp16.h>
#include <math.h>
#include <stdint.h>

#define Bv 2
#define Tv 2048
#define Cv 1024
#define Hv 16
#define DHv 64
#define Mv (Bv*Tv)       // 4096 rows
#define NCHUNK 32        // T / 64
#define CC (Cv*Cv)

// ---------------- scratch (static device memory; no allocs) ----------------
__device__ float g_q[Mv*Cv];
__device__ float g_k[Mv*Cv];
__device__ float g_v[Mv*Cv];
__device__ float g_G[Bv*Hv*NCHUNK*DHv*DHv];
__device__ float g_S[Bv*Hv*NCHUNK*DHv*DHv];

__device__ __align__(256) __half g_att16[Mv*Cv];     // fp16 retention output
__device__ __align__(256) __half g_xh[Mv*Cv];        // fp16 x
__device__ __align__(256) __half g_whi[4*CC];        // fp16 hi of Wq,Wk,Wv,Wo (concat rows)
__device__ __align__(256) __half g_wlo[4*CC];        // fp16 lo residuals

// ======================= helpers ===========================================
__device__ __forceinline__ uint32_t smem_to_u32(const void* p) {
    uint32_t a;
    asm("{ .reg .u64 t; cvta.to.shared.u64 t, %1; cvt.u32.u64 %0, t; }" : "=r"(a) : "l"(p));
    return a;
}
__device__ __forceinline__ void ldmatrix_x4(uint32_t* r, uint32_t addr) {
    asm volatile("ldmatrix.sync.aligned.m8n8.x4.shared.b16 {%0,%1,%2,%3}, [%4];"
                 : "=r"(r[0]), "=r"(r[1]), "=r"(r[2]), "=r"(r[3]) : "r"(addr));
}
__device__ __forceinline__ void mma16816h(float* d, const uint32_t* a, uint32_t b0, uint32_t b1) {
    asm volatile(
        "mma.sync.aligned.m16n8k16.row.col.f32.f16.f16.f32 "
        "{%0,%1,%2,%3}, {%4,%5,%6,%7}, {%8,%9}, {%0,%1,%2,%3};"
        : "+f"(d[0]), "+f"(d[1]), "+f"(d[2]), "+f"(d[3])
        : "r"(a[0]), "r"(a[1]), "r"(a[2]), "r"(a[3]), "r"(b0), "r"(b1));
}

// =================== splits ================================================
// x -> fp16 (unsplit; A-side of GEMM)
__global__ void split_x(const float* __restrict__ s, __half* __restrict__ hi, int n4)
{
    int i = blockIdx.x*blockDim.x + threadIdx.x;
    if (i >= n4) return;
    float4 f = ((const float4*)s)[i];
    __half2* hp = (__half2*)(hi + (size_t)i*4);
    hp[0] = __floats2half2_rn(f.x, f.y);
    hp[1] = __floats2half2_rn(f.z, f.w);
}

// 4 weights -> fp16 hi + fp16 lo residual, concatenated [4*C, C]
__global__ void split_4w(const float* __restrict__ W0, const float* __restrict__ W1,
                         const float* __restrict__ W2, const float* __restrict__ W3,
                         __half* __restrict__ hi, __half* __restrict__ lo)
{
    int i = blockIdx.x*blockDim.x + threadIdx.x;   // 0 .. 4*CC/4
    int w = i >> 18;                                // CC/4 = 262144 = 2^18
    const float* s = (w==0) ? W0 : (w==1) ? W1 : (w==2) ? W2 : W3;
    int j = i & 262143;
    float4 f = ((const float4*)s)[j];
    __half h0 = __float2half_rn(f.x);
    __half h1 = __float2half_rn(f.y);
    __half h2 = __float2half_rn(f.z);
    __half h3 = __float2half_rn(f.w);
    __half l0 = __float2half_rn(f.x - __half2float(h0));
    __half l1 = __float2half_rn(f.y - __half2float(h1));
    __half l2 = __float2half_rn(f.z - __half2float(h2));
    __half l3 = __float2half_rn(f.w - __half2float(h3));
    __half2* hp = (__half2*)(hi + (size_t)i*4);
    __half2* lp = (__half2*)(lo + (size_t)i*4);
    hp[0] = __halves2half2(h0, h1); hp[1] = __halves2half2(h2, h3);
    lp[0] = __halves2half2(l0, l1); lp[1] = __halves2half2(l2, l3);
}

// =================== fp16 2-term mma.sync GEMM =============================
// C[M,1024-per-out] = A[M,K](fp16) * (Bh+Bl)[N,K]^T
// CTA tile 128x128, BK=64 (128B swizzled rows), double-buffered cp.async.
// 3 smem tiles per stage (A, Bh, Bl) = 48KB; 2 stages = 96KB -> 2 CTA/SM.
// blockIdx.x covers concatenated N; output selected per 1024-col group.
#define GTILE_SZ 16384          // 128 rows x 128 bytes
#define GBUF_SZ  (3*GTILE_SZ)   // A, Bh, Bl
#define GSMEM_TOTAL (2*GBUF_SZ) // 98304

__global__ __launch_bounds__(256, 2)
void gemm_fp16_2t(const __half* __restrict__ A,
                  const __half* __restrict__ Bh,
                  const __half* __restrict__ Bl,
                  float* __restrict__ o0, float* __restrict__ o1, float* __restrict__ o2,
                  int K)
{
    extern __shared__ char smem[];
    const uint32_t sb = smem_to_u32(smem);
    const int tid  = threadIdx.x;
    const int lane = tid & 31;
    const int wid  = tid >> 5;
    const int wm   = wid & 1;     // 2 warps along M
    const int wn   = wid >> 1;    // 4 warps along N

    const size_t rowA0 = (size_t)blockIdx.y * 128;
    const size_t rowB0 = (size_t)blockIdx.x * 128;   // concatenated weight row
    const int which   = blockIdx.x >> 3;
    float* C = (which == 0) ? o0 : (which == 1) ? o1 : o2;
    const int colBase = (blockIdx.x & 7) * 128;

    const __half* tps[3] = { A + rowA0*K, Bh + rowB0*K, Bl + rowB0*K };

    auto load_chunk = [&](int k0, int b) {
        const uint32_t dst = sb + b * GBUF_SZ;
        #pragma unroll
        for (int t = 0; t < 3; ++t) {
            const __half* gp = tps[t] + k0;
            const uint32_t td = dst + t * GTILE_SZ;
            #pragma unroll
            for (int i = 0; i < 4; ++i) {
                int v = tid + i * 256;          // 0..1023
                int row = v >> 3, colv = v & 7; // 8 x 16B per 128B row
                uint32_t boff = row * 128 + colv * 16;
                uint32_t sw = boff ^ ((boff >> 3) & 0x70);
                const void* src = gp + (size_t)row * K + colv * 8;
                asm volatile("cp.async.cg.shared.global [%0], [%1], 16;"
                             :: "r"(td + sw), "l"(src) : "memory");
            }
        }
        asm volatile("cp.async.commit_group;" ::: "memory");
    };

    float acc[4][4][4];
    #pragma unroll
    for (int mt = 0; mt < 4; ++mt)
        #pragma unroll
        for (int nt = 0; nt < 4; ++nt)
            #pragma unroll
            for (int u = 0; u < 4; ++u) acc[mt][nt][u] = 0.f;

    const int  a_r    = lane & 15;
    const uint32_t a_hi = (uint32_t)(lane >> 4) * 16;
    const int  b_r    = (lane & 7) + ((lane >> 4) << 3);
    const uint32_t b_hi = (uint32_t)((lane >> 3) & 1) * 16;

    load_chunk(0, 0);

    const int nchunks = K >> 6;   // 16
    for (int c = 0; c < nchunks; ++c) {
        if (c + 1 < nchunks) {
            load_chunk((c + 1) * 64, (c + 1) & 1);
            asm volatile("cp.async.wait_group 1;" ::: "memory");
        } else {
            asm volatile("cp.async.wait_group 0;" ::: "memory");
        }
        __syncthreads();

        const uint32_t base = sb + (c & 1) * GBUF_SZ;
        const uint32_t aT = base;
        const uint32_t bH = base + GTILE_SZ, bL = base + 2*GTILE_SZ;

        #pragma unroll
        for (int ks = 0; ks < 4; ++ks) {
            const uint32_t kb = ks * 32;
            uint32_t a[4][4], bh[2][4], bl[2][4];
            #pragma unroll
            for (int mt = 0; mt < 4; ++mt) {
                int row = wm*64 + mt*16 + a_r;
                uint32_t off = (uint32_t)row*128 + (((kb + a_hi) ^ ((row & 7) << 4)));
                ldmatrix_x4(a[mt], aT + off);
            }
            #pragma unroll
            for (int ntp = 0; ntp < 2; ++ntp) {
                int row = wn*32 + ntp*16 + b_r;
                uint32_t off = (uint32_t)row*128 + (((kb + b_hi) ^ ((row & 7) << 4)));
                ldmatrix_x4(bh[ntp], bH + off);
                ldmatrix_x4(bl[ntp], bL + off);
            }
            #pragma unroll
            for (int mt = 0; mt < 4; ++mt) {
                #pragma unroll
                for (int nt = 0; nt < 4; ++nt) {
                    uint32_t b0 = bh[nt >> 1][(nt & 1)*2 + 0];
                    uint32_t b1 = bh[nt >> 1][(nt & 1)*2 + 1];
                    uint32_t c0 = bl[nt >> 1][(nt & 1)*2 + 0];
                    uint32_t c1 = bl[nt >> 1][(nt & 1)*2 + 1];
                    mma16816h(acc[mt][nt], a[mt], b0, b1);
                    mma16816h(acc[mt][nt], a[mt], c0, c1);
                }
            }
        }
        __syncthreads();
    }

    // ---- epilogue ----
    #pragma unroll
    for (int mt = 0; mt < 4; ++mt) {
        int r0 = (int)rowA0 + wm*64 + mt*16 + (lane >> 2);
        #pragma unroll
        for (int nt = 0; nt < 4; ++nt) {
            int col = colBase + wn*32 + nt*8 + 2*(lane & 3);
            float2 v0 = make_float2(acc[mt][nt][0], acc[mt][nt][1]);
            float2 v1 = make_float2(acc[mt][nt][2], acc[mt][nt][3]);
            *(float2*)(C + (size_t)r0 * Cv + col)       = v0;
            *(float2*)(C + (size_t)(r0 + 8) * Cv + col) = v1;
        }
    }
}

// ---------------- RoPE on q,k in-place ([B,T,H,DH] == [M, C]) --------------
__global__ void rope_kernel()
{
    int idx = blockIdx.x*blockDim.x + threadIdx.x;
    if (idx >= Bv*Tv*Hv*32) return;
    int d  = idx & 31;
    int h  = (idx >> 5) & (Hv-1);
    int bt = idx >> 9;
    int t  = bt & (Tv-1);
    float inv = exp2f(-(float)d * (13.287712379549449f / 32.0f));
    float ang = (float)t * inv;
    float s, c;
    sincosf(ang, &s, &c);
    size_t base = (size_t)bt*Cv + h*DHv + d;
    float q1 = g_q[base], q2 = g_q[base+32];
    g_q[base]    = q1*c - q2*s;
    g_q[base+32] = q2*c + q1*s;
    float k1 = g_k[base], k2 = g_k[base+32];
    g_k[base]    = k1*c - k2*s;
    g_k[base+32] = k2*c + k1*s;
}

// ---------------- Pass 1: per-chunk local state ----------------------------
__global__ __launch_bounds__(256)
void ret_pass1()
{
    __shared__ float sK[64*64];
    __shared__ float sV[64*64];
    const int blk = blockIdx.x;
    const int c   = blk & 31;
    const int h   = (blk >> 5) & 15;
    const int b   = blk >> 9;
    const int tid = threadIdx.x;
    const float gamma = 1.0f - exp2f(-5.0f - (float)h);
    const float lg = log2f(gamma);
    const size_t rowbase = ((size_t)(b*Tv + c*64))*Cv + (size_t)h*64;
    const int fq = tid & 15;
    for (int r = tid >> 4; r < 64; r += 16) {
        float w = exp2f((float)(64 - r) * lg);
        float4 kv = *(const float4*)(g_k + rowbase + (size_t)r*Cv + fq*4);
        kv.x *= w; kv.y *= w; kv.z *= w; kv.w *= w;
        *(float4*)&sK[r*64 + fq*4] = kv;
        *(float4*)&sV[r*64 + fq*4] = *(const float4*)(g_v + rowbase + (size_t)r*Cv + fq*4);
    }
    __syncthreads();
    const int dk  = tid >> 2;
    const int dvb = (tid & 3) * 16;
    float acc[16];
    #pragma unroll
    for (int u = 0; u < 16; ++u) acc[u] = 0.f;
    #pragma unroll 8
    for (int j = 0; j < 64; ++j) {
        float kv = sK[j*64 + dk];
        const float4* vp = (const float4*)&sV[j*64 + dvb];
        float4 v0 = vp[0], v1 = vp[1], v2 = vp[2], v3 = vp[3];
        acc[0]  = fmaf(kv, v0.x, acc[0]);  acc[1]  = fmaf(kv, v0.y, acc[1]);
        acc[2]  = fmaf(kv, v0.z, acc[2]);  acc[3]  = fmaf(kv, v0.w, acc[3]);
        acc[4]  = fmaf(kv, v1.x, acc[4]);  acc[5]  = fmaf(kv, v1.y, acc[5]);
        acc[6]  = fmaf(kv, v1.z, acc[6]);  acc[7]  = fmaf(kv, v1.w, acc[7]);
        acc[8]  = fmaf(kv, v2.x, acc[8]);  acc[9]  = fmaf(kv, v2.y, acc[9]);
        acc[10] = fmaf(kv, v2.z, acc[10]); acc[11] = fmaf(kv, v2.w, acc[11]);
        acc[12] = fmaf(kv, v3.x, acc[12]); acc[13] = fmaf(kv, v3.y, acc[13]);
        acc[14] = fmaf(kv, v3.z, acc[14]); acc[15] = fmaf(kv, v3.w, acc[15]);
    }
    float* Gp = g_G + ((size_t)blk*64 + dk)*64 + dvb;
    #pragma unroll
    for (int u = 0; u < 16; u += 4)
        *(float4*)(Gp + u) = make_float4(acc[u], acc[u+1], acc[u+2], acc[u+3]);
}

// ---------------- Pass 2: sequential scan per (b,h) ------------------------
__global__ void ret_pass2()
{
    const int bh  = blockIdx.x;
    const int tid = threadIdx.x;
    const int h   = bh & 15;
    const float gamma = 1.0f - exp2f(-5.0f - (float)h);
    const float gL = exp2f(64.0f * log2f(gamma));
    float s[16];
    #pragma unroll
    for (int u = 0; u < 16; ++u) s[u] = 0.f;
    for (int c = 0; c < NCHUNK; ++c) {
        size_t base = ((size_t)bh*NCHUNK + c)*4096;
        #pragma unroll
        for (int u = 0; u < 16; ++u) {
            size_t e = base + (size_t)u*256 + tid;
            g_S[e] = s[u];
            s[u] = fmaf(gL, s[u], g_G[e]);
        }
    }
}

// ---------------- Pass 3: intra-chunk + cross + fused GroupNorm ------------
// Writes the normalized output directly as fp16 (A-side of the Wo GEMM).
__global__ __launch_bounds__(256)
void ret_pass3(const float* __restrict__ gnw, const float* __restrict__ gnb)
{
    __shared__ float sQt[64*64];
    __shared__ float sT[64*64];
    __shared__ float sA[64*64];
    const int blk = blockIdx.x;
    const int c   = blk & 31;
    const int h   = (blk >> 5) & 15;
    const int b   = blk >> 9;
    const int tid = threadIdx.x;
    const float gamma = 1.0f - exp2f(-5.0f - (float)h);
    const float lg = log2f(gamma);
    const size_t rowbase = ((size_t)(b*Tv + c*64))*Cv + (size_t)h*64;
    const int fq = tid & 15;

    for (int r = tid >> 4; r < 64; r += 16) {
        float4 qv = *(const float4*)(g_q + rowbase + (size_t)r*Cv + fq*4);
        float4 kv = *(const float4*)(g_k + rowbase + (size_t)r*Cv + fq*4);
        int d0 = fq*4;
        sQt[(d0+0)*64 + r] = 0.125f*qv.x;
        sQt[(d0+1)*64 + r] = 0.125f*qv.y;
        sQt[(d0+2)*64 + r] = 0.125f*qv.z;
        sQt[(d0+3)*64 + r] = 0.125f*qv.w;
        sT[(d0+0)*64 + r] = kv.x;
        sT[(d0+1)*64 + r] = kv.y;
        sT[(d0+2)*64 + r] = kv.z;
        sT[(d0+3)*64 + r] = kv.w;
    }
    __syncthreads();

    const int i  = tid >> 2;
    const int jb = (tid & 3) * 16;

    float a[16];
    #pragma unroll
    for (int u = 0; u < 16; ++u) a[u] = 0.f;
    #pragma unroll 8
    for (int d = 0; d < 64; ++d) {
        float qv = sQt[d*64 + i];
        const float4* tp = (const float4*)&sT[d*64 + jb];
        float4 t0 = tp[0], t1 = tp[1], t2 = tp[2], t3 = tp[3];
        a[0]  = fmaf(qv, t0.x, a[0]);  a[1]  = fmaf(qv, t0.y, a[1]);
        a[2]  = fmaf(qv, t0.z, a[2]);  a[3]  = fmaf(qv, t0.w, a[3]);
        a[4]  = fmaf(qv, t1.x, a[4]);  a[5]  = fmaf(qv, t1.y, a[5]);
        a[6]  = fmaf(qv, t1.z, a[6]);  a[7]  = fmaf(qv, t1.w, a[7]);
        a[8]  = fmaf(qv, t2.x, a[8]);  a[9]  = fmaf(qv, t2.y, a[9]);
        a[10] = fmaf(qv, t2.z, a[10]); a[11] = fmaf(qv, t2.w, a[11]);
        a[12] = fmaf(qv, t3.x, a[12]); a[13] = fmaf(qv, t3.y, a[13]);
        a[14] = fmaf(qv, t3.z, a[14]); a[15] = fmaf(qv, t3.w, a[15]);
    }
    #pragma unroll
    for (int u = 0; u < 16; ++u) {
        int j = jb + u;
        float dec = (j <= i) ? exp2f((float)(i - j) * lg) : 0.f;
        sA[j*64 + i] = a[u] * dec;
    }
    __syncthreads();

    const float* Sp = g_S + (size_t)blk*4096;
    for (int e = tid*4; e < 4096; e += 1024)
        *(float4*)&sT[e] = *(const float4*)&Sp[e];
    __syncthreads();

    const int dvb = jb;
    float o[16];
    #pragma unroll
    for (int u = 0; u < 16; ++u) o[u] = 0.f;
    #pragma unroll 8
    for (int d = 0; d < 64; ++d) {
        float qv = sQt[d*64 + i];
        const float4* sp = (const float4*)&sT[d*64 + dvb];
        float4 s0 = sp[0], s1 = sp[1], s2 = sp[2], s3 = sp[3];
        o[0]  = fmaf(qv, s0.x, o[0]);  o[1]  = fmaf(qv, s0.y, o[1]);
        o[2]  = fmaf(qv, s0.z, o[2]);  o[3]  = fmaf(qv, s0.w, o[3]);
        o[4]  = fmaf(qv, s1.x, o[4]);  o[5]  = fmaf(qv, s1.y, o[5]);
        o[6]  = fmaf(qv, s1.z, o[6]);  o[7]  = fmaf(qv, s1.w, o[7]);
        o[8]  = fmaf(qv, s2.x, o[8]);  o[9]  = fmaf(qv, s2.y, o[9]);
        o[10] = fmaf(qv, s2.z, o[10]); o[11] = fmaf(qv, s2.w, o[11]);
        o[12] = fmaf(qv, s3.x, o[12]); o[13] = fmaf(qv, s3.y, o[13]);
        o[14] = fmaf(qv, s3.z, o[14]); o[15] = fmaf(qv, s3.w, o[15]);
    }
    {
        float cd = exp2f((float)i * lg);
        #pragma unroll
        for (int u = 0; u < 16; ++u) o[u] *= cd;
    }
    __syncthreads();

    for (int r = tid >> 4; r < 64; r += 16)
        *(float4*)&sQt[r*64 + fq*4] = *(const float4*)(g_v + rowbase + (size_t)r*Cv + fq*4);
    __syncthreads();

    #pragma unroll 8
    for (int s = 0; s < 64; ++s) {
        float av = sA[s*64 + i];
        const float4* vp = (const float4*)&sQt[s*64 + dvb];
        float4 v0 = vp[0], v1 = vp[1], v2 = vp[2], v3 = vp[3];
        o[0]  = fmaf(av, v0.x, o[0]);  o[1]  = fmaf(av, v0.y, o[1]);
        o[2]  = fmaf(av, v0.z, o[2]);  o[3]  = fmaf(av, v0.w, o[3]);
        o[4]  = fmaf(av, v1.x, o[4]);  o[5]  = fmaf(av, v1.y, o[5]);
        o[6]  = fmaf(av, v1.z, o[6]);  o[7]  = fmaf(av, v1.w, o[7]);
        o[8]  = fmaf(av, v2.x, o[8]);  o[9]  = fmaf(av, v2.y, o[9]);
        o[10] = fmaf(av, v2.z, o[10]); o[11] = fmaf(av, v2.w, o[11]);
        o[12] = fmaf(av, v3.x, o[12]); o[13] = fmaf(av, v3.y, o[13]);
        o[14] = fmaf(av, v3.z, o[14]); o[15] = fmaf(av, v3.w, o[15]);
    }

    float sum = 0.f;
    #pragma unroll
    for (int u = 0; u < 16; ++u) sum += o[u];
    sum += __shfl_xor_sync(0xffffffffu, sum, 1);
    sum += __shfl_xor_sync(0xffffffffu, sum, 2);
    float mean = sum * (1.0f/64.0f);
    float sq = 0.f;
    #pragma unroll
    for (int u = 0; u < 16; ++u) { float dd = o[u] - mean; sq = fmaf(dd, dd, sq); }
    sq += __shfl_xor_sync(0xffffffffu, sq, 1);
    sq += __shfl_xor_sync(0xffffffffu, sq, 2);
    float rstd = rsqrtf(sq * (1.0f/64.0f) + 1e-5f);

    __half* op = g_att16 + ((size_t)(b*Tv + c*64 + i))*Cv + (size_t)h*64 + dvb;
    const float* wg = gnw + h*64 + dvb;
    const float* bg = gnb + h*64 + dvb;
    #pragma unroll
    for (int u = 0; u < 16; u += 2) {
        float r0 = fmaf((o[u+0]-mean)*rstd, wg[u+0], bg[u+0]);
        float r1 = fmaf((o[u+1]-mean)*rstd, wg[u+1], bg[u+1]);
        *(__half2*)(op + u) = __floats2half2_rn(r0, r1);
    }
}

// ---------------------------------------------------------------------------
extern "C" void kernel_launch(void* const* d_in, const int* in_sizes, int n_in,
                              void* d_out, int out_size)
{
    const float* x   = (const float*)d_in[0];
    const float* Wq  = (const float*)d_in[1];
    const float* Wk  = (const float*)d_in[2];
    const float* Wv  = (const float*)d_in[3];
    const float* Wo  = (const float*)d_in[4];
    const float* gnw = (const float*)d_in[5];
    const float* gnb = (const float*)d_in[6];
    float* out = (float*)d_out;

    float *q, *k, *v;
    cudaGetSymbolAddress((void**)&q, g_q);
    cudaGetSymbolAddress((void**)&k, g_k);
    cudaGetSymbolAddress((void**)&v, g_v);
    __half *xh, *att16, *whi, *wlo;
    cudaGetSymbolAddress((void**)&xh,    g_xh);
    cudaGetSymbolAddress((void**)&att16, g_att16);
    cudaGetSymbolAddress((void**)&whi,   g_whi);
    cudaGetSymbolAddress((void**)&wlo,   g_wlo);

    static bool attr_set = false;
    if (!attr_set) {
        cudaFuncSetAttribute(gemm_fp16_2t,
                             cudaFuncAttributeMaxDynamicSharedMemorySize, GSMEM_TOTAL);
        attr_set = true;
    }

    const int nx4 = (Mv*Cv)/4;     // 1M float4s
    split_x<<<(nx4+255)/256, 256>>>(x, xh, nx4);
    split_4w<<<(4*CC/4)/256, 256>>>(Wq, Wk, Wv, Wo, whi, wlo);

    // merged QKV projection: concatenated weight rows 0..3071
    gemm_fp16_2t<<<dim3(24, 32), 256, GSMEM_TOTAL>>>(xh, whi, wlo, q, k, v, Cv);

    rope_kernel<<<(Bv*Tv*Hv*32)/256, 256>>>();
    ret_pass1<<<Bv*Hv*NCHUNK, 256>>>();
    ret_pass2<<<Bv*Hv, 256>>>();
    ret_pass3<<<Bv*Hv*NCHUNK, 256>>>(gnw, gnb);

    // output GEMM: Wo rows are 3*CC..4*CC of the concatenated split buffers
    gemm_fp16_2t<<<dim3(8, 32), 256, GSMEM_TOTAL>>>(att16, whi + (size_t)3*CC, wlo + (size_t)3*CC,
                                                    out, out, out, Cv);
}

// round 9
// speedup vs baseline: 2.5518x; 1.0487x over previous
#include <cuda_runtime.h>
#include <cuda_fp16.h>
#include <math.h>
#include <stdint.h>

#define Bv 2
#define Tv 2048
#define Cv 1024
#define Hv 16
#define DHv 64
#define Mv (Bv*Tv)       // 4096 rows
#define NCHUNK 32        // T / 64
#define CC (Cv*Cv)

// ---------------- scratch (static device memory; no allocs) ----------------
__device__ float g_q[Mv*Cv];
__device__ float g_k[Mv*Cv];
__device__ float g_v[Mv*Cv];
__device__ float g_G[Bv*Hv*NCHUNK*DHv*DHv];
__device__ float g_S[Bv*Hv*NCHUNK*DHv*DHv];
__device__ float g_rope_cos[Tv*32];
__device__ float g_rope_sin[Tv*32];

__device__ __align__(256) __half g_att16[Mv*Cv];     // fp16 retention output
__device__ __align__(256) __half g_xh[Mv*Cv];        // fp16 x
__device__ __align__(256) __half g_whi[4*CC];        // fp16 hi of Wq,Wk,Wv,Wo
__device__ __align__(256) __half g_wlo[4*CC];        // fp16 lo residuals

// ======================= helpers ===========================================
__device__ __forceinline__ uint32_t smem_to_u32(const void* p) {
    uint32_t a;
    asm("{ .reg .u64 t; cvta.to.shared.u64 t, %1; cvt.u32.u64 %0, t; }" : "=r"(a) : "l"(p));
    return a;
}
__device__ __forceinline__ void ldmatrix_x4(uint32_t* r, uint32_t addr) {
    asm volatile("ldmatrix.sync.aligned.m8n8.x4.shared.b16 {%0,%1,%2,%3}, [%4];"
                 : "=r"(r[0]), "=r"(r[1]), "=r"(r[2]), "=r"(r[3]) : "r"(addr));
}
__device__ __forceinline__ void mma16816h(float* d, const uint32_t* a, uint32_t b0, uint32_t b1) {
    asm volatile(
        "mma.sync.aligned.m16n8k16.row.col.f32.f16.f16.f32 "
        "{%0,%1,%2,%3}, {%4,%5,%6,%7}, {%8,%9}, {%0,%1,%2,%3};"
        : "+f"(d[0]), "+f"(d[1]), "+f"(d[2]), "+f"(d[3])
        : "r"(a[0]), "r"(a[1]), "r"(a[2]), "r"(a[3]), "r"(b0), "r"(b1));
}

// =================== small prep kernels ====================================
__global__ void split_x(const float* __restrict__ s, __half* __restrict__ hi, int n4)
{
    int i = blockIdx.x*blockDim.x + threadIdx.x;
    if (i >= n4) return;
    float4 f = ((const float4*)s)[i];
    __half2* hp = (__half2*)(hi + (size_t)i*4);
    hp[0] = __floats2half2_rn(f.x, f.y);
    hp[1] = __floats2half2_rn(f.z, f.w);
}

__global__ void split_4w(const float* __restrict__ W0, const float* __restrict__ W1,
                         const float* __restrict__ W2, const float* __restrict__ W3,
                         __half* __restrict__ hi, __half* __restrict__ lo)
{
    int i = blockIdx.x*blockDim.x + threadIdx.x;   // 0 .. 4*CC/4
    int w = i >> 18;
    const float* s = (w==0) ? W0 : (w==1) ? W1 : (w==2) ? W2 : W3;
    int j = i & 262143;
    float4 f = ((const float4*)s)[j];
    __half h0 = __float2half_rn(f.x);
    __half h1 = __float2half_rn(f.y);
    __half h2 = __float2half_rn(f.z);
    __half h3 = __float2half_rn(f.w);
    __half l0 = __float2half_rn(f.x - __half2float(h0));
    __half l1 = __float2half_rn(f.y - __half2float(h1));
    __half l2 = __float2half_rn(f.z - __half2float(h2));
    __half l3 = __float2half_rn(f.w - __half2float(h3));
    __half2* hp = (__half2*)(hi + (size_t)i*4);
    __half2* lp = (__half2*)(lo + (size_t)i*4);
    hp[0] = __halves2half2(h0, h1); hp[1] = __halves2half2(h2, h3);
    lp[0] = __halves2half2(l0, l1); lp[1] = __halves2half2(l2, l3);
}

__global__ void rope_table()
{
    int i = blockIdx.x*blockDim.x + threadIdx.x;   // 0..65535
    int dm = i & 31, t = i >> 5;
    float inv = exp2f(-(float)dm * (13.287712379549449f / 32.0f));
    float ang = (float)t * inv;
    float s, c;
    sincosf(ang, &s, &c);
    g_rope_cos[i] = c;
    g_rope_sin[i] = s;
}

// =================== fp16 2-term QKV GEMM (rope fused) =====================
// q,k,v[M,1024] = x[M,K](fp16) * (Wh+Wl)[3072,K]^T ; rope applied to q,k.
#define GTILE_SZ 16384          // 128 rows x 128 bytes
#define GBUF_SZ  (3*GTILE_SZ)   // A, Bh, Bl
#define GSMEM_TOTAL (2*GBUF_SZ) // 98304

__global__ __launch_bounds__(256, 2)
void gemm_qkv(const __half* __restrict__ A,
              const __half* __restrict__ Bh,
              const __half* __restrict__ Bl,
              float* __restrict__ o0, float* __restrict__ o1, float* __restrict__ o2)
{
    extern __shared__ char smem[];
    const uint32_t sb = smem_to_u32(smem);
    const int tid  = threadIdx.x;
    const int lane = tid & 31;
    const int wid  = tid >> 5;
    const int wm   = wid & 1;
    const int wn   = wid >> 1;
    const int K = Cv;

    const size_t rowA0 = (size_t)blockIdx.y * 128;
    const size_t rowB0 = (size_t)blockIdx.x * 128;
    const int which   = blockIdx.x >> 3;            // 0=q 1=k 2=v
    float* C = (which == 0) ? o0 : (which == 1) ? o1 : o2;
    const int colBase = (blockIdx.x & 7) * 128;

    const __half* tps[3] = { A + rowA0*K, Bh + rowB0*K, Bl + rowB0*K };

    auto load_chunk = [&](int k0, int b) {
        const uint32_t dst = sb + b * GBUF_SZ;
        #pragma unroll
        for (int t = 0; t < 3; ++t) {
            const __half* gp = tps[t] + k0;
            const uint32_t td = dst + t * GTILE_SZ;
            #pragma unroll
            for (int i = 0; i < 4; ++i) {
                int v = tid + i * 256;
                int row = v >> 3, colv = v & 7;
                uint32_t boff = row * 128 + colv * 16;
                uint32_t sw = boff ^ ((boff >> 3) & 0x70);
                const void* src = gp + (size_t)row * K + colv * 8;
                asm volatile("cp.async.cg.shared.global [%0], [%1], 16;"
                             :: "r"(td + sw), "l"(src) : "memory");
            }
        }
        asm volatile("cp.async.commit_group;" ::: "memory");
    };

    float acc[4][4][4];
    #pragma unroll
    for (int mt = 0; mt < 4; ++mt)
        #pragma unroll
        for (int nt = 0; nt < 4; ++nt)
            #pragma unroll
            for (int u = 0; u < 4; ++u) acc[mt][nt][u] = 0.f;

    const int  a_r    = lane & 15;
    const uint32_t a_hi = (uint32_t)(lane >> 4) * 16;
    const int  b_r    = (lane & 7) + ((lane >> 4) << 3);
    const uint32_t b_hi = (uint32_t)((lane >> 3) & 1) * 16;

    load_chunk(0, 0);

    for (int c = 0; c < 16; ++c) {
        if (c + 1 < 16) {
            load_chunk((c + 1) * 64, (c + 1) & 1);
            asm volatile("cp.async.wait_group 1;" ::: "memory");
        } else {
            asm volatile("cp.async.wait_group 0;" ::: "memory");
        }
        __syncthreads();

        const uint32_t base = sb + (c & 1) * GBUF_SZ;
        const uint32_t aT = base;
        const uint32_t bH = base + GTILE_SZ, bL = base + 2*GTILE_SZ;

        #pragma unroll
        for (int ks = 0; ks < 4; ++ks) {
            const uint32_t kb = ks * 32;
            uint32_t a[4][4], bh[2][4], bl[2][4];
            #pragma unroll
            for (int mt = 0; mt < 4; ++mt) {
                int row = wm*64 + mt*16 + a_r;
                uint32_t off = (uint32_t)row*128 + (((kb + a_hi) ^ ((row & 7) << 4)));
                ldmatrix_x4(a[mt], aT + off);
            }
            #pragma unroll
            for (int ntp = 0; ntp < 2; ++ntp) {
                int row = wn*32 + ntp*16 + b_r;
                uint32_t off = (uint32_t)row*128 + (((kb + b_hi) ^ ((row & 7) << 4)));
                ldmatrix_x4(bh[ntp], bH + off);
                ldmatrix_x4(bl[ntp], bL + off);
            }
            #pragma unroll
            for (int mt = 0; mt < 4; ++mt) {
                #pragma unroll
                for (int nt = 0; nt < 4; ++nt) {
                    uint32_t b0 = bh[nt >> 1][(nt & 1)*2 + 0];
                    uint32_t b1 = bh[nt >> 1][(nt & 1)*2 + 1];
                    uint32_t c0 = bl[nt >> 1][(nt & 1)*2 + 0];
                    uint32_t c1 = bl[nt >> 1][(nt & 1)*2 + 1];
                    mma16816h(acc[mt][nt], a[mt], b0, b1);
                    mma16816h(acc[mt][nt], a[mt], c0, c1);
                }
            }
        }
        __syncthreads();
    }

    // ---- stage tile to smem, apply rope (q,k), store ----
    float* st = (float*)smem;
    #pragma unroll
    for (int mt = 0; mt < 4; ++mt) {
        int r = wm*64 + mt*16 + (lane >> 2);
        #pragma unroll
        for (int nt = 0; nt < 4; ++nt) {
            int col = wn*32 + nt*8 + 2*(lane & 3);
            *(float2*)&st[r*128 + col]       = make_float2(acc[mt][nt][0], acc[mt][nt][1]);
            *(float2*)&st[(r+8)*128 + col]   = make_float2(acc[mt][nt][2], acc[mt][nt][3]);
        }
    }
    __syncthreads();

    #pragma unroll 4
    for (int it = 0; it < 32; ++it) {
        int unit = tid + it*256;
        int row = unit >> 6;
        int col = (unit & 63) * 2;
        float2 val = *(float2*)&st[row*128 + col];
        float2 res = val;
        if (which < 2) {
            int gr = (int)rowA0 + row;
            int tt = gr & (Tv-1);
            int d = col & 63;
            float2 par;
            if (d < 32) {
                par = *(float2*)&st[row*128 + col + 32];
                par.x = -par.x; par.y = -par.y;
            } else {
                par = *(float2*)&st[row*128 + col - 32];
            }
            int dm = d & 31;
            float2 cc = *(const float2*)&g_rope_cos[tt*32 + dm];
            float2 ss = *(const float2*)&g_rope_sin[tt*32 + dm];
            res.x = val.x*cc.x + par.x*ss.x;
            res.y = val.y*cc.y + par.y*ss.y;
        }
        *(float2*)(C + ((size_t)rowA0 + row)*Cv + colBase + col) = res;
    }
}

// =================== fp16 1-term Wo GEMM ===================================
#define G1BUF_SZ  (2*GTILE_SZ)    // A, Bh
#define G1SMEM_TOTAL (2*G1BUF_SZ) // 65536

__global__ __launch_bounds__(256, 3)
void gemm_wo(const __half* __restrict__ A,
             const __half* __restrict__ Bh,
             float* __restrict__ C)
{
    extern __shared__ char smem[];
    const uint32_t sb = smem_to_u32(smem);
    const int tid  = threadIdx.x;
    const int lane = tid & 31;
    const int wid  = tid >> 5;
    const int wm   = wid & 1;
    const int wn   = wid >> 1;
    const int K = Cv;

    const size_t rowA0 = (size_t)blockIdx.y * 128;
    const size_t rowB0 = (size_t)blockIdx.x * 128;
    const int colBase  = blockIdx.x * 128;

    const __half* tps[2] = { A + rowA0*K, Bh + rowB0*K };

    auto load_chunk = [&](int k0, int b) {
        const uint32_t dst = sb + b * G1BUF_SZ;
        #pragma unroll
        for (int t = 0; t < 2; ++t) {
            const __half* gp = tps[t] + k0;
            const uint32_t td = dst + t * GTILE_SZ;
            #pragma unroll
            for (int i = 0; i < 4; ++i) {
                int v = tid + i * 256;
                int row = v >> 3, colv = v & 7;
                uint32_t boff = row * 128 + colv * 16;
                uint32_t sw = boff ^ ((boff >> 3) & 0x70);
                const void* src = gp + (size_t)row * K + colv * 8;
                asm volatile("cp.async.cg.shared.global [%0], [%1], 16;"
                             :: "r"(td + sw), "l"(src) : "memory");
            }
        }
        asm volatile("cp.async.commit_group;" ::: "memory");
    };

    float acc[4][4][4];
    #pragma unroll
    for (int mt = 0; mt < 4; ++mt)
        #pragma unroll
        for (int nt = 0; nt < 4; ++nt)
            #pragma unroll
            for (int u = 0; u < 4; ++u) acc[mt][nt][u] = 0.f;

    const int  a_r    = lane & 15;
    const uint32_t a_hi = (uint32_t)(lane >> 4) * 16;
    const int  b_r    = (lane & 7) + ((lane >> 4) << 3);
    const uint32_t b_hi = (uint32_t)((lane >> 3) & 1) * 16;

    load_chunk(0, 0);

    for (int c = 0; c < 16; ++c) {
        if (c + 1 < 16) {
            load_chunk((c + 1) * 64, (c + 1) & 1);
            asm volatile("cp.async.wait_group 1;" ::: "memory");
        } else {
            asm volatile("cp.async.wait_group 0;" ::: "memory");
        }
        __syncthreads();

        const uint32_t base = sb + (c & 1) * G1BUF_SZ;
        const uint32_t aT = base;
        const uint32_t bH = base + GTILE_SZ;

        #pragma unroll
        for (int ks = 0; ks < 4; ++ks) {
            const uint32_t kb = ks * 32;
            uint32_t a[4][4], bh[2][4];
            #pragma unroll
            for (int mt = 0; mt < 4; ++mt) {
                int row = wm*64 + mt*16 + a_r;
                uint32_t off = (uint32_t)row*128 + (((kb + a_hi) ^ ((row & 7) << 4)));
                ldmatrix_x4(a[mt], aT + off);
            }
            #pragma unroll
            for (int ntp = 0; ntp < 2; ++ntp) {
                int row = wn*32 + ntp*16 + b_r;
                uint32_t off = (uint32_t)row*128 + (((kb + b_hi) ^ ((row & 7) << 4)));
                ldmatrix_x4(bh[ntp], bH + off);
            }
            #pragma unroll
            for (int mt = 0; mt < 4; ++mt) {
                #pragma unroll
                for (int nt = 0; nt < 4; ++nt) {
                    uint32_t b0 = bh[nt >> 1][(nt & 1)*2 + 0];
                    uint32_t b1 = bh[nt >> 1][(nt & 1)*2 + 1];
                    mma16816h(acc[mt][nt], a[mt], b0, b1);
                }
            }
        }
        __syncthreads();
    }

    #pragma unroll
    for (int mt = 0; mt < 4; ++mt) {
        int r0 = (int)rowA0 + wm*64 + mt*16 + (lane >> 2);
        #pragma unroll
        for (int nt = 0; nt < 4; ++nt) {
            int col = colBase + wn*32 + nt*8 + 2*(lane & 3);
            *(float2*)(C + (size_t)r0 * Cv + col)       = make_float2(acc[mt][nt][0], acc[mt][nt][1]);
            *(float2*)(C + (size_t)(r0 + 8) * Cv + col) = make_float2(acc[mt][nt][2], acc[mt][nt][3]);
        }
    }
}

// ---------------- Pass 1: per-chunk local state ----------------------------
__global__ __launch_bounds__(256)
void ret_pass1()
{
    __shared__ float sK[64*64];
    __shared__ float sV[64*64];
    const int blk = blockIdx.x;
    const int c   = blk & 31;
    const int h   = (blk >> 5) & 15;
    const int b   = blk >> 9;
    const int tid = threadIdx.x;
    const float gamma = 1.0f - exp2f(-5.0f - (float)h);
    const float lg = log2f(gamma);
    const size_t rowbase = ((size_t)(b*Tv + c*64))*Cv + (size_t)h*64;
    const int fq = tid & 15;
    for (int r = tid >> 4; r < 64; r += 16) {
        float w = exp2f((float)(64 - r) * lg);
        float4 kv = *(const float4*)(g_k + rowbase + (size_t)r*Cv + fq*4);
        kv.x *= w; kv.y *= w; kv.z *= w; kv.w *= w;
        *(float4*)&sK[r*64 + fq*4] = kv;
        *(float4*)&sV[r*64 + fq*4] = *(const float4*)(g_v + rowbase + (size_t)r*Cv + fq*4);
    }
    __syncthreads();
    const int dk  = tid >> 2;
    const int dvb = (tid & 3) * 16;
    float acc[16];
    #pragma unroll
    for (int u = 0; u < 16; ++u) acc[u] = 0.f;
    #pragma unroll 8
    for (int j = 0; j < 64; ++j) {
        float kv = sK[j*64 + dk];
        const float4* vp = (const float4*)&sV[j*64 + dvb];
        float4 v0 = vp[0], v1 = vp[1], v2 = vp[2], v3 = vp[3];
        acc[0]  = fmaf(kv, v0.x, acc[0]);  acc[1]  = fmaf(kv, v0.y, acc[1]);
        acc[2]  = fmaf(kv, v0.z, acc[2]);  acc[3]  = fmaf(kv, v0.w, acc[3]);
        acc[4]  = fmaf(kv, v1.x, acc[4]);  acc[5]  = fmaf(kv, v1.y, acc[5]);
        acc[6]  = fmaf(kv, v1.z, acc[6]);  acc[7]  = fmaf(kv, v1.w, acc[7]);
        acc[8]  = fmaf(kv, v2.x, acc[8]);  acc[9]  = fmaf(kv, v2.y, acc[9]);
        acc[10] = fmaf(kv, v2.z, acc[10]); acc[11] = fmaf(kv, v2.w, acc[11]);
        acc[12] = fmaf(kv, v3.x, acc[12]); acc[13] = fmaf(kv, v3.y, acc[13]);
        acc[14] = fmaf(kv, v3.z, acc[14]); acc[15] = fmaf(kv, v3.w, acc[15]);
    }
    float* Gp = g_G + ((size_t)blk*64 + dk)*64 + dvb;
    #pragma unroll
    for (int u = 0; u < 16; u += 4)
        *(float4*)(Gp + u) = make_float4(acc[u], acc[u+1], acc[u+2], acc[u+3]);
}

// ---------------- Pass 2: parallel elementwise scan ------------------------
__global__ void ret_pass2()
{
    int el = blockIdx.x*blockDim.x + threadIdx.x;  // 0 .. 131071
    int bh  = el >> 12;
    int idx = el & 4095;
    int h   = bh & 15;
    const float gamma = 1.0f - exp2f(-5.0f - (float)h);
    const float gL = exp2f(64.0f * log2f(gamma));
    float s = 0.f;
    size_t e = (size_t)bh*NCHUNK*4096 + idx;
    #pragma unroll 8
    for (int c = 0; c < NCHUNK; ++c, e += 4096) {
        g_S[e] = s;
        s = fmaf(gL, s, g_G[e]);
    }
}

// ---------------- Pass 3: intra-chunk + cross + fused GroupNorm ------------
__global__ __launch_bounds__(256)
void ret_pass3(const float* __restrict__ gnw, const float* __restrict__ gnb)
{
    __shared__ float sQt[64*64];
    __shared__ float sT[64*64];
    __shared__ float sA[64*64];
    const int blk = blockIdx.x;
    const int c   = blk & 31;
    const int h   = (blk >> 5) & 15;
    const int b   = blk >> 9;
    const int tid = threadIdx.x;
    const float gamma = 1.0f - exp2f(-5.0f - (float)h);
    const float lg = log2f(gamma);
    const size_t rowbase = ((size_t)(b*Tv + c*64))*Cv + (size_t)h*64;
    const int fq = tid & 15;

    for (int r = tid >> 4; r < 64; r += 16) {
        float4 qv = *(const float4*)(g_q + rowbase + (size_t)r*Cv + fq*4);
        float4 kv = *(const float4*)(g_k + rowbase + (size_t)r*Cv + fq*4);
        int d0 = fq*4;
        sQt[(d0+0)*64 + r] = 0.125f*qv.x;
        sQt[(d0+1)*64 + r] = 0.125f*qv.y;
        sQt[(d0+2)*64 + r] = 0.125f*qv.z;
        sQt[(d0+3)*64 + r] = 0.125f*qv.w;
        sT[(d0+0)*64 + r] = kv.x;
        sT[(d0+1)*64 + r] = kv.y;
        sT[(d0+2)*64 + r] = kv.z;
        sT[(d0+3)*64 + r] = kv.w;
    }
    __syncthreads();

    const int i  = tid >> 2;
    const int jb = (tid & 3) * 16;

    float a[16];
    #pragma unroll
    for (int u = 0; u < 16; ++u) a[u] = 0.f;
    #pragma unroll 8
    for (int d = 0; d < 64; ++d) {
        float qv = sQt[d*64 + i];
        const float4* tp = (const float4*)&sT[d*64 + jb];
        float4 t0 = tp[0], t1 = tp[1], t2 = tp[2], t3 = tp[3];
        a[0]  = fmaf(qv, t0.x, a[0]);  a[1]  = fmaf(qv, t0.y, a[1]);
        a[2]  = fmaf(qv, t0.z, a[2]);  a[3]  = fmaf(qv, t0.w, a[3]);
        a[4]  = fmaf(qv, t1.x, a[4]);  a[5]  = fmaf(qv, t1.y, a[5]);
        a[6]  = fmaf(qv, t1.z, a[6]);  a[7]  = fmaf(qv, t1.w, a[7]);
        a[8]  = fmaf(qv, t2.x, a[8]);  a[9]  = fmaf(qv, t2.y, a[9]);
        a[10] = fmaf(qv, t2.z, a[10]); a[11] = fmaf(qv, t2.w, a[11]);
        a[12] = fmaf(qv, t3.x, a[12]); a[13] = fmaf(qv, t3.y, a[13]);
        a[14] = fmaf(qv, t3.z, a[14]); a[15] = fmaf(qv, t3.w, a[15]);
    }
    #pragma unroll
    for (int u = 0; u < 16; ++u) {
        int j = jb + u;
        float dec = (j <= i) ? exp2f((float)(i - j) * lg) : 0.f;
        sA[j*64 + i] = a[u] * dec;
    }
    __syncthreads();

    const float* Sp = g_S + (size_t)blk*4096;
    for (int e = tid*4; e < 4096; e += 1024)
        *(float4*)&sT[e] = *(const float4*)&Sp[e];
    __syncthreads();

    const int dvb = jb;
    float o[16];
    #pragma unroll
    for (int u = 0; u < 16; ++u) o[u] = 0.f;
    #pragma unroll 8
    for (int d = 0; d < 64; ++d) {
        float qv = sQt[d*64 + i];
        const float4* sp = (const float4*)&sT[d*64 + dvb];
        float4 s0 = sp[0], s1 = sp[1], s2 = sp[2], s3 = sp[3];
        o[0]  = fmaf(qv, s0.x, o[0]);  o[1]  = fmaf(qv, s0.y, o[1]);
        o[2]  = fmaf(qv, s0.z, o[2]);  o[3]  = fmaf(qv, s0.w, o[3]);
        o[4]  = fmaf(qv, s1.x, o[4]);  o[5]  = fmaf(qv, s1.y, o[5]);
        o[6]  = fmaf(qv, s1.z, o[6]);  o[7]  = fmaf(qv, s1.w, o[7]);
        o[8]  = fmaf(qv, s2.x, o[8]);  o[9]  = fmaf(qv, s2.y, o[9]);
        o[10] = fmaf(qv, s2.z, o[10]); o[11] = fmaf(qv, s2.w, o[11]);
        o[12] = fmaf(qv, s3.x, o[12]); o[13] = fmaf(qv, s3.y, o[13]);
        o[14] = fmaf(qv, s3.z, o[14]); o[15] = fmaf(qv, s3.w, o[15]);
    }
    {
        float cd = exp2f((float)i * lg);
        #pragma unroll
        for (int u = 0; u < 16; ++u) o[u] *= cd;
    }
    __syncthreads();

    for (int r = tid >> 4; r < 64; r += 16)
        *(float4*)&sQt[r*64 + fq*4] = *(const float4*)(g_v + rowbase + (size_t)r*Cv + fq*4);
    __syncthreads();

    #pragma unroll 8
    for (int s = 0; s < 64; ++s) {
        float av = sA[s*64 + i];
        const float4* vp = (const float4*)&sQt[s*64 + dvb];
        float4 v0 = vp[0], v1 = vp[1], v2 = vp[2], v3 = vp[3];
        o[0]  = fmaf(av, v0.x, o[0]);  o[1]  = fmaf(av, v0.y, o[1]);
        o[2]  = fmaf(av, v0.z, o[2]);  o[3]  = fmaf(av, v0.w, o[3]);
        o[4]  = fmaf(av, v1.x, o[4]);  o[5]  = fmaf(av, v1.y, o[5]);
        o[6]  = fmaf(av, v1.z, o[6]);  o[7]  = fmaf(av, v1.w, o[7]);
        o[8]  = fmaf(av, v2.x, o[8]);  o[9]  = fmaf(av, v2.y, o[9]);
        o[10] = fmaf(av, v2.z, o[10]); o[11] = fmaf(av, v2.w, o[11]);
        o[12] = fmaf(av, v3.x, o[12]); o[13] = fmaf(av, v3.y, o[13]);
        o[14] = fmaf(av, v3.z, o[14]); o[15] = fmaf(av, v3.w, o[15]);
    }

    float sum = 0.f;
    #pragma unroll
    for (int u = 0; u < 16; ++u) sum += o[u];
    sum += __shfl_xor_sync(0xffffffffu, sum, 1);
    sum += __shfl_xor_sync(0xffffffffu, sum, 2);
    float mean = sum * (1.0f/64.0f);
    float sq = 0.f;
    #pragma unroll
    for (int u = 0; u < 16; ++u) { float dd = o[u] - mean; sq = fmaf(dd, dd, sq); }
    sq += __shfl_xor_sync(0xffffffffu, sq, 1);
    sq += __shfl_xor_sync(0xffffffffu, sq, 2);
    float rstd = rsqrtf(sq * (1.0f/64.0f) + 1e-5f);

    __half* op = g_att16 + ((size_t)(b*Tv + c*64 + i))*Cv + (size_t)h*64 + dvb;
    const float* wg = gnw + h*64 + dvb;
    const float* bg = gnb + h*64 + dvb;
    #pragma unroll
    for (int u = 0; u < 16; u += 2) {
        float r0 = fmaf((o[u+0]-mean)*rstd, wg[u+0], bg[u+0]);
        float r1 = fmaf((o[u+1]-mean)*rstd, wg[u+1], bg[u+1]);
        *(__half2*)(op + u) = __floats2half2_rn(r0, r1);
    }
}

// ---------------------------------------------------------------------------
extern "C" void kernel_launch(void* const* d_in, const int* in_sizes, int n_in,
                              void* d_out, int out_size)
{
    const float* x   = (const float*)d_in[0];
    const float* Wq  = (const float*)d_in[1];
    const float* Wk  = (const float*)d_in[2];
    const float* Wv  = (const float*)d_in[3];
    const float* Wo  = (const float*)d_in[4];
    const float* gnw = (const float*)d_in[5];
    const float* gnb = (const float*)d_in[6];
    float* out = (float*)d_out;

    float *q, *k, *v;
    cudaGetSymbolAddress((void**)&q, g_q);
    cudaGetSymbolAddress((void**)&k, g_k);
    cudaGetSymbolAddress((void**)&v, g_v);
    __half *xh, *att16, *whi, *wlo;
    cudaGetSymbolAddress((void**)&xh,    g_xh);
    cudaGetSymbolAddress((void**)&att16, g_att16);
    cudaGetSymbolAddress((void**)&whi,   g_whi);
    cudaGetSymbolAddress((void**)&wlo,   g_wlo);

    static bool attr_set = false;
    if (!attr_set) {
        cudaFuncSetAttribute(gemm_qkv,
                             cudaFuncAttributeMaxDynamicSharedMemorySize, GSMEM_TOTAL);
        cudaFuncSetAttribute(gemm_wo,
                             cudaFuncAttributeMaxDynamicSharedMemorySize, G1SMEM_TOTAL);
        attr_set = true;
    }

    const int nx4 = (Mv*Cv)/4;
    split_x<<<(nx4+255)/256, 256>>>(x, xh, nx4);
    split_4w<<<(4*CC/4)/256, 256>>>(Wq, Wk, Wv, Wo, whi, wlo);
    rope_table<<<(Tv*32)/256, 256>>>();

    // merged QKV projection with fused rope
    gemm_qkv<<<dim3(24, 32), 256, GSMEM_TOTAL>>>(xh, whi, wlo, q, k, v);

    ret_pass1<<<Bv*Hv*NCHUNK, 256>>>();
    ret_pass2<<<(Bv*Hv*4096)/256, 256>>>();
    ret_pass3<<<Bv*Hv*NCHUNK, 256>>>(gnw, gnb);

    // output GEMM: Wo rows are 3*CC..4*CC of the concatenated split buffer
    gemm_wo<<<dim3(8, 32), 256, G1SMEM_TOTAL>>>(att16, whi + (size_t)3*CC, out);
}

// round 11
// speedup vs baseline: 4.1764x; 1.6367x over previous
#include <cuda_runtime.h>
#include <cuda_fp16.h>
#include <math.h>
#include <stdint.h>

#define Bv 2
#define Tv 2048
#define Cv 1024
#define Hv 16
#define DHv 64
#define Mv (Bv*Tv)       // 4096 rows
#define NCHUNK 32        // T / 64
#define CC (Cv*Cv)

// ---------------- scratch (static device memory; no allocs) ----------------
__device__ float g_q[Mv*Cv];
__device__ float g_k[Mv*Cv];
__device__ float g_v[Mv*Cv];
__device__ float g_G[Bv*Hv*NCHUNK*DHv*DHv];
__device__ float g_S[Bv*Hv*NCHUNK*DHv*DHv];
__device__ float g_rope_cos[Tv*32];
__device__ float g_rope_sin[Tv*32];

__device__ __align__(256) __half g_att16[Mv*Cv];     // fp16 retention output
__device__ __align__(256) __half g_xh[Mv*Cv];        // fp16 x
__device__ __align__(256) __half g_whi[4*CC];        // fp16 hi of Wq,Wk,Wv,Wo
__device__ __align__(256) __half g_wlo[4*CC];        // fp16 lo residuals

// ======================= helpers ===========================================
__device__ __forceinline__ uint32_t smem_to_u32(const void* p) {
    uint32_t a;
    asm("{ .reg .u64 t; cvta.to.shared.u64 t, %1; cvt.u32.u64 %0, t; }" : "=r"(a) : "l"(p));
    return a;
}
__device__ __forceinline__ void ldmatrix_x4(uint32_t* r, uint32_t addr) {
    asm volatile("ldmatrix.sync.aligned.m8n8.x4.shared.b16 {%0,%1,%2,%3}, [%4];"
                 : "=r"(r[0]), "=r"(r[1]), "=r"(r[2]), "=r"(r[3]) : "r"(addr));
}
__device__ __forceinline__ void mma16816h(float* d, const uint32_t* a, uint32_t b0, uint32_t b1) {
    asm volatile(
        "mma.sync.aligned.m16n8k16.row.col.f32.f16.f16.f32 "
        "{%0,%1,%2,%3}, {%4,%5,%6,%7}, {%8,%9}, {%0,%1,%2,%3};"
        : "+f"(d[0]), "+f"(d[1]), "+f"(d[2]), "+f"(d[3])
        : "r"(a[0]), "r"(a[1]), "r"(a[2]), "r"(a[3]), "r"(b0), "r"(b1));
}

// =================== small prep kernels ====================================
__global__ void split_x(const float* __restrict__ s, __half* __restrict__ hi, int n4)
{
    int i = blockIdx.x*blockDim.x + threadIdx.x;
    if (i >= n4) return;
    float4 f = ((const float4*)s)[i];
    __half2* hp = (__half2*)(hi + (size_t)i*4);
    hp[0] = __floats2half2_rn(f.x, f.y);
    hp[1] = __floats2half2_rn(f.z, f.w);
}

__global__ void split_4w(const float* __restrict__ W0, const float* __restrict__ W1,
                         const float* __restrict__ W2, const float* __restrict__ W3,
                         __half* __restrict__ hi, __half* __restrict__ lo)
{
    int i = blockIdx.x*blockDim.x + threadIdx.x;   // 0 .. 4*CC/4
    int w = i >> 18;
    const float* s = (w==0) ? W0 : (w==1) ? W1 : (w==2) ? W2 : W3;
    int j = i & 262143;
    float4 f = ((const float4*)s)[j];
    __half h0 = __float2half_rn(f.x);
    __half h1 = __float2half_rn(f.y);
    __half h2 = __float2half_rn(f.z);
    __half h3 = __float2half_rn(f.w);
    __half l0 = __float2half_rn(f.x - __half2float(h0));
    __half l1 = __float2half_rn(f.y - __half2float(h1));
    __half l2 = __float2half_rn(f.z - __half2float(h2));
    __half l3 = __float2half_rn(f.w - __half2float(h3));
    __half2* hp = (__half2*)(hi + (size_t)i*4);
    __half2* lp = (__half2*)(lo + (size_t)i*4);
    hp[0] = __halves2half2(h0, h1); hp[1] = __halves2half2(h2, h3);
    lp[0] = __halves2half2(l0, l1); lp[1] = __halves2half2(l2, l3);
}

__global__ void rope_table()
{
    int i = blockIdx.x*blockDim.x + threadIdx.x;   // 0..65535
    int dm = i & 31, t = i >> 5;
    float inv = exp2f(-(float)dm * (13.287712379549449f / 32.0f));
    float ang = (float)t * inv;
    float s, c;
    sincosf(ang, &s, &c);
    g_rope_cos[i] = c;
    g_rope_sin[i] = s;
}

// =================== fp16 2-term QKV GEMM (rope fused) =====================
#define GTILE_SZ 16384          // 128 rows x 128 bytes
#define GBUF_SZ  (3*GTILE_SZ)   // A, Bh, Bl
#define GSMEM_TOTAL (2*GBUF_SZ) // 98304

__global__ __launch_bounds__(256, 2)
void gemm_qkv(const __half* __restrict__ A,
              const __half* __restrict__ Bh,
              const __half* __restrict__ Bl,
              float* __restrict__ o0, float* __restrict__ o1, float* __restrict__ o2)
{
    extern __shared__ char smem[];
    const uint32_t sb = smem_to_u32(smem);
    const int tid  = threadIdx.x;
    const int lane = tid & 31;
    const int wid  = tid >> 5;
    const int wm   = wid & 1;
    const int wn   = wid >> 1;
    const int K = Cv;

    const size_t rowA0 = (size_t)blockIdx.y * 128;
    const size_t rowB0 = (size_t)blockIdx.x * 128;
    const int which   = blockIdx.x >> 3;            // 0=q 1=k 2=v
    float* C = (which == 0) ? o0 : (which == 1) ? o1 : o2;
    const int colBase = (blockIdx.x & 7) * 128;

    const __half* tps[3] = { A + rowA0*K, Bh + rowB0*K, Bl + rowB0*K };

    auto load_chunk = [&](int k0, int b) {
        const uint32_t dst = sb + b * GBUF_SZ;
        #pragma unroll
        for (int t = 0; t < 3; ++t) {
            const __half* gp = tps[t] + k0;
            const uint32_t td = dst + t * GTILE_SZ;
            #pragma unroll
            for (int i = 0; i < 4; ++i) {
                int v = tid + i * 256;
                int row = v >> 3, colv = v & 7;
                uint32_t boff = row * 128 + colv * 16;
                uint32_t sw = boff ^ ((boff >> 3) & 0x70);
                const void* src = gp + (size_t)row * K + colv * 8;
                asm volatile("cp.async.cg.shared.global [%0], [%1], 16;"
                             :: "r"(td + sw), "l"(src) : "memory");
            }
        }
        asm volatile("cp.async.commit_group;" ::: "memory");
    };

    float acc[4][4][4];
    #pragma unroll
    for (int mt = 0; mt < 4; ++mt)
        #pragma unroll
        for (int nt = 0; nt < 4; ++nt)
            #pragma unroll
            for (int u = 0; u < 4; ++u) acc[mt][nt][u] = 0.f;

    const int  a_r    = lane & 15;
    const uint32_t a_hi = (uint32_t)(lane >> 4) * 16;
    const int  b_r    = (lane & 7) + ((lane >> 4) << 3);
    const uint32_t b_hi = (uint32_t)((lane >> 3) & 1) * 16;

    load_chunk(0, 0);

    for (int c = 0; c < 16; ++c) {
        if (c + 1 < 16) {
            load_chunk((c + 1) * 64, (c + 1) & 1);
            asm volatile("cp.async.wait_group 1;" ::: "memory");
        } else {
            asm volatile("cp.async.wait_group 0;" ::: "memory");
        }
        __syncthreads();

        const uint32_t base = sb + (c & 1) * GBUF_SZ;
        const uint32_t aT = base;
        const uint32_t bH = base + GTILE_SZ, bL = base + 2*GTILE_SZ;

        #pragma unroll
        for (int ks = 0; ks < 4; ++ks) {
            const uint32_t kb = ks * 32;
            uint32_t a[4][4], bh[2][4], bl[2][4];
            #pragma unroll
            for (int mt = 0; mt < 4; ++mt) {
                int row = wm*64 + mt*16 + a_r;
                uint32_t off = (uint32_t)row*128 + (((kb + a_hi) ^ ((row & 7) << 4)));
                ldmatrix_x4(a[mt], aT + off);
            }
            #pragma unroll
            for (int ntp = 0; ntp < 2; ++ntp) {
                int row = wn*32 + ntp*16 + b_r;
                uint32_t off = (uint32_t)row*128 + (((kb + b_hi) ^ ((row & 7) << 4)));
                ldmatrix_x4(bh[ntp], bH + off);
                ldmatrix_x4(bl[ntp], bL + off);
            }
            #pragma unroll
            for (int mt = 0; mt < 4; ++mt) {
                #pragma unroll
                for (int nt = 0; nt < 4; ++nt) {
                    uint32_t b0 = bh[nt >> 1][(nt & 1)*2 + 0];
                    uint32_t b1 = bh[nt >> 1][(nt & 1)*2 + 1];
                    uint32_t c0 = bl[nt >> 1][(nt & 1)*2 + 0];
                    uint32_t c1 = bl[nt >> 1][(nt & 1)*2 + 1];
                    mma16816h(acc[mt][nt], a[mt], b0, b1);
                    mma16816h(acc[mt][nt], a[mt], c0, c1);
                }
            }
        }
        __syncthreads();
    }

    // ---- stage tile to smem, apply rope (q,k), store ----
    float* st = (float*)smem;
    #pragma unroll
    for (int mt = 0; mt < 4; ++mt) {
        int r = wm*64 + mt*16 + (lane >> 2);
        #pragma unroll
        for (int nt = 0; nt < 4; ++nt) {
            int col = wn*32 + nt*8 + 2*(lane & 3);
            *(float2*)&st[r*128 + col]       = make_float2(acc[mt][nt][0], acc[mt][nt][1]);
            *(float2*)&st[(r+8)*128 + col]   = make_float2(acc[mt][nt][2], acc[mt][nt][3]);
        }
    }
    __syncthreads();

    #pragma unroll 4
    for (int it = 0; it < 32; ++it) {
        int unit = tid + it*256;
        int row = unit >> 6;
        int col = (unit & 63) * 2;
        float2 val = *(float2*)&st[row*128 + col];
        float2 res = val;
        if (which < 2) {
            int gr = (int)rowA0 + row;
            int tt = gr & (Tv-1);
            int d = col & 63;
            float2 par;
            if (d < 32) {
                par = *(float2*)&st[row*128 + col + 32];
                par.x = -par.x; par.y = -par.y;
            } else {
                par = *(float2*)&st[row*128 + col - 32];
            }
            int dm = d & 31;
            float2 cc = *(const float2*)&g_rope_cos[tt*32 + dm];
            float2 ss = *(const float2*)&g_rope_sin[tt*32 + dm];
            res.x = val.x*cc.x + par.x*ss.x;
            res.y = val.y*cc.y + par.y*ss.y;
        }
        *(float2*)(C + ((size_t)rowA0 + row)*Cv + colBase + col) = res;
    }
}

// =================== fp16 1-term Wo GEMM ===================================
#define G1BUF_SZ  (2*GTILE_SZ)    // A, Bh
#define G1SMEM_TOTAL (2*G1BUF_SZ) // 65536

__global__ __launch_bounds__(256, 3)
void gemm_wo(const __half* __restrict__ A,
             const __half* __restrict__ Bh,
             float* __restrict__ C)
{
    extern __shared__ char smem[];
    const uint32_t sb = smem_to_u32(smem);
    const int tid  = threadIdx.x;
    const int lane = tid & 31;
    const int wid  = tid >> 5;
    const int wm   = wid & 1;
    const int wn   = wid >> 1;
    const int K = Cv;

    const size_t rowA0 = (size_t)blockIdx.y * 128;
    const size_t rowB0 = (size_t)blockIdx.x * 128;
    const int colBase  = blockIdx.x * 128;

    const __half* tps[2] = { A + rowA0*K, Bh + rowB0*K };

    auto load_chunk = [&](int k0, int b) {
        const uint32_t dst = sb + b * G1BUF_SZ;
        #pragma unroll
        for (int t = 0; t < 2; ++t) {
            const __half* gp = tps[t] + k0;
            const uint32_t td = dst + t * GTILE_SZ;
            #pragma unroll
            for (int i = 0; i < 4; ++i) {
                int v = tid + i * 256;
                int row = v >> 3, colv = v & 7;
                uint32_t boff = row * 128 + colv * 16;
                uint32_t sw = boff ^ ((boff >> 3) & 0x70);
                const void* src = gp + (size_t)row * K + colv * 8;
                asm volatile("cp.async.cg.shared.global [%0], [%1], 16;"
                             :: "r"(td + sw), "l"(src) : "memory");
            }
        }
        asm volatile("cp.async.commit_group;" ::: "memory");
    };

    float acc[4][4][4];
    #pragma unroll
    for (int mt = 0; mt < 4; ++mt)
        #pragma unroll
        for (int nt = 0; nt < 4; ++nt)
            #pragma unroll
            for (int u = 0; u < 4; ++u) acc[mt][nt][u] = 0.f;

    const int  a_r    = lane & 15;
    const uint32_t a_hi = (uint32_t)(lane >> 4) * 16;
    const int  b_r    = (lane & 7) + ((lane >> 4) << 3);
    const uint32_t b_hi = (uint32_t)((lane >> 3) & 1) * 16;

    load_chunk(0, 0);

    for (int c = 0; c < 16; ++c) {
        if (c + 1 < 16) {
            load_chunk((c + 1) * 64, (c + 1) & 1);
            asm volatile("cp.async.wait_group 1;" ::: "memory");
        } else {
            asm volatile("cp.async.wait_group 0;" ::: "memory");
        }
        __syncthreads();

        const uint32_t base = sb + (c & 1) * G1BUF_SZ;
        const uint32_t aT = base;
        const uint32_t bH = base + GTILE_SZ;

        #pragma unroll
        for (int ks = 0; ks < 4; ++ks) {
            const uint32_t kb = ks * 32;
            uint32_t a[4][4], bh[2][4];
            #pragma unroll
            for (int mt = 0; mt < 4; ++mt) {
                int row = wm*64 + mt*16 + a_r;
                uint32_t off = (uint32_t)row*128 + (((kb + a_hi) ^ ((row & 7) << 4)));
                ldmatrix_x4(a[mt], aT + off);
            }
            #pragma unroll
            for (int ntp = 0; ntp < 2; ++ntp) {
                int row = wn*32 + ntp*16 + b_r;
                uint32_t off = (uint32_t)row*128 + (((kb + b_hi) ^ ((row & 7) << 4)));
                ldmatrix_x4(bh[ntp], bH + off);
            }
            #pragma unroll
            for (int mt = 0; mt < 4; ++mt) {
                #pragma unroll
                for (int nt = 0; nt < 4; ++nt) {
                    uint32_t b0 = bh[nt >> 1][(nt & 1)*2 + 0];
                    uint32_t b1 = bh[nt >> 1][(nt & 1)*2 + 1];
                    mma16816h(acc[mt][nt], a[mt], b0, b1);
                }
            }
        }
        __syncthreads();
    }

    #pragma unroll
    for (int mt = 0; mt < 4; ++mt) {
        int r0 = (int)rowA0 + wm*64 + mt*16 + (lane >> 2);
        #pragma unroll
        for (int nt = 0; nt < 4; ++nt) {
            int col = colBase + wn*32 + nt*8 + 2*(lane & 3);
            *(float2*)(C + (size_t)r0 * Cv + col)       = make_float2(acc[mt][nt][0], acc[mt][nt][1]);
            *(float2*)(C + (size_t)(r0 + 8) * Cv + col) = make_float2(acc[mt][nt][2], acc[mt][nt][3]);
        }
    }
}

// ---------------- Pass 1: per-chunk local state (4x4 register tiles) -------
__global__ __launch_bounds__(256)
void ret_pass1()
{
    __shared__ float sK[64*64];   // [j][dk], pre-scaled by gamma^{64-j}
    __shared__ float sV[64*64];   // [j][dv]
    const int blk = blockIdx.x;
    const int c   = blk & 31;
    const int h   = (blk >> 5) & 15;
    const int b   = blk >> 9;
    const int tid = threadIdx.x;
    const float gamma = 1.0f - exp2f(-5.0f - (float)h);
    const float lg = log2f(gamma);
    const size_t rowbase = ((size_t)(b*Tv + c*64))*Cv + (size_t)h*64;
    const int fq = tid & 15;
    for (int r = tid >> 4; r < 64; r += 16) {
        float w = exp2f((float)(64 - r) * lg);
        float4 kv = *(const float4*)(g_k + rowbase + (size_t)r*Cv + fq*4);
        kv.x *= w; kv.y *= w; kv.z *= w; kv.w *= w;
        *(float4*)&sK[r*64 + fq*4] = kv;
        *(float4*)&sV[r*64 + fq*4] = *(const float4*)(g_v + rowbase + (size_t)r*Cv + fq*4);
    }
    __syncthreads();

    const int i0 = (tid >> 4) * 4;   // dk group
    const int j0 = (tid & 15) * 4;   // dv group
    float acc[4][4];
    #pragma unroll
    for (int ii = 0; ii < 4; ++ii)
        #pragma unroll
        for (int jj = 0; jj < 4; ++jj) acc[ii][jj] = 0.f;

    #pragma unroll 8
    for (int j = 0; j < 64; ++j) {
        float4 kv = *(const float4*)&sK[j*64 + i0];
        float4 vv = *(const float4*)&sV[j*64 + j0];
        const float kk[4] = {kv.x, kv.y, kv.z, kv.w};
        const float vx[4] = {vv.x, vv.y, vv.z, vv.w};
        #pragma unroll
        for (int ii = 0; ii < 4; ++ii)
            #pragma unroll
            for (int jj = 0; jj < 4; ++jj)
                acc[ii][jj] = fmaf(kk[ii], vx[jj], acc[ii][jj]);
    }
    #pragma unroll
    for (int ii = 0; ii < 4; ++ii) {
        float* Gp = g_G + ((size_t)blk*64 + i0 + ii)*64 + j0;
        *(float4*)Gp = make_float4(acc[ii][0], acc[ii][1], acc[ii][2], acc[ii][3]);
    }
}

// ---------------- Pass 2: parallel elementwise scan ------------------------
__global__ void ret_pass2()
{
    int el = blockIdx.x*blockDim.x + threadIdx.x;  // 0 .. 131071
    int bh  = el >> 12;
    int idx = el & 4095;
    int h   = bh & 15;
    const float gamma = 1.0f - exp2f(-5.0f - (float)h);
    const float gL = exp2f(64.0f * log2f(gamma));
    float s = 0.f;
    size_t e = (size_t)bh*NCHUNK*4096 + idx;
    #pragma unroll 8
    for (int c = 0; c < NCHUNK; ++c, e += 4096) {
        g_S[e] = s;
        s = fmaf(gL, s, g_G[e]);
    }
}

// ---------------- Pass 3: intra + cross + GroupNorm (4x4 register tiles) ---
__global__ __launch_bounds__(256)
void ret_pass3(const float* __restrict__ gnw, const float* __restrict__ gnb)
{
    __shared__ float sQt[64*64];  // Q^T * 0.125 [d][i]; later V [s][dv]
    __shared__ float sT[64*64];   // K^T [d][j]; later S [dk][dv]
    __shared__ float sA[64*64];   // A^T [j][i]
    const int blk = blockIdx.x;
    const int c   = blk & 31;
    const int h   = (blk >> 5) & 15;
    const int b   = blk >> 9;
    const int tid = threadIdx.x;
    const float gamma = 1.0f - exp2f(-5.0f - (float)h);
    const float lg = log2f(gamma);
    const size_t rowbase = ((size_t)(b*Tv + c*64))*Cv + (size_t)h*64;
    const int fq = tid & 15;

    for (int r = tid >> 4; r < 64; r += 16) {
        float4 qv = *(const float4*)(g_q + rowbase + (size_t)r*Cv + fq*4);
        float4 kv = *(const float4*)(g_k + rowbase + (size_t)r*Cv + fq*4);
        int d0 = fq*4;
        sQt[(d0+0)*64 + r] = 0.125f*qv.x;
        sQt[(d0+1)*64 + r] = 0.125f*qv.y;
        sQt[(d0+2)*64 + r] = 0.125f*qv.z;
        sQt[(d0+3)*64 + r] = 0.125f*qv.w;
        sT[(d0+0)*64 + r] = kv.x;
        sT[(d0+1)*64 + r] = kv.y;
        sT[(d0+2)*64 + r] = kv.z;
        sT[(d0+3)*64 + r] = kv.w;
    }
    __syncthreads();

    const int i0 = (tid >> 4) * 4;   // token rows
    const int j0 = (tid & 15) * 4;   // cols (j for A; dv for o)

    // ---- A[i][j] = (q_i . k_j)/8 * gamma^{i-j} (causal), stored as A^T ----
    {
        float a[4][4];
        #pragma unroll
        for (int ii = 0; ii < 4; ++ii)
            #pragma unroll
            for (int jj = 0; jj < 4; ++jj) a[ii][jj] = 0.f;
        #pragma unroll 8
        for (int d = 0; d < 64; ++d) {
            float4 qv = *(const float4*)&sQt[d*64 + i0];
            float4 kv = *(const float4*)&sT[d*64 + j0];
            const float qq[4] = {qv.x, qv.y, qv.z, qv.w};
            const float kk[4] = {kv.x, kv.y, kv.z, kv.w};
            #pragma unroll
            for (int ii = 0; ii < 4; ++ii)
                #pragma unroll
                for (int jj = 0; jj < 4; ++jj)
                    a[ii][jj] = fmaf(qq[ii], kk[jj], a[ii][jj]);
        }
        #pragma unroll
        for (int jj = 0; jj < 4; ++jj) {
            int j = j0 + jj;
            float4 row;
            float* rp = (float*)&row;
            #pragma unroll
            for (int ii = 0; ii < 4; ++ii) {
                int i = i0 + ii;
                float dec = (j <= i) ? exp2f((float)(i - j) * lg) : 0.f;
                rp[ii] = a[ii][jj] * dec;
            }
            *(float4*)&sA[j*64 + i0] = row;
        }
    }
    __syncthreads();   // A^T written; k in sT no longer needed

    // ---- load S (state before chunk) into sT ----
    const float* Sp = g_S + (size_t)blk*4096;
    for (int e = tid*4; e < 4096; e += 1024)
        *(float4*)&sT[e] = *(const float4*)&Sp[e];
    __syncthreads();

    // ---- cross term: o = gamma^i * (q_i @ S) ----
    float o[4][4];
    #pragma unroll
    for (int ii = 0; ii < 4; ++ii)
        #pragma unroll
        for (int jj = 0; jj < 4; ++jj) o[ii][jj] = 0.f;
    #pragma unroll 8
    for (int d = 0; d < 64; ++d) {
        float4 qv = *(const float4*)&sQt[d*64 + i0];
        float4 sv = *(const float4*)&sT[d*64 + j0];
        const float qq[4] = {qv.x, qv.y, qv.z, qv.w};
        const float ss[4] = {sv.x, sv.y, sv.z, sv.w};
        #pragma unroll
        for (int ii = 0; ii < 4; ++ii)
            #pragma unroll
            for (int jj = 0; jj < 4; ++jj)
                o[ii][jj] = fmaf(qq[ii], ss[jj], o[ii][jj]);
    }
    #pragma unroll
    for (int ii = 0; ii < 4; ++ii) {
        float cd = exp2f((float)(i0 + ii) * lg);
        #pragma unroll
        for (int jj = 0; jj < 4; ++jj) o[ii][jj] *= cd;
    }
    __syncthreads();   // q in sQt no longer needed

    // ---- load V into sQt ([s][dv]) ----
    for (int r = tid >> 4; r < 64; r += 16)
        *(float4*)&sQt[r*64 + fq*4] = *(const float4*)(g_v + rowbase + (size_t)r*Cv + fq*4);
    __syncthreads();

    // ---- o += A @ V ----
    #pragma unroll 8
    for (int s = 0; s < 64; ++s) {
        float4 av = *(const float4*)&sA[s*64 + i0];
        float4 vv = *(const float4*)&sQt[s*64 + j0];
        const float aa[4] = {av.x, av.y, av.z, av.w};
        const float vx[4] = {vv.x, vv.y, vv.z, vv.w};
        #pragma unroll
        for (int ii = 0; ii < 4; ++ii)
            #pragma unroll
            for (int jj = 0; jj < 4; ++jj)
                o[ii][jj] = fmaf(aa[ii], vx[jj], o[ii][jj]);
    }

    // ---- GroupNorm per row (64 cols spread over 16 lanes, 4 each) ----
    float rsum[4], rsq[4];
    #pragma unroll
    for (int ii = 0; ii < 4; ++ii) {
        float s = o[ii][0] + o[ii][1] + o[ii][2] + o[ii][3];
        s += __shfl_xor_sync(0xffffffffu, s, 1);
        s += __shfl_xor_sync(0xffffffffu, s, 2);
        s += __shfl_xor_sync(0xffffffffu, s, 4);
        s += __shfl_xor_sync(0xffffffffu, s, 8);
        rsum[ii] = s * (1.0f/64.0f);
    }
    #pragma unroll
    for (int ii = 0; ii < 4; ++ii) {
        float q0 = o[ii][0]-rsum[ii], q1 = o[ii][1]-rsum[ii];
        float q2 = o[ii][2]-rsum[ii], q3 = o[ii][3]-rsum[ii];
        float s = q0*q0 + q1*q1 + q2*q2 + q3*q3;
        s += __shfl_xor_sync(0xffffffffu, s, 1);
        s += __shfl_xor_sync(0xffffffffu, s, 2);
        s += __shfl_xor_sync(0xffffffffu, s, 4);
        s += __shfl_xor_sync(0xffffffffu, s, 8);
        rsq[ii] = rsqrtf(s * (1.0f/64.0f) + 1e-5f);
    }

    const float* wg = gnw + h*64 + j0;
    const float* bg = gnb + h*64 + j0;
    float w0 = wg[0], w1 = wg[1], w2 = wg[2], w3 = wg[3];
    float b0 = bg[0], b1 = bg[1], b2 = bg[2], b3 = bg[3];
    #pragma unroll
    for (int ii = 0; ii < 4; ++ii) {
        int i = i0 + ii;
        __half* op = g_att16 + ((size_t)(b*Tv + c*64 + i))*Cv + (size_t)h*64 + j0;
        float r0 = fmaf((o[ii][0]-rsum[ii])*rsq[ii], w0, b0);
        float r1 = fmaf((o[ii][1]-rsum[ii])*rsq[ii], w1, b1);
        float r2 = fmaf((o[ii][2]-rsum[ii])*rsq[ii], w2, b2);
        float r3 = fmaf((o[ii][3]-rsum[ii])*rsq[ii], w3, b3);
        *(__half2*)(op)     = __floats2half2_rn(r0, r1);
        *(__half2*)(op + 2) = __floats2half2_rn(r2, r3);
    }
}

// ---------------------------------------------------------------------------
extern "C" void kernel_launch(void* const* d_in, const int* in_sizes, int n_in,
                              void* d_out, int out_size)
{
    const float* x   = (const float*)d_in[0];
    const float* Wq  = (const float*)d_in[1];
    const float* Wk  = (const float*)d_in[2];
    const float* Wv  = (const float*)d_in[3];
    const float* Wo  = (const float*)d_in[4];
    const float* gnw = (const float*)d_in[5];
    const float* gnb = (const float*)d_in[6];
    float* out = (float*)d_out;

    float *q, *k, *v;
    cudaGetSymbolAddress((void**)&q, g_q);
    cudaGetSymbolAddress((void**)&k, g_k);
    cudaGetSymbolAddress((void**)&v, g_v);
    __half *xh, *att16, *whi, *wlo;
    cudaGetSymbolAddress((void**)&xh,    g_xh);
    cudaGetSymbolAddress((void**)&att16, g_att16);
    cudaGetSymbolAddress((void**)&whi,   g_whi);
    cudaGetSymbolAddress((void**)&wlo,   g_wlo);

    static bool attr_set = false;
    if (!attr_set) {
        cudaFuncSetAttribute(gemm_qkv,
                             cudaFuncAttributeMaxDynamicSharedMemorySize, GSMEM_TOTAL);
        cudaFuncSetAttribute(gemm_wo,
                             cudaFuncAttributeMaxDynamicSharedMemorySize, G1SMEM_TOTAL);
        attr_set = true;
    }

    const int nx4 = (Mv*Cv)/4;
    split_x<<<(nx4+255)/256, 256>>>(x, xh, nx4);
    split_4w<<<(4*CC/4)/256, 256>>>(Wq, Wk, Wv, Wo, whi, wlo);
    rope_table<<<(Tv*32)/256, 256>>>();

    gemm_qkv<<<dim3(24, 32), 256, GSMEM_TOTAL>>>(xh, whi, wlo, q, k, v);

    ret_pass1<<<Bv*Hv*NCHUNK, 256>>>();
    ret_pass2<<<(Bv*Hv*4096)/256, 256>>>();
    ret_pass3<<<Bv*Hv*NCHUNK, 256>>>(gnw, gnb);

    gemm_wo<<<dim3(8, 32), 256, G1SMEM_TOTAL>>>(att16, whi + (size_t)3*CC, out);
}

// round 13
// speedup vs baseline: 5.5597x; 1.3312x over previous
#include <cuda_runtime.h>
#include <cuda_fp16.h>
#include <math.h>
#include <stdint.h>

#define Bv 2
#define Tv 2048
#define Cv 1024
#define Hv 16
#define DHv 64
#define Mv (Bv*Tv)       // 4096 rows
#define NCHUNK 32        // T / 64
#define CC (Cv*Cv)

// ---------------- scratch (static device memory; no allocs) ----------------
__device__ float g_q[Mv*Cv];
__device__ float g_k[Mv*Cv];
__device__ float g_v[Mv*Cv];
__device__ float g_G[Bv*Hv*NCHUNK*DHv*DHv];
__device__ float g_S[Bv*Hv*NCHUNK*DHv*DHv];
__device__ float g_rope_cos[Tv*32];
__device__ float g_rope_sin[Tv*32];

__device__ __align__(256) __half g_att16[Mv*Cv];     // fp16 retention output
__device__ __align__(256) __half g_xh[Mv*Cv];        // fp16 x
__device__ __align__(256) __half g_whi[4*CC];        // fp16 Wq,Wk,Wv,Wo (concat rows)

// ======================= helpers ===========================================
__device__ __forceinline__ uint32_t smem_to_u32(const void* p) {
    uint32_t a;
    asm("{ .reg .u64 t; cvta.to.shared.u64 t, %1; cvt.u32.u64 %0, t; }" : "=r"(a) : "l"(p));
    return a;
}
__device__ __forceinline__ void ldmatrix_x4(uint32_t* r, uint32_t addr) {
    asm volatile("ldmatrix.sync.aligned.m8n8.x4.shared.b16 {%0,%1,%2,%3}, [%4];"
                 : "=r"(r[0]), "=r"(r[1]), "=r"(r[2]), "=r"(r[3]) : "r"(addr));
}
__device__ __forceinline__ void mma16816h(float* d, const uint32_t* a, uint32_t b0, uint32_t b1) {
    asm volatile(
        "mma.sync.aligned.m16n8k16.row.col.f32.f16.f16.f32 "
        "{%0,%1,%2,%3}, {%4,%5,%6,%7}, {%8,%9}, {%0,%1,%2,%3};"
        : "+f"(d[0]), "+f"(d[1]), "+f"(d[2]), "+f"(d[3])
        : "r"(a[0]), "r"(a[1]), "r"(a[2]), "r"(a[3]), "r"(b0), "r"(b1));
}

// =================== small prep kernels ====================================
__global__ void split_x(const float* __restrict__ s, __half* __restrict__ hi, int n4)
{
    int i = blockIdx.x*blockDim.x + threadIdx.x;
    if (i >= n4) return;
    float4 f = ((const float4*)s)[i];
    __half2* hp = (__half2*)(hi + (size_t)i*4);
    hp[0] = __floats2half2_rn(f.x, f.y);
    hp[1] = __floats2half2_rn(f.z, f.w);
}

__global__ void conv_4w(const float* __restrict__ W0, const float* __restrict__ W1,
                        const float* __restrict__ W2, const float* __restrict__ W3,
                        __half* __restrict__ hi)
{
    int i = blockIdx.x*blockDim.x + threadIdx.x;   // 0 .. 4*CC/4
    int w = i >> 18;
    const float* s = (w==0) ? W0 : (w==1) ? W1 : (w==2) ? W2 : W3;
    int j = i & 262143;
    float4 f = ((const float4*)s)[j];
    __half2* hp = (__half2*)(hi + (size_t)i*4);
    hp[0] = __floats2half2_rn(f.x, f.y);
    hp[1] = __floats2half2_rn(f.z, f.w);
}

__global__ void rope_table()
{
    int i = blockIdx.x*blockDim.x + threadIdx.x;   // 0..65535
    int dm = i & 31, t = i >> 5;
    float inv = exp2f(-(float)dm * (13.287712379549449f / 32.0f));
    float ang = (float)t * inv;
    float s, c;
    sincosf(ang, &s, &c);
    g_rope_cos[i] = c;
    g_rope_sin[i] = s;
}

// =================== fp16 1-term QKV GEMM (rope fused) =====================
// q,k,v[M,1024] = x[M,1024](fp16) * W[3072,1024]^T(fp16); rope on q,k.
// CTA tile 128x128, BK=64 (128B swizzled rows), 3-stage cp.async pipeline.
#define GTILE_SZ 16384          // 128 rows x 128 bytes
#define GBUF_SZ  (2*GTILE_SZ)   // A, B
#define GSMEM_TOTAL (3*GBUF_SZ) // 98304 (also covers 64KB rope staging)

__global__ __launch_bounds__(256, 2)
void gemm_qkv(const __half* __restrict__ A,
              const __half* __restrict__ Bh,
              float* __restrict__ o0, float* __restrict__ o1, float* __restrict__ o2)
{
    extern __shared__ char smem[];
    const uint32_t sb = smem_to_u32(smem);
    const int tid  = threadIdx.x;
    const int lane = tid & 31;
    const int wid  = tid >> 5;
    const int wm   = wid & 1;
    const int wn   = wid >> 1;
    const int K = Cv;

    const size_t rowA0 = (size_t)blockIdx.y * 128;
    const size_t rowB0 = (size_t)blockIdx.x * 128;
    const int which   = blockIdx.x >> 3;            // 0=q 1=k 2=v
    float* C = (which == 0) ? o0 : (which == 1) ? o1 : o2;
    const int colBase = (blockIdx.x & 7) * 128;

    const __half* tps[2] = { A + rowA0*K, Bh + rowB0*K };

    auto load_chunk = [&](int k0, int b) {
        const uint32_t dst = sb + b * GBUF_SZ;
        #pragma unroll
        for (int t = 0; t < 2; ++t) {
            const __half* gp = tps[t] + k0;
            const uint32_t td = dst + t * GTILE_SZ;
            #pragma unroll
            for (int i = 0; i < 4; ++i) {
                int v = tid + i * 256;
                int row = v >> 3, colv = v & 7;
                uint32_t boff = row * 128 + colv * 16;
                uint32_t sw = boff ^ ((boff >> 3) & 0x70);
                const void* src = gp + (size_t)row * K + colv * 8;
                asm volatile("cp.async.cg.shared.global [%0], [%1], 16;"
                             :: "r"(td + sw), "l"(src) : "memory");
            }
        }
        asm volatile("cp.async.commit_group;" ::: "memory");
    };

    float acc[4][4][4];
    #pragma unroll
    for (int mt = 0; mt < 4; ++mt)
        #pragma unroll
        for (int nt = 0; nt < 4; ++nt)
            #pragma unroll
            for (int u = 0; u < 4; ++u) acc[mt][nt][u] = 0.f;

    const int  a_r    = lane & 15;
    const uint32_t a_hi = (uint32_t)(lane >> 4) * 16;
    const int  b_r    = (lane & 7) + ((lane >> 4) << 3);
    const uint32_t b_hi = (uint32_t)((lane >> 3) & 1) * 16;

    load_chunk(0, 0);
    load_chunk(64, 1);

    int buf = 0;
    for (int c = 0; c < 16; ++c) {
        if (c <= 13) {
            load_chunk((c + 2) * 64, (c + 2) % 3);
            asm volatile("cp.async.wait_group 2;" ::: "memory");
        } else if (c == 14) {
            asm volatile("cp.async.wait_group 1;" ::: "memory");
        } else {
            asm volatile("cp.async.wait_group 0;" ::: "memory");
        }
        __syncthreads();

        const uint32_t base = sb + buf * GBUF_SZ;
        const uint32_t aT = base, bH = base + GTILE_SZ;

        #pragma unroll
        for (int ks = 0; ks < 4; ++ks) {
            const uint32_t kb = ks * 32;
            uint32_t a[4][4], bh[2][4];
            #pragma unroll
            for (int mt = 0; mt < 4; ++mt) {
                int row = wm*64 + mt*16 + a_r;
                uint32_t off = (uint32_t)row*128 + (((kb + a_hi) ^ ((row & 7) << 4)));
                ldmatrix_x4(a[mt], aT + off);
            }
            #pragma unroll
            for (int ntp = 0; ntp < 2; ++ntp) {
                int row = wn*32 + ntp*16 + b_r;
                uint32_t off = (uint32_t)row*128 + (((kb + b_hi) ^ ((row & 7) << 4)));
                ldmatrix_x4(bh[ntp], bH + off);
            }
            #pragma unroll
            for (int mt = 0; mt < 4; ++mt) {
                #pragma unroll
                for (int nt = 0; nt < 4; ++nt) {
                    uint32_t b0 = bh[nt >> 1][(nt & 1)*2 + 0];
                    uint32_t b1 = bh[nt >> 1][(nt & 1)*2 + 1];
                    mma16816h(acc[mt][nt], a[mt], b0, b1);
                }
            }
        }
        __syncthreads();
        buf = (buf + 1) % 3;
    }

    // ---- stage tile to smem, apply rope (q,k), store ----
    float* st = (float*)smem;
    #pragma unroll
    for (int mt = 0; mt < 4; ++mt) {
        int r = wm*64 + mt*16 + (lane >> 2);
        #pragma unroll
        for (int nt = 0; nt < 4; ++nt) {
            int col = wn*32 + nt*8 + 2*(lane & 3);
            *(float2*)&st[r*128 + col]       = make_float2(acc[mt][nt][0], acc[mt][nt][1]);
            *(float2*)&st[(r+8)*128 + col]   = make_float2(acc[mt][nt][2], acc[mt][nt][3]);
        }
    }
    __syncthreads();

    #pragma unroll 4
    for (int it = 0; it < 32; ++it) {
        int unit = tid + it*256;
        int row = unit >> 6;
        int col = (unit & 63) * 2;
        float2 val = *(float2*)&st[row*128 + col];
        float2 res = val;
        if (which < 2) {
            int gr = (int)rowA0 + row;
            int tt = gr & (Tv-1);
            int d = col & 63;
            float2 par;
            if (d < 32) {
                par = *(float2*)&st[row*128 + col + 32];
                par.x = -par.x; par.y = -par.y;
            } else {
                par = *(float2*)&st[row*128 + col - 32];
            }
            int dm = d & 31;
            float2 cc = *(const float2*)&g_rope_cos[tt*32 + dm];
            float2 ss = *(const float2*)&g_rope_sin[tt*32 + dm];
            res.x = val.x*cc.x + par.x*ss.x;
            res.y = val.y*cc.y + par.y*ss.y;
        }
        *(float2*)(C + ((size_t)rowA0 + row)*Cv + colBase + col) = res;
    }
}

// =================== fp16 1-term Wo GEMM (3-stage) =========================
__global__ __launch_bounds__(256, 2)
void gemm_wo(const __half* __restrict__ A,
             const __half* __restrict__ Bh,
             float* __restrict__ C)
{
    extern __shared__ char smem[];
    const uint32_t sb = smem_to_u32(smem);
    const int tid  = threadIdx.x;
    const int lane = tid & 31;
    const int wid  = tid >> 5;
    const int wm   = wid & 1;
    const int wn   = wid >> 1;
    const int K = Cv;

    const size_t rowA0 = (size_t)blockIdx.y * 128;
    const size_t rowB0 = (size_t)blockIdx.x * 128;
    const int colBase  = blockIdx.x * 128;

    const __half* tps[2] = { A + rowA0*K, Bh + rowB0*K };

    auto load_chunk = [&](int k0, int b) {
        const uint32_t dst = sb + b * GBUF_SZ;
        #pragma unroll
        for (int t = 0; t < 2; ++t) {
            const __half* gp = tps[t] + k0;
            const uint32_t td = dst + t * GTILE_SZ;
            #pragma unroll
            for (int i = 0; i < 4; ++i) {
                int v = tid + i * 256;
                int row = v >> 3, colv = v & 7;
                uint32_t boff = row * 128 + colv * 16;
                uint32_t sw = boff ^ ((boff >> 3) & 0x70);
                const void* src = gp + (size_t)row * K + colv * 8;
                asm volatile("cp.async.cg.shared.global [%0], [%1], 16;"
                             :: "r"(td + sw), "l"(src) : "memory");
            }
        }
        asm volatile("cp.async.commit_group;" ::: "memory");
    };

    float acc[4][4][4];
    #pragma unroll
    for (int mt = 0; mt < 4; ++mt)
        #pragma unroll
        for (int nt = 0; nt < 4; ++nt)
            #pragma unroll
            for (int u = 0; u < 4; ++u) acc[mt][nt][u] = 0.f;

    const int  a_r    = lane & 15;
    const uint32_t a_hi = (uint32_t)(lane >> 4) * 16;
    const int  b_r    = (lane & 7) + ((lane >> 4) << 3);
    const uint32_t b_hi = (uint32_t)((lane >> 3) & 1) * 16;

    load_chunk(0, 0);
    load_chunk(64, 1);

    int buf = 0;
    for (int c = 0; c < 16; ++c) {
        if (c <= 13) {
            load_chunk((c + 2) * 64, (c + 2) % 3);
            asm volatile("cp.async.wait_group 2;" ::: "memory");
        } else if (c == 14) {
            asm volatile("cp.async.wait_group 1;" ::: "memory");
        } else {
            asm volatile("cp.async.wait_group 0;" ::: "memory");
        }
        __syncthreads();

        const uint32_t base = sb + buf * GBUF_SZ;
        const uint32_t aT = base, bH = base + GTILE_SZ;

        #pragma unroll
        for (int ks = 0; ks < 4; ++ks) {
            const uint32_t kb = ks * 32;
            uint32_t a[4][4], bh[2][4];
            #pragma unroll
            for (int mt = 0; mt < 4; ++mt) {
                int row = wm*64 + mt*16 + a_r;
                uint32_t off = (uint32_t)row*128 + (((kb + a_hi) ^ ((row & 7) << 4)));
                ldmatrix_x4(a[mt], aT + off);
            }
            #pragma unroll
            for (int ntp = 0; ntp < 2; ++ntp) {
                int row = wn*32 + ntp*16 + b_r;
                uint32_t off = (uint32_t)row*128 + (((kb + b_hi) ^ ((row & 7) << 4)));
                ldmatrix_x4(bh[ntp], bH + off);
            }
            #pragma unroll
            for (int mt = 0; mt < 4; ++mt) {
                #pragma unroll
                for (int nt = 0; nt < 4; ++nt) {
                    uint32_t b0 = bh[nt >> 1][(nt & 1)*2 + 0];
                    uint32_t b1 = bh[nt >> 1][(nt & 1)*2 + 1];
                    mma16816h(acc[mt][nt], a[mt], b0, b1);
                }
            }
        }
        __syncthreads();
        buf = (buf + 1) % 3;
    }

    #pragma unroll
    for (int mt = 0; mt < 4; ++mt) {
        int r0 = (int)rowA0 + wm*64 + mt*16 + (lane >> 2);
        #pragma unroll
        for (int nt = 0; nt < 4; ++nt) {
            int col = colBase + wn*32 + nt*8 + 2*(lane & 3);
            *(float2*)(C + (size_t)r0 * Cv + col)       = make_float2(acc[mt][nt][0], acc[mt][nt][1]);
            *(float2*)(C + (size_t)(r0 + 8) * Cv + col) = make_float2(acc[mt][nt][2], acc[mt][nt][3]);
        }
    }
}

// ---------------- Pass 1: per-chunk local state (4x4 register tiles) -------
__global__ __launch_bounds__(256)
void ret_pass1()
{
    __shared__ float sK[64*64];
    __shared__ float sV[64*64];
    const int blk = blockIdx.x;
    const int c   = blk & 31;
    const int h   = (blk >> 5) & 15;
    const int b   = blk >> 9;
    const int tid = threadIdx.x;
    const float gamma = 1.0f - exp2f(-5.0f - (float)h);
    const float lg = log2f(gamma);
    const size_t rowbase = ((size_t)(b*Tv + c*64))*Cv + (size_t)h*64;
    const int fq = tid & 15;
    for (int r = tid >> 4; r < 64; r += 16) {
        float w = exp2f((float)(64 - r) * lg);
        float4 kv = *(const float4*)(g_k + rowbase + (size_t)r*Cv + fq*4);
        kv.x *= w; kv.y *= w; kv.z *= w; kv.w *= w;
        *(float4*)&sK[r*64 + fq*4] = kv;
        *(float4*)&sV[r*64 + fq*4] = *(const float4*)(g_v + rowbase + (size_t)r*Cv + fq*4);
    }
    __syncthreads();

    const int i0 = (tid >> 4) * 4;
    const int j0 = (tid & 15) * 4;
    float acc[4][4];
    #pragma unroll
    for (int ii = 0; ii < 4; ++ii)
        #pragma unroll
        for (int jj = 0; jj < 4; ++jj) acc[ii][jj] = 0.f;

    #pragma unroll 8
    for (int j = 0; j < 64; ++j) {
        float4 kv = *(const float4*)&sK[j*64 + i0];
        float4 vv = *(const float4*)&sV[j*64 + j0];
        const float kk[4] = {kv.x, kv.y, kv.z, kv.w};
        const float vx[4] = {vv.x, vv.y, vv.z, vv.w};
        #pragma unroll
        for (int ii = 0; ii < 4; ++ii)
            #pragma unroll
            for (int jj = 0; jj < 4; ++jj)
                acc[ii][jj] = fmaf(kk[ii], vx[jj], acc[ii][jj]);
    }
    #pragma unroll
    for (int ii = 0; ii < 4; ++ii) {
        float* Gp = g_G + ((size_t)blk*64 + i0 + ii)*64 + j0;
        *(float4*)Gp = make_float4(acc[ii][0], acc[ii][1], acc[ii][2], acc[ii][3]);
    }
}

// ---------------- Pass 2: parallel elementwise scan ------------------------
__global__ void ret_pass2()
{
    int el = blockIdx.x*blockDim.x + threadIdx.x;  // 0 .. 131071
    int bh  = el >> 12;
    int idx = el & 4095;
    int h   = bh & 15;
    const float gamma = 1.0f - exp2f(-5.0f - (float)h);
    const float gL = exp2f(64.0f * log2f(gamma));
    float s = 0.f;
    size_t e = (size_t)bh*NCHUNK*4096 + idx;
    #pragma unroll 8
    for (int c = 0; c < NCHUNK; ++c, e += 4096) {
        g_S[e] = s;
        s = fmaf(gL, s, g_G[e]);
    }
}

// ---------------- Pass 3: intra + cross + GroupNorm (4x4 register tiles) ---
__global__ __launch_bounds__(256)
void ret_pass3(const float* __restrict__ gnw, const float* __restrict__ gnb)
{
    __shared__ float sQt[64*64];
    __shared__ float sT[64*64];
    __shared__ float sA[64*64];
    const int blk = blockIdx.x;
    const int c   = blk & 31;
    const int h   = (blk >> 5) & 15;
    const int b   = blk >> 9;
    const int tid = threadIdx.x;
    const float gamma = 1.0f - exp2f(-5.0f - (float)h);
    const float lg = log2f(gamma);
    const size_t rowbase = ((size_t)(b*Tv + c*64))*Cv + (size_t)h*64;
    const int fq = tid & 15;

    for (int r = tid >> 4; r < 64; r += 16) {
        float4 qv = *(const float4*)(g_q + rowbase + (size_t)r*Cv + fq*4);
        float4 kv = *(const float4*)(g_k + rowbase + (size_t)r*Cv + fq*4);
        int d0 = fq*4;
        sQt[(d0+0)*64 + r] = 0.125f*qv.x;
        sQt[(d0+1)*64 + r] = 0.125f*qv.y;
        sQt[(d0+2)*64 + r] = 0.125f*qv.z;
        sQt[(d0+3)*64 + r] = 0.125f*qv.w;
        sT[(d0+0)*64 + r] = kv.x;
        sT[(d0+1)*64 + r] = kv.y;
        sT[(d0+2)*64 + r] = kv.z;
        sT[(d0+3)*64 + r] = kv.w;
    }
    __syncthreads();

    const int i0 = (tid >> 4) * 4;
    const int j0 = (tid & 15) * 4;

    {
        float a[4][4];
        #pragma unroll
        for (int ii = 0; ii < 4; ++ii)
            #pragma unroll
            for (int jj = 0; jj < 4; ++jj) a[ii][jj] = 0.f;
        #pragma unroll 8
        for (int d = 0; d < 64; ++d) {
            float4 qv = *(const float4*)&sQt[d*64 + i0];
            float4 kv = *(const float4*)&sT[d*64 + j0];
            const float qq[4] = {qv.x, qv.y, qv.z, qv.w};
            const float kk[4] = {kv.x, kv.y, kv.z, kv.w};
            #pragma unroll
            for (int ii = 0; ii < 4; ++ii)
                #pragma unroll
                for (int jj = 0; jj < 4; ++jj)
                    a[ii][jj] = fmaf(qq[ii], kk[jj], a[ii][jj]);
        }
        #pragma unroll
        for (int jj = 0; jj < 4; ++jj) {
            int j = j0 + jj;
            float4 row;
            float* rp = (float*)&row;
            #pragma unroll
            for (int ii = 0; ii < 4; ++ii) {
                int i = i0 + ii;
                float dec = (j <= i) ? exp2f((float)(i - j) * lg) : 0.f;
                rp[ii] = a[ii][jj] * dec;
            }
            *(float4*)&sA[j*64 + i0] = row;
        }
    }
    __syncthreads();

    const float* Sp = g_S + (size_t)blk*4096;
    for (int e = tid*4; e < 4096; e += 1024)
        *(float4*)&sT[e] = *(const float4*)&Sp[e];
    __syncthreads();

    float o[4][4];
    #pragma unroll
    for (int ii = 0; ii < 4; ++ii)
        #pragma unroll
        for (int jj = 0; jj < 4; ++jj) o[ii][jj] = 0.f;
    #pragma unroll 8
    for (int d = 0; d < 64; ++d) {
        float4 qv = *(const float4*)&sQt[d*64 + i0];
        float4 sv = *(const float4*)&sT[d*64 + j0];
        const float qq[4] = {qv.x, qv.y, qv.z, qv.w};
        const float ss[4] = {sv.x, sv.y, sv.z, sv.w};
        #pragma unroll
        for (int ii = 0; ii < 4; ++ii)
            #pragma unroll
            for (int jj = 0; jj < 4; ++jj)
                o[ii][jj] = fmaf(qq[ii], ss[jj], o[ii][jj]);
    }
    #pragma unroll
    for (int ii = 0; ii < 4; ++ii) {
        float cd = exp2f((float)(i0 + ii) * lg);
        #pragma unroll
        for (int jj = 0; jj < 4; ++jj) o[ii][jj] *= cd;
    }
    __syncthreads();

    for (int r = tid >> 4; r < 64; r += 16)
        *(float4*)&sQt[r*64 + fq*4] = *(const float4*)(g_v + rowbase + (size_t)r*Cv + fq*4);
    __syncthreads();

    #pragma unroll 8
    for (int s = 0; s < 64; ++s) {
        float4 av = *(const float4*)&sA[s*64 + i0];
        float4 vv = *(const float4*)&sQt[s*64 + j0];
        const float aa[4] = {av.x, av.y, av.z, av.w};
        const float vx[4] = {vv.x, vv.y, vv.z, vv.w};
        #pragma unroll
        for (int ii = 0; ii < 4; ++ii)
            #pragma unroll
            for (int jj = 0; jj < 4; ++jj)
                o[ii][jj] = fmaf(aa[ii], vx[jj], o[ii][jj]);
    }

    float rsum[4], rsq[4];
    #pragma unroll
    for (int ii = 0; ii < 4; ++ii) {
        float s = o[ii][0] + o[ii][1] + o[ii][2] + o[ii][3];
        s += __shfl_xor_sync(0xffffffffu, s, 1);
        s += __shfl_xor_sync(0xffffffffu, s, 2);
        s += __shfl_xor_sync(0xffffffffu, s, 4);
        s += __shfl_xor_sync(0xffffffffu, s, 8);
        rsum[ii] = s * (1.0f/64.0f);
    }
    #pragma unroll
    for (int ii = 0; ii < 4; ++ii) {
        float q0 = o[ii][0]-rsum[ii], q1 = o[ii][1]-rsum[ii];
        float q2 = o[ii][2]-rsum[ii], q3 = o[ii][3]-rsum[ii];
        float s = q0*q0 + q1*q1 + q2*q2 + q3*q3;
        s += __shfl_xor_sync(0xffffffffu, s, 1);
        s += __shfl_xor_sync(0xffffffffu, s, 2);
        s += __shfl_xor_sync(0xffffffffu, s, 4);
        s += __shfl_xor_sync(0xffffffffu, s, 8);
        rsq[ii] = rsqrtf(s * (1.0f/64.0f) + 1e-5f);
    }

    const float* wg = gnw + h*64 + j0;
    const float* bg = gnb + h*64 + j0;
    float w0 = wg[0], w1 = wg[1], w2 = wg[2], w3 = wg[3];
    float b0 = bg[0], b1 = bg[1], b2 = bg[2], b3 = bg[3];
    #pragma unroll
    for (int ii = 0; ii < 4; ++ii) {
        int i = i0 + ii;
        __half* op = g_att16 + ((size_t)(b*Tv + c*64 + i))*Cv + (size_t)h*64 + j0;
        float r0 = fmaf((o[ii][0]-rsum[ii])*rsq[ii], w0, b0);
        float r1 = fmaf((o[ii][1]-rsum[ii])*rsq[ii], w1, b1);
        float r2 = fmaf((o[ii][2]-rsum[ii])*rsq[ii], w2, b2);
        float r3 = fmaf((o[ii][3]-rsum[ii])*rsq[ii], w3, b3);
        *(__half2*)(op)     = __floats2half2_rn(r0, r1);
        *(__half2*)(op + 2) = __floats2half2_rn(r2, r3);
    }
}

// ---------------------------------------------------------------------------
extern "C" void kernel_launch(void* const* d_in, const int* in_sizes, int n_in,
                              void* d_out, int out_size)
{
    const float* x   = (const float*)d_in[0];
    const float* Wq  = (const float*)d_in[1];
    const float* Wk  = (const float*)d_in[2];
    const float* Wv  = (const float*)d_in[3];
    const float* Wo  = (const float*)d_in[4];
    const float* gnw = (const float*)d_in[5];
    const float* gnb = (const float*)d_in[6];
    float* out = (float*)d_out;

    float *q, *k, *v;
    cudaGetSymbolAddress((void**)&q, g_q);
    cudaGetSymbolAddress((void**)&k, g_k);
    cudaGetSymbolAddress((void**)&v, g_v);
    __half *xh, *att16, *whi;
    cudaGetSymbolAddress((void**)&xh,    g_xh);
    cudaGetSymbolAddress((void**)&att16, g_att16);
    cudaGetSymbolAddress((void**)&whi,   g_whi);

    static bool attr_set = false;
    if (!attr_set) {
        cudaFuncSetAttribute(gemm_qkv,
                             cudaFuncAttributeMaxDynamicSharedMemorySize, GSMEM_TOTAL);
        cudaFuncSetAttribute(gemm_wo,
                             cudaFuncAttributeMaxDynamicSharedMemorySize, GSMEM_TOTAL);
        attr_set = true;
    }

    const int nx4 = (Mv*Cv)/4;
    split_x<<<(nx4+255)/256, 256>>>(x, xh, nx4);
    conv_4w<<<(4*CC/4)/256, 256>>>(Wq, Wk, Wv, Wo, whi);
    rope_table<<<(Tv*32)/256, 256>>>();

    gemm_qkv<<<dim3(24, 32), 256, GSMEM_TOTAL>>>(xh, whi, q, k, v);

    ret_pass1<<<Bv*Hv*NCHUNK, 256>>>();
    ret_pass2<<<(Bv*Hv*4096)/256, 256>>>();
    ret_pass3<<<Bv*Hv*NCHUNK, 256>>>(gnw, gnb);

    gemm_wo<<<dim3(8, 32), 256, GSMEM_TOTAL>>>(att16, whi + (size_t)3*CC, out);
}

// round 14
// speedup vs baseline: 6.8192x; 1.2265x over previous
#include <cuda_runtime.h>
#include <cuda_fp16.h>
#include <math.h>
#include <stdint.h>

#define Bv 2
#define Tv 2048
#define Cv 1024
#define Hv 16
#define DHv 64
#define Mv (Bv*Tv)       // 4096 rows
#define NCHUNK 32        // T / 64
#define CC (Cv*Cv)

// ---------------- scratch (static device memory; no allocs) ----------------
__device__ float g_q[Mv*Cv];
__device__ float g_k[Mv*Cv];
__device__ float g_v[Mv*Cv];
__device__ float g_G[Bv*Hv*NCHUNK*DHv*DHv];              // G^T: [dv][dk] per chunk
__device__ __align__(256) __half g_S16[Bv*Hv*NCHUNK*DHv*DHv]; // S^T fp16
__device__ float g_rope_cos[Tv*32];
__device__ float g_rope_sin[Tv*32];

__device__ __align__(256) __half g_att16[Mv*Cv];     // fp16 retention output
__device__ __align__(256) __half g_xh[Mv*Cv];        // fp16 x
__device__ __align__(256) __half g_whi[4*CC];        // fp16 Wq,Wk,Wv,Wo (concat rows)

// ======================= helpers ===========================================
__device__ __forceinline__ uint32_t smem_to_u32(const void* p) {
    uint32_t a;
    asm("{ .reg .u64 t; cvta.to.shared.u64 t, %1; cvt.u32.u64 %0, t; }" : "=r"(a) : "l"(p));
    return a;
}
__device__ __forceinline__ void ldmatrix_x4(uint32_t* r, uint32_t addr) {
    asm volatile("ldmatrix.sync.aligned.m8n8.x4.shared.b16 {%0,%1,%2,%3}, [%4];"
                 : "=r"(r[0]), "=r"(r[1]), "=r"(r[2]), "=r"(r[3]) : "r"(addr));
}
__device__ __forceinline__ void mma16816h(float* d, const uint32_t* a, uint32_t b0, uint32_t b1) {
    asm volatile(
        "mma.sync.aligned.m16n8k16.row.col.f32.f16.f16.f32 "
        "{%0,%1,%2,%3}, {%4,%5,%6,%7}, {%8,%9}, {%0,%1,%2,%3};"
        : "+f"(d[0]), "+f"(d[1]), "+f"(d[2]), "+f"(d[3])
        : "r"(a[0]), "r"(a[1]), "r"(a[2]), "r"(a[3]), "r"(b0), "r"(b1));
}

// =================== small prep kernels ====================================
__global__ void split_x(const float* __restrict__ s, __half* __restrict__ hi, int n4)
{
    int i = blockIdx.x*blockDim.x + threadIdx.x;
    if (i >= n4) return;
    float4 f = ((const float4*)s)[i];
    __half2* hp = (__half2*)(hi + (size_t)i*4);
    hp[0] = __floats2half2_rn(f.x, f.y);
    hp[1] = __floats2half2_rn(f.z, f.w);
}

__global__ void conv_4w(const float* __restrict__ W0, const float* __restrict__ W1,
                        const float* __restrict__ W2, const float* __restrict__ W3,
                        __half* __restrict__ hi)
{
    int i = blockIdx.x*blockDim.x + threadIdx.x;   // 0 .. 4*CC/4
    int w = i >> 18;
    const float* s = (w==0) ? W0 : (w==1) ? W1 : (w==2) ? W2 : W3;
    int j = i & 262143;
    float4 f = ((const float4*)s)[j];
    __half2* hp = (__half2*)(hi + (size_t)i*4);
    hp[0] = __floats2half2_rn(f.x, f.y);
    hp[1] = __floats2half2_rn(f.z, f.w);
}

__global__ void rope_table()
{
    int i = blockIdx.x*blockDim.x + threadIdx.x;   // 0..65535
    int dm = i & 31, t = i >> 5;
    float inv = exp2f(-(float)dm * (13.287712379549449f / 32.0f));
    float ang = (float)t * inv;
    float s, c;
    sincosf(ang, &s, &c);
    g_rope_cos[i] = c;
    g_rope_sin[i] = s;
}

// =================== fp16 1-term QKV GEMM (rope fused) =====================
#define GTILE_SZ 16384          // 128 rows x 128 bytes
#define GBUF_SZ  (2*GTILE_SZ)   // A, B
#define GSMEM_TOTAL (3*GBUF_SZ) // 98304 (also covers 64KB rope staging)

__global__ __launch_bounds__(256, 2)
void gemm_qkv(const __half* __restrict__ A,
              const __half* __restrict__ Bh,
              float* __restrict__ o0, float* __restrict__ o1, float* __restrict__ o2)
{
    extern __shared__ char smem[];
    const uint32_t sb = smem_to_u32(smem);
    const int tid  = threadIdx.x;
    const int lane = tid & 31;
    const int wid  = tid >> 5;
    const int wm   = wid & 1;
    const int wn   = wid >> 1;
    const int K = Cv;

    const size_t rowA0 = (size_t)blockIdx.y * 128;
    const size_t rowB0 = (size_t)blockIdx.x * 128;
    const int which   = blockIdx.x >> 3;            // 0=q 1=k 2=v
    float* C = (which == 0) ? o0 : (which == 1) ? o1 : o2;
    const int colBase = (blockIdx.x & 7) * 128;

    const __half* tps[2] = { A + rowA0*K, Bh + rowB0*K };

    auto load_chunk = [&](int k0, int b) {
        const uint32_t dst = sb + b * GBUF_SZ;
        #pragma unroll
        for (int t = 0; t < 2; ++t) {
            const __half* gp = tps[t] + k0;
            const uint32_t td = dst + t * GTILE_SZ;
            #pragma unroll
            for (int i = 0; i < 4; ++i) {
                int v = tid + i * 256;
                int row = v >> 3, colv = v & 7;
                uint32_t boff = row * 128 + colv * 16;
                uint32_t sw = boff ^ ((boff >> 3) & 0x70);
                const void* src = gp + (size_t)row * K + colv * 8;
                asm volatile("cp.async.cg.shared.global [%0], [%1], 16;"
                             :: "r"(td + sw), "l"(src) : "memory");
            }
        }
        asm volatile("cp.async.commit_group;" ::: "memory");
    };

    float acc[4][4][4];
    #pragma unroll
    for (int mt = 0; mt < 4; ++mt)
        #pragma unroll
        for (int nt = 0; nt < 4; ++nt)
            #pragma unroll
            for (int u = 0; u < 4; ++u) acc[mt][nt][u] = 0.f;

    const int  a_r    = lane & 15;
    const uint32_t a_hi = (uint32_t)(lane >> 4) * 16;
    const int  b_r    = (lane & 7) + ((lane >> 4) << 3);
    const uint32_t b_hi = (uint32_t)((lane >> 3) & 1) * 16;

    load_chunk(0, 0);
    load_chunk(64, 1);

    int buf = 0;
    for (int c = 0; c < 16; ++c) {
        if (c <= 13) {
            load_chunk((c + 2) * 64, (c + 2) % 3);
            asm volatile("cp.async.wait_group 2;" ::: "memory");
        } else if (c == 14) {
            asm volatile("cp.async.wait_group 1;" ::: "memory");
        } else {
            asm volatile("cp.async.wait_group 0;" ::: "memory");
        }
        __syncthreads();

        const uint32_t base = sb + buf * GBUF_SZ;
        const uint32_t aT = base, bH = base + GTILE_SZ;

        #pragma unroll
        for (int ks = 0; ks < 4; ++ks) {
            const uint32_t kb = ks * 32;
            uint32_t a[4][4], bh[2][4];
            #pragma unroll
            for (int mt = 0; mt < 4; ++mt) {
                int row = wm*64 + mt*16 + a_r;
                uint32_t off = (uint32_t)row*128 + (((kb + a_hi) ^ ((row & 7) << 4)));
                ldmatrix_x4(a[mt], aT + off);
            }
            #pragma unroll
            for (int ntp = 0; ntp < 2; ++ntp) {
                int row = wn*32 + ntp*16 + b_r;
                uint32_t off = (uint32_t)row*128 + (((kb + b_hi) ^ ((row & 7) << 4)));
                ldmatrix_x4(bh[ntp], bH + off);
            }
            #pragma unroll
            for (int mt = 0; mt < 4; ++mt) {
                #pragma unroll
                for (int nt = 0; nt < 4; ++nt) {
                    uint32_t b0 = bh[nt >> 1][(nt & 1)*2 + 0];
                    uint32_t b1 = bh[nt >> 1][(nt & 1)*2 + 1];
                    mma16816h(acc[mt][nt], a[mt], b0, b1);
                }
            }
        }
        __syncthreads();
        buf = (buf + 1) % 3;
    }

    // ---- stage tile to smem, apply rope (q,k), store ----
    float* st = (float*)smem;
    #pragma unroll
    for (int mt = 0; mt < 4; ++mt) {
        int r = wm*64 + mt*16 + (lane >> 2);
        #pragma unroll
        for (int nt = 0; nt < 4; ++nt) {
            int col = wn*32 + nt*8 + 2*(lane & 3);
            *(float2*)&st[r*128 + col]       = make_float2(acc[mt][nt][0], acc[mt][nt][1]);
            *(float2*)&st[(r+8)*128 + col]   = make_float2(acc[mt][nt][2], acc[mt][nt][3]);
        }
    }
    __syncthreads();

    #pragma unroll 4
    for (int it = 0; it < 32; ++it) {
        int unit = tid + it*256;
        int row = unit >> 6;
        int col = (unit & 63) * 2;
        float2 val = *(float2*)&st[row*128 + col];
        float2 res = val;
        if (which < 2) {
            int gr = (int)rowA0 + row;
            int tt = gr & (Tv-1);
            int d = col & 63;
            float2 par;
            if (d < 32) {
                par = *(float2*)&st[row*128 + col + 32];
                par.x = -par.x; par.y = -par.y;
            } else {
                par = *(float2*)&st[row*128 + col - 32];
            }
            int dm = d & 31;
            float2 cc = *(const float2*)&g_rope_cos[tt*32 + dm];
            float2 ss = *(const float2*)&g_rope_sin[tt*32 + dm];
            res.x = val.x*cc.x + par.x*ss.x;
            res.y = val.y*cc.y + par.y*ss.y;
        }
        *(float2*)(C + ((size_t)rowA0 + row)*Cv + colBase + col) = res;
    }
}

// =================== fp16 1-term Wo GEMM (3-stage) =========================
__global__ __launch_bounds__(256, 2)
void gemm_wo(const __half* __restrict__ A,
             const __half* __restrict__ Bh,
             float* __restrict__ C)
{
    extern __shared__ char smem[];
    const uint32_t sb = smem_to_u32(smem);
    const int tid  = threadIdx.x;
    const int lane = tid & 31;
    const int wid  = tid >> 5;
    const int wm   = wid & 1;
    const int wn   = wid >> 1;
    const int K = Cv;

    const size_t rowA0 = (size_t)blockIdx.y * 128;
    const size_t rowB0 = (size_t)blockIdx.x * 128;
    const int colBase  = blockIdx.x * 128;

    const __half* tps[2] = { A + rowA0*K, Bh + rowB0*K };

    auto load_chunk = [&](int k0, int b) {
        const uint32_t dst = sb + b * GBUF_SZ;
        #pragma unroll
        for (int t = 0; t < 2; ++t) {
            const __half* gp = tps[t] + k0;
            const uint32_t td = dst + t * GTILE_SZ;
            #pragma unroll
            for (int i = 0; i < 4; ++i) {
                int v = tid + i * 256;
                int row = v >> 3, colv = v & 7;
                uint32_t boff = row * 128 + colv * 16;
                uint32_t sw = boff ^ ((boff >> 3) & 0x70);
                const void* src = gp + (size_t)row * K + colv * 8;
                asm volatile("cp.async.cg.shared.global [%0], [%1], 16;"
                             :: "r"(td + sw), "l"(src) : "memory");
            }
        }
        asm volatile("cp.async.commit_group;" ::: "memory");
    };

    float acc[4][4][4];
    #pragma unroll
    for (int mt = 0; mt < 4; ++mt)
        #pragma unroll
        for (int nt = 0; nt < 4; ++nt)
            #pragma unroll
            for (int u = 0; u < 4; ++u) acc[mt][nt][u] = 0.f;

    const int  a_r    = lane & 15;
    const uint32_t a_hi = (uint32_t)(lane >> 4) * 16;
    const int  b_r    = (lane & 7) + ((lane >> 4) << 3);
    const uint32_t b_hi = (uint32_t)((lane >> 3) & 1) * 16;

    load_chunk(0, 0);
    load_chunk(64, 1);

    int buf = 0;
    for (int c = 0; c < 16; ++c) {
        if (c <= 13) {
            load_chunk((c + 2) * 64, (c + 2) % 3);
            asm volatile("cp.async.wait_group 2;" ::: "memory");
        } else if (c == 14) {
            asm volatile("cp.async.wait_group 1;" ::: "memory");
        } else {
            asm volatile("cp.async.wait_group 0;" ::: "memory");
        }
        __syncthreads();

        const uint32_t base = sb + buf * GBUF_SZ;
        const uint32_t aT = base, bH = base + GTILE_SZ;

        #pragma unroll
        for (int ks = 0; ks < 4; ++ks) {
            const uint32_t kb = ks * 32;
            uint32_t a[4][4], bh[2][4];
            #pragma unroll
            for (int mt = 0; mt < 4; ++mt) {
                int row = wm*64 + mt*16 + a_r;
                uint32_t off = (uint32_t)row*128 + (((kb + a_hi) ^ ((row & 7) << 4)));
                ldmatrix_x4(a[mt], aT + off);
            }
            #pragma unroll
            for (int ntp = 0; ntp < 2; ++ntp) {
                int row = wn*32 + ntp*16 + b_r;
                uint32_t off = (uint32_t)row*128 + (((kb + b_hi) ^ ((row & 7) << 4)));
                ldmatrix_x4(bh[ntp], bH + off);
            }
            #pragma unroll
            for (int mt = 0; mt < 4; ++mt) {
                #pragma unroll
                for (int nt = 0; nt < 4; ++nt) {
                    uint32_t b0 = bh[nt >> 1][(nt & 1)*2 + 0];
                    uint32_t b1 = bh[nt >> 1][(nt & 1)*2 + 1];
                    mma16816h(acc[mt][nt], a[mt], b0, b1);
                }
            }
        }
        __syncthreads();
        buf = (buf + 1) % 3;
    }

    #pragma unroll
    for (int mt = 0; mt < 4; ++mt) {
        int r0 = (int)rowA0 + wm*64 + mt*16 + (lane >> 2);
        #pragma unroll
        for (int nt = 0; nt < 4; ++nt) {
            int col = colBase + wn*32 + nt*8 + 2*(lane & 3);
            *(float2*)(C + (size_t)r0 * Cv + col)       = make_float2(acc[mt][nt][0], acc[mt][nt][1]);
            *(float2*)(C + (size_t)(r0 + 8) * Cv + col) = make_float2(acc[mt][nt][2], acc[mt][nt][3]);
        }
    }
}

// ---------------- Pass 1: per-chunk local state via fp16 mma ---------------
// G^T[dv][dk] = (V^T @ Kdecay)^T; stores transposed via smem bounce.
#define SPAD 72   // fp16 row stride (144 B) - conflict-free ldmatrix

__global__ __launch_bounds__(256)
void ret_pass1()
{
    __shared__ __align__(16) unsigned char sm[2*SPAD*64*2];  // 18432 B
    __half* sKdT = (__half*)sm;               // [dk][j]
    __half* sVt  = (__half*)(sm + SPAD*64*2); // [dv][j]
    float*  sG   = (float*)sm;                // overlay: [dv][dk] fp32 (16KB)

    const int blk = blockIdx.x;
    const int c   = blk & 31;
    const int h   = (blk >> 5) & 15;
    const int b   = blk >> 9;
    const int tid = threadIdx.x;
    const int lane = tid & 31;
    const int wid  = tid >> 5;
    const float gamma = 1.0f - exp2f(-5.0f - (float)h);
    const float lg = log2f(gamma);
    const size_t rowbase = ((size_t)(b*Tv + c*64))*Cv + (size_t)h*64;
    const int fq = tid & 15;

    // stage transposed fp16
    for (int r = tid >> 4; r < 64; r += 16) {
        float w = exp2f((float)(64 - r) * lg);
        float4 kv = *(const float4*)(g_k + rowbase + (size_t)r*Cv + fq*4);
        float4 vv = *(const float4*)(g_v + rowbase + (size_t)r*Cv + fq*4);
        int d0 = fq*4;
        sKdT[(d0+0)*SPAD + r] = __float2half_rn(kv.x * w);
        sKdT[(d0+1)*SPAD + r] = __float2half_rn(kv.y * w);
        sKdT[(d0+2)*SPAD + r] = __float2half_rn(kv.z * w);
        sKdT[(d0+3)*SPAD + r] = __float2half_rn(kv.w * w);
        sVt[(d0+0)*SPAD + r] = __float2half_rn(vv.x);
        sVt[(d0+1)*SPAD + r] = __float2half_rn(vv.y);
        sVt[(d0+2)*SPAD + r] = __float2half_rn(vv.z);
        sVt[(d0+3)*SPAD + r] = __float2half_rn(vv.w);
    }
    __syncthreads();

    const int wm = wid >> 1, wn = wid & 1;
    const int  aRow = wm*16 + (lane & 15);
    const uint32_t aOff = (uint32_t)(lane >> 4) * 16;
    const int  bRow = (lane & 7) + ((lane >> 4) << 3);
    const uint32_t bOff = (uint32_t)((lane >> 3) & 1) * 16;

    const uint32_t uA  = smem_to_u32(sKdT) + (uint32_t)aRow*(SPAD*2) + aOff;
    const uint32_t uB0 = smem_to_u32(sVt) + (uint32_t)(wn*32 + bRow)*(SPAD*2) + bOff;
    const uint32_t uB1 = uB0 + 16*(SPAD*2);

    float acc[4][4];
    #pragma unroll
    for (int nt = 0; nt < 4; ++nt)
        #pragma unroll
        for (int u = 0; u < 4; ++u) acc[nt][u] = 0.f;

    #pragma unroll
    for (int ks = 0; ks < 4; ++ks) {
        uint32_t a[4], b0[4], b1[4];
        ldmatrix_x4(a,  uA  + ks*32);
        ldmatrix_x4(b0, uB0 + ks*32);
        ldmatrix_x4(b1, uB1 + ks*32);
        mma16816h(acc[0], a, b0[0], b0[1]);
        mma16816h(acc[1], a, b0[2], b0[3]);
        mma16816h(acc[2], a, b1[0], b1[1]);
        mma16816h(acc[3], a, b1[2], b1[3]);
    }
    __syncthreads();

    // scatter to sG as [dv][dk]
    const int r0 = wm*16 + (lane >> 2), r1 = r0 + 8;   // dk
    #pragma unroll
    for (int nt = 0; nt < 4; ++nt) {
        int col = wn*32 + nt*8 + 2*(lane & 3);          // dv
        sG[col*64 + r0]     = acc[nt][0];
        sG[(col+1)*64 + r0] = acc[nt][1];
        sG[col*64 + r1]     = acc[nt][2];
        sG[(col+1)*64 + r1] = acc[nt][3];
    }
    __syncthreads();

    float* Gp = g_G + (size_t)blk*4096;
    #pragma unroll
    for (int u = 0; u < 4; ++u)
        *(float4*)(Gp + tid*16 + u*4) = *(const float4*)&sG[tid*16 + u*4];
}

// ---------------- Pass 2: parallel elementwise scan (fp16 S out) -----------
__global__ void ret_pass2()
{
    int el = blockIdx.x*blockDim.x + threadIdx.x;  // 0 .. 131071
    int bh  = el >> 12;
    int idx = el & 4095;
    int h   = bh & 15;
    const float gamma = 1.0f - exp2f(-5.0f - (float)h);
    const float gL = exp2f(64.0f * log2f(gamma));
    float s = 0.f;
    size_t e = (size_t)bh*NCHUNK*4096 + idx;
    #pragma unroll 8
    for (int c = 0; c < NCHUNK; ++c, e += 4096) {
        g_S16[e] = __float2half_rn(s);
        s = fmaf(gL, s, g_G[e]);
    }
}

// ---------------- Pass 3: retention core via fp16 mma + fused GroupNorm ----
__global__ __launch_bounds__(256)
void ret_pass3(const float* __restrict__ gnw, const float* __restrict__ gnb)
{
    __shared__ __align__(16) __half sQ[64*SPAD];   // [i][d] * 0.125
    __shared__ __align__(16) __half sK[64*SPAD];   // [j][d]
    __shared__ __align__(16) __half sVt[64*SPAD];  // [dv][j]
    __shared__ __align__(16) __half sS[64*SPAD];   // [dv][dk]  (S^T)
    __shared__ __align__(16) __half sA[64*SPAD];   // [i][j]
    __shared__ float sbuf[64][4];

    const int blk = blockIdx.x;
    const int c   = blk & 31;
    const int h   = (blk >> 5) & 15;
    const int b   = blk >> 9;
    const int tid = threadIdx.x;
    const int lane = tid & 31;
    const int wid  = tid >> 5;
    const float gamma = 1.0f - exp2f(-5.0f - (float)h);
    const float lg = log2f(gamma);
    const size_t rowbase = ((size_t)(b*Tv + c*64))*Cv + (size_t)h*64;

    // ---- staging ----
    {
        int r4 = tid >> 2, q4 = tid & 3;
        const float* qp = g_q + rowbase + (size_t)r4*Cv + q4*16;
        const float* kp = g_k + rowbase + (size_t)r4*Cv + q4*16;
        #pragma unroll
        for (int u = 0; u < 4; ++u) {
            float4 f = ((const float4*)qp)[u];
            *(__half2*)&sQ[r4*SPAD + q4*16 + u*4]     = __floats2half2_rn(0.125f*f.x, 0.125f*f.y);
            *(__half2*)&sQ[r4*SPAD + q4*16 + u*4 + 2] = __floats2half2_rn(0.125f*f.z, 0.125f*f.w);
            float4 g = ((const float4*)kp)[u];
            *(__half2*)&sK[r4*SPAD + q4*16 + u*4]     = __floats2half2_rn(g.x, g.y);
            *(__half2*)&sK[r4*SPAD + q4*16 + u*4 + 2] = __floats2half2_rn(g.z, g.w);
        }
        // S^T rows (fp16 direct copy)
        const uint4* sp = (const uint4*)(g_S16 + (size_t)blk*4096);
        *(uint4*)&sS[r4*SPAD + q4*16]     = sp[r4*8 + q4*2];
        *(uint4*)&sS[r4*SPAD + q4*16 + 8] = sp[r4*8 + q4*2 + 1];
    }
    {   // V transposed
        const int fq = tid & 15;
        for (int r = tid >> 4; r < 64; r += 16) {
            float4 vv = *(const float4*)(g_v + rowbase + (size_t)r*Cv + fq*4);
            int d0 = fq*4;
            sVt[(d0+0)*SPAD + r] = __float2half_rn(vv.x);
            sVt[(d0+1)*SPAD + r] = __float2half_rn(vv.y);
            sVt[(d0+2)*SPAD + r] = __float2half_rn(vv.z);
            sVt[(d0+3)*SPAD + r] = __float2half_rn(vv.w);
        }
    }
    __syncthreads();

    const int wm = wid >> 1, wn = wid & 1;
    const int  aRow = wm*16 + (lane & 15);
    const uint32_t aOff = (uint32_t)(lane >> 4) * 16;
    const int  bRowI = (lane & 7) + ((lane >> 4) << 3);
    const uint32_t bOff = (uint32_t)((lane >> 3) & 1) * 16;
    const uint32_t bRowByte = (uint32_t)(wn*32 + bRowI)*(SPAD*2) + bOff;

    const uint32_t uQ = smem_to_u32(sQ) + (uint32_t)aRow*(SPAD*2) + aOff;
    const uint32_t uK = smem_to_u32(sK) + bRowByte;
    const uint32_t uS = smem_to_u32(sS) + bRowByte;
    const uint32_t uV = smem_to_u32(sVt) + bRowByte;
    const uint32_t uAa = smem_to_u32(sA) + (uint32_t)aRow*(SPAD*2) + aOff;

    float acc1[4][4], acc[4][4];
    #pragma unroll
    for (int nt = 0; nt < 4; ++nt)
        #pragma unroll
        for (int u = 0; u < 4; ++u) { acc1[nt][u] = 0.f; acc[nt][u] = 0.f; }

    // ---- matmul1 (QK^T) + matmul2 (Q @ S) fused over k=d ----
    #pragma unroll
    for (int ks = 0; ks < 4; ++ks) {
        uint32_t a[4], bk0[4], bk1[4], bs0[4], bs1[4];
        ldmatrix_x4(a,   uQ + ks*32);
        ldmatrix_x4(bk0, uK + ks*32);
        ldmatrix_x4(bk1, uK + 16*(SPAD*2) + ks*32);
        ldmatrix_x4(bs0, uS + ks*32);
        ldmatrix_x4(bs1, uS + 16*(SPAD*2) + ks*32);
        mma16816h(acc1[0], a, bk0[0], bk0[1]);
        mma16816h(acc1[1], a, bk0[2], bk0[3]);
        mma16816h(acc1[2], a, bk1[0], bk1[1]);
        mma16816h(acc1[3], a, bk1[2], bk1[3]);
        mma16816h(acc[0],  a, bs0[0], bs0[1]);
        mma16816h(acc[1],  a, bs0[2], bs0[3]);
        mma16816h(acc[2],  a, bs1[0], bs1[1]);
        mma16816h(acc[3],  a, bs1[2], bs1[3]);
    }

    // decay on A_att, store [i][j] fp16
    const int r0 = wm*16 + (lane >> 2), r1 = r0 + 8;
    #pragma unroll
    for (int nt = 0; nt < 4; ++nt) {
        int j0c = wn*32 + nt*8 + 2*(lane & 3);
        float v00 = (j0c   <= r0) ? acc1[nt][0]*exp2f((float)(r0-j0c)*lg)   : 0.f;
        float v01 = (j0c+1 <= r0) ? acc1[nt][1]*exp2f((float)(r0-j0c-1)*lg) : 0.f;
        float v10 = (j0c   <= r1) ? acc1[nt][2]*exp2f((float)(r1-j0c)*lg)   : 0.f;
        float v11 = (j0c+1 <= r1) ? acc1[nt][3]*exp2f((float)(r1-j0c-1)*lg) : 0.f;
        *(__half2*)&sA[r0*SPAD + j0c] = __floats2half2_rn(v00, v01);
        *(__half2*)&sA[r1*SPAD + j0c] = __floats2half2_rn(v10, v11);
    }
    // cross-term scale gamma^i
    {
        float cd0 = exp2f((float)r0 * lg);
        float cd1 = exp2f((float)r1 * lg);
        #pragma unroll
        for (int nt = 0; nt < 4; ++nt) {
            acc[nt][0] *= cd0; acc[nt][1] *= cd0;
            acc[nt][2] *= cd1; acc[nt][3] *= cd1;
        }
    }
    __syncthreads();   // sA visible to all

    // ---- matmul3: O += A_att @ V  (k = j) ----
    #pragma unroll
    for (int ks = 0; ks < 4; ++ks) {
        uint32_t a[4], bv0[4], bv1[4];
        ldmatrix_x4(a,   uAa + ks*32);
        ldmatrix_x4(bv0, uV + ks*32);
        ldmatrix_x4(bv1, uV + 16*(SPAD*2) + ks*32);
        mma16816h(acc[0], a, bv0[0], bv0[1]);
        mma16816h(acc[1], a, bv0[2], bv0[3]);
        mma16816h(acc[2], a, bv1[0], bv1[1]);
        mma16816h(acc[3], a, bv1[2], bv1[3]);
    }

    // ---- GroupNorm over 64 cols per row ----
    float s0 = 0.f, s1 = 0.f, q0 = 0.f, q1 = 0.f;
    #pragma unroll
    for (int nt = 0; nt < 4; ++nt) {
        s0 += acc[nt][0] + acc[nt][1];
        s1 += acc[nt][2] + acc[nt][3];
        q0 = fmaf(acc[nt][0], acc[nt][0], q0); q0 = fmaf(acc[nt][1], acc[nt][1], q0);
        q1 = fmaf(acc[nt][2], acc[nt][2], q1); q1 = fmaf(acc[nt][3], acc[nt][3], q1);
    }
    s0 += __shfl_xor_sync(0xffffffffu, s0, 1); s0 += __shfl_xor_sync(0xffffffffu, s0, 2);
    s1 += __shfl_xor_sync(0xffffffffu, s1, 1); s1 += __shfl_xor_sync(0xffffffffu, s1, 2);
    q0 += __shfl_xor_sync(0xffffffffu, q0, 1); q0 += __shfl_xor_sync(0xffffffffu, q0, 2);
    q1 += __shfl_xor_sync(0xffffffffu, q1, 1); q1 += __shfl_xor_sync(0xffffffffu, q1, 2);
    if ((lane & 3) == 0) {
        sbuf[r0][wn*2]   = s0; sbuf[r0][wn*2+1] = q0;
        sbuf[r1][wn*2]   = s1; sbuf[r1][wn*2+1] = q1;
    }
    __syncthreads();
    float mean0 = (sbuf[r0][0] + sbuf[r0][2]) * (1.0f/64.0f);
    float mq0   = (sbuf[r0][1] + sbuf[r0][3]) * (1.0f/64.0f);
    float mean1 = (sbuf[r1][0] + sbuf[r1][2]) * (1.0f/64.0f);
    float mq1   = (sbuf[r1][1] + sbuf[r1][3]) * (1.0f/64.0f);
    float rstd0 = rsqrtf(mq0 - mean0*mean0 + 1e-5f);
    float rstd1 = rsqrtf(mq1 - mean1*mean1 + 1e-5f);

    #pragma unroll
    for (int nt = 0; nt < 4; ++nt) {
        int colj = wn*32 + nt*8 + 2*(lane & 3);
        float2 w = *(const float2*)(gnw + h*64 + colj);
        float2 bb = *(const float2*)(gnb + h*64 + colj);
        float o00 = fmaf((acc[nt][0]-mean0)*rstd0, w.x, bb.x);
        float o01 = fmaf((acc[nt][1]-mean0)*rstd0, w.y, bb.y);
        float o10 = fmaf((acc[nt][2]-mean1)*rstd1, w.x, bb.x);
        float o11 = fmaf((acc[nt][3]-mean1)*rstd1, w.y, bb.y);
        __half* op0 = g_att16 + ((size_t)(b*Tv + c*64 + r0))*Cv + (size_t)h*64 + colj;
        __half* op1 = g_att16 + ((size_t)(b*Tv + c*64 + r1))*Cv + (size_t)h*64 + colj;
        *(__half2*)op0 = __floats2half2_rn(o00, o01);
        *(__half2*)op1 = __floats2half2_rn(o10, o11);
    }
}

// ---------------------------------------------------------------------------
extern "C" void kernel_launch(void* const* d_in, const int* in_sizes, int n_in,
                              void* d_out, int out_size)
{
    const float* x   = (const float*)d_in[0];
    const float* Wq  = (const float*)d_in[1];
    const float* Wk  = (const float*)d_in[2];
    const float* Wv  = (const float*)d_in[3];
    const float* Wo  = (const float*)d_in[4];
    const float* gnw = (const float*)d_in[5];
    const float* gnb = (const float*)d_in[6];
    float* out = (float*)d_out;

    float *q, *k, *v;
    cudaGetSymbolAddress((void**)&q, g_q);
    cudaGetSymbolAddress((void**)&k, g_k);
    cudaGetSymbolAddress((void**)&v, g_v);
    __half *xh, *att16, *whi;
    cudaGetSymbolAddress((void**)&xh,    g_xh);
    cudaGetSymbolAddress((void**)&att16, g_att16);
    cudaGetSymbolAddress((void**)&whi,   g_whi);

    static bool attr_set = false;
    if (!attr_set) {
        cudaFuncSetAttribute(gemm_qkv,
                             cudaFuncAttributeMaxDynamicSharedMemorySize, GSMEM_TOTAL);
        cudaFuncSetAttribute(gemm_wo,
                             cudaFuncAttributeMaxDynamicSharedMemorySize, GSMEM_TOTAL);
        attr_set = true;
    }

    const int nx4 = (Mv*Cv)/4;
    split_x<<<(nx4+255)/256, 256>>>(x, xh, nx4);
    conv_4w<<<(4*CC/4)/256, 256>>>(Wq, Wk, Wv, Wo, whi);
    rope_table<<<(Tv*32)/256, 256>>>();

    gemm_qkv<<<dim3(24, 32), 256, GSMEM_TOTAL>>>(xh, whi, q, k, v);

    ret_pass1<<<Bv*Hv*NCHUNK, 256>>>();
    ret_pass2<<<(Bv*Hv*4096)/256, 256>>>();
    ret_pass3<<<Bv*Hv*NCHUNK, 256>>>(gnw, gnb);

    gemm_wo<<<dim3(8, 32), 256, GSMEM_TOTAL>>>(att16, whi + (size_t)3*CC, out);
}

// round 16
// speedup vs baseline: 7.0416x; 1.0326x over previous
#include <cuda_runtime.h>
#include <cuda_fp16.h>
#include <math.h>
#include <stdint.h>

#define Bv 2
#define Tv 2048
#define Cv 1024
#define Hv 16
#define DHv 64
#define Mv (Bv*Tv)       // 4096 rows
#define NCHUNK 32        // T / 64
#define CC (Cv*Cv)

// ---------------- scratch (static device memory; no allocs) ----------------
__device__ float g_G[Bv*Hv*NCHUNK*DHv*DHv];                   // G^T: [dv][dk]
__device__ __align__(256) __half g_S16[Bv*Hv*NCHUNK*DHv*DHv]; // S^T fp16
__device__ float g_rope_cos[Tv*32];
__device__ float g_rope_sin[Tv*32];

__device__ __align__(256) __half g_q16[Mv*Cv];
__device__ __align__(256) __half g_k16[Mv*Cv];
__device__ __align__(256) __half g_v16[Mv*Cv];
__device__ __align__(256) __half g_att16[Mv*Cv];     // fp16 retention output
__device__ __align__(256) __half g_xh[Mv*Cv];        // fp16 x
__device__ __align__(256) __half g_whi[4*CC];        // fp16 Wq,Wk,Wv,Wo

// ======================= helpers ===========================================
__device__ __forceinline__ uint32_t smem_to_u32(const void* p) {
    uint32_t a;
    asm("{ .reg .u64 t; cvta.to.shared.u64 t, %1; cvt.u32.u64 %0, t; }" : "=r"(a) : "l"(p));
    return a;
}
__device__ __forceinline__ void ldmatrix_x4(uint32_t* r, uint32_t addr) {
    asm volatile("ldmatrix.sync.aligned.m8n8.x4.shared.b16 {%0,%1,%2,%3}, [%4];"
                 : "=r"(r[0]), "=r"(r[1]), "=r"(r[2]), "=r"(r[3]) : "r"(addr));
}
__device__ __forceinline__ void mma16816h(float* d, const uint32_t* a, uint32_t b0, uint32_t b1) {
    asm volatile(
        "mma.sync.aligned.m16n8k16.row.col.f32.f16.f16.f32 "
        "{%0,%1,%2,%3}, {%4,%5,%6,%7}, {%8,%9}, {%0,%1,%2,%3};"
        : "+f"(d[0]), "+f"(d[1]), "+f"(d[2]), "+f"(d[3])
        : "r"(a[0]), "r"(a[1]), "r"(a[2]), "r"(a[3]), "r"(b0), "r"(b1));
}

// =================== fused prep kernel =====================================
// blocks [0,4096): x -> fp16; [4096,8192): 4 weights -> fp16; [8192,8448): rope table
__global__ void prep_all(const float* __restrict__ x,
                         const float* __restrict__ W0, const float* __restrict__ W1,
                         const float* __restrict__ W2, const float* __restrict__ W3)
{
    int bid = blockIdx.x;
    int tid = threadIdx.x;
    if (bid < 4096) {
        int i = bid*256 + tid;                 // 0 .. Mv*Cv/4
        float4 f = ((const float4*)x)[i];
        __half2* hp = (__half2*)(g_xh + (size_t)i*4);
        hp[0] = __floats2half2_rn(f.x, f.y);
        hp[1] = __floats2half2_rn(f.z, f.w);
    } else if (bid < 8192) {
        int i = (bid - 4096)*256 + tid;        // 0 .. 4*CC/4
        int w = i >> 18;
        const float* s = (w==0) ? W0 : (w==1) ? W1 : (w==2) ? W2 : W3;
        int j = i & 262143;
        float4 f = ((const float4*)s)[j];
        __half2* hp = (__half2*)(g_whi + (size_t)i*4);
        hp[0] = __floats2half2_rn(f.x, f.y);
        hp[1] = __floats2half2_rn(f.z, f.w);
    } else {
        int i = (bid - 8192)*256 + tid;        // 0..65535
        int dm = i & 31, t = i >> 5;
        float inv = exp2f(-(float)dm * (13.287712379549449f / 32.0f));
        float ang = (float)t * inv;
        float s, c;
        sincosf(ang, &s, &c);
        g_rope_cos[i] = c;
        g_rope_sin[i] = s;
    }
}

// =================== fp16 1-term QKV GEMM (rope fused, fp16 out) ===========
#define GTILE_SZ 16384          // 128 rows x 128 bytes
#define GBUF_SZ  (2*GTILE_SZ)   // A, B
#define GSMEM_TOTAL (3*GBUF_SZ) // 98304 (also covers 64KB fp32 staging)

__global__ __launch_bounds__(256, 2)
void gemm_qkv(const __half* __restrict__ A,
              const __half* __restrict__ Bh,
              __half* __restrict__ o0, __half* __restrict__ o1, __half* __restrict__ o2)
{
    extern __shared__ char smem[];
    const uint32_t sb = smem_to_u32(smem);
    const int tid  = threadIdx.x;
    const int lane = tid & 31;
    const int wid  = tid >> 5;
    const int wm   = wid & 1;
    const int wn   = wid >> 1;
    const int K = Cv;

    const size_t rowA0 = (size_t)blockIdx.y * 128;
    const size_t rowB0 = (size_t)blockIdx.x * 128;
    const int which   = blockIdx.x >> 3;            // 0=q 1=k 2=v
    __half* C = (which == 0) ? o0 : (which == 1) ? o1 : o2;
    const int colBase = (blockIdx.x & 7) * 128;

    const __half* tps[2] = { A + rowA0*K, Bh + rowB0*K };

    auto load_chunk = [&](int k0, int b) {
        const uint32_t dst = sb + b * GBUF_SZ;
        #pragma unroll
        for (int t = 0; t < 2; ++t) {
            const __half* gp = tps[t] + k0;
            const uint32_t td = dst + t * GTILE_SZ;
            #pragma unroll
            for (int i = 0; i < 4; ++i) {
                int v = tid + i * 256;
                int row = v >> 3, colv = v & 7;
                uint32_t boff = row * 128 + colv * 16;
                uint32_t sw = boff ^ ((boff >> 3) & 0x70);
                const void* src = gp + (size_t)row * K + colv * 8;
                asm volatile("cp.async.cg.shared.global [%0], [%1], 16;"
                             :: "r"(td + sw), "l"(src) : "memory");
            }
        }
        asm volatile("cp.async.commit_group;" ::: "memory");
    };

    float acc[4][4][4];
    #pragma unroll
    for (int mt = 0; mt < 4; ++mt)
        #pragma unroll
        for (int nt = 0; nt < 4; ++nt)
            #pragma unroll
            for (int u = 0; u < 4; ++u) acc[mt][nt][u] = 0.f;

    const int  a_r    = lane & 15;
    const uint32_t a_hi = (uint32_t)(lane >> 4) * 16;
    const int  b_r    = (lane & 7) + ((lane >> 4) << 3);
    const uint32_t b_hi = (uint32_t)((lane >> 3) & 1) * 16;

    load_chunk(0, 0);
    load_chunk(64, 1);

    for (int c = 0; c < 16; ++c) {
        if (c < 15) {
            asm volatile("cp.async.wait_group 1;" ::: "memory");
        } else {
            asm volatile("cp.async.wait_group 0;" ::: "memory");
        }
        __syncthreads();
        if (c <= 13) load_chunk((c + 2) * 64, (c + 2) % 3);

        const uint32_t base = sb + (c % 3) * GBUF_SZ;
        const uint32_t aT = base, bH = base + GTILE_SZ;

        #pragma unroll
        for (int ks = 0; ks < 4; ++ks) {
            const uint32_t kb = ks * 32;
            uint32_t a[4][4], bh[2][4];
            #pragma unroll
            for (int mt = 0; mt < 4; ++mt) {
                int row = wm*64 + mt*16 + a_r;
                uint32_t off = (uint32_t)row*128 + (((kb + a_hi) ^ ((row & 7) << 4)));
                ldmatrix_x4(a[mt], aT + off);
            }
            #pragma unroll
            for (int ntp = 0; ntp < 2; ++ntp) {
                int row = wn*32 + ntp*16 + b_r;
                uint32_t off = (uint32_t)row*128 + (((kb + b_hi) ^ ((row & 7) << 4)));
                ldmatrix_x4(bh[ntp], bH + off);
            }
            #pragma unroll
            for (int mt = 0; mt < 4; ++mt) {
                #pragma unroll
                for (int nt = 0; nt < 4; ++nt) {
                    uint32_t b0 = bh[nt >> 1][(nt & 1)*2 + 0];
                    uint32_t b1 = bh[nt >> 1][(nt & 1)*2 + 1];
                    mma16816h(acc[mt][nt], a[mt], b0, b1);
                }
            }
        }
        __syncthreads();
    }

    // ---- stage tile fp32, apply rope (q,k), store fp16 ----
    float* st = (float*)smem;
    #pragma unroll
    for (int mt = 0; mt < 4; ++mt) {
        int r = wm*64 + mt*16 + (lane >> 2);
        #pragma unroll
        for (int nt = 0; nt < 4; ++nt) {
            int col = wn*32 + nt*8 + 2*(lane & 3);
            *(float2*)&st[r*128 + col]       = make_float2(acc[mt][nt][0], acc[mt][nt][1]);
            *(float2*)&st[(r+8)*128 + col]   = make_float2(acc[mt][nt][2], acc[mt][nt][3]);
        }
    }
    __syncthreads();

    #pragma unroll 4
    for (int it = 0; it < 32; ++it) {
        int unit = tid + it*256;
        int row = unit >> 6;
        int col = (unit & 63) * 2;
        float2 val = *(float2*)&st[row*128 + col];
        float2 res = val;
        if (which < 2) {
            int gr = (int)rowA0 + row;
            int tt = gr & (Tv-1);
            int d = col & 63;
            float2 par;
            if (d < 32) {
                par = *(float2*)&st[row*128 + col + 32];
                par.x = -par.x; par.y = -par.y;
            } else {
                par = *(float2*)&st[row*128 + col - 32];
            }
            int dm = d & 31;
            float2 cc = *(const float2*)&g_rope_cos[tt*32 + dm];
            float2 ss = *(const float2*)&g_rope_sin[tt*32 + dm];
            res.x = val.x*cc.x + par.x*ss.x;
            res.y = val.y*cc.y + par.y*ss.y;
        }
        *(__half2*)(C + ((size_t)rowA0 + row)*Cv + colBase + col) = __floats2half2_rn(res.x, res.y);
    }
}

// =================== fp16 1-term Wo GEMM (3-stage) =========================
__global__ __launch_bounds__(256, 2)
void gemm_wo(const __half* __restrict__ A,
             const __half* __restrict__ Bh,
             float* __restrict__ C)
{
    extern __shared__ char smem[];
    const uint32_t sb = smem_to_u32(smem);
    const int tid  = threadIdx.x;
    const int lane = tid & 31;
    const int wid  = tid >> 5;
    const int wm   = wid & 1;
    const int wn   = wid >> 1;
    const int K = Cv;

    const size_t rowA0 = (size_t)blockIdx.y * 128;
    const size_t rowB0 = (size_t)blockIdx.x * 128;
    const int colBase  = blockIdx.x * 128;

    const __half* tps[2] = { A + rowA0*K, Bh + rowB0*K };

    auto load_chunk = [&](int k0, int b) {
        const uint32_t dst = sb + b * GBUF_SZ;
        #pragma unroll
        for (int t = 0; t < 2; ++t) {
            const __half* gp = tps[t] + k0;
            const uint32_t td = dst + t * GTILE_SZ;
            #pragma unroll
            for (int i = 0; i < 4; ++i) {
                int v = tid + i * 256;
                int row = v >> 3, colv = v & 7;
                uint32_t boff = row * 128 + colv * 16;
                uint32_t sw = boff ^ ((boff >> 3) & 0x70);
                const void* src = gp + (size_t)row * K + colv * 8;
                asm volatile("cp.async.cg.shared.global [%0], [%1], 16;"
                             :: "r"(td + sw), "l"(src) : "memory");
            }
        }
        asm volatile("cp.async.commit_group;" ::: "memory");
    };

    float acc[4][4][4];
    #pragma unroll
    for (int mt = 0; mt < 4; ++mt)
        #pragma unroll
        for (int nt = 0; nt < 4; ++nt)
            #pragma unroll
            for (int u = 0; u < 4; ++u) acc[mt][nt][u] = 0.f;

    const int  a_r    = lane & 15;
    const uint32_t a_hi = (uint32_t)(lane >> 4) * 16;
    const int  b_r    = (lane & 7) + ((lane >> 4) << 3);
    const uint32_t b_hi = (uint32_t)((lane >> 3) & 1) * 16;

    load_chunk(0, 0);
    load_chunk(64, 1);

    for (int c = 0; c < 16; ++c) {
        if (c < 15) {
            asm volatile("cp.async.wait_group 1;" ::: "memory");
        } else {
            asm volatile("cp.async.wait_group 0;" ::: "memory");
        }
        __syncthreads();
        if (c <= 13) load_chunk((c + 2) * 64, (c + 2) % 3);

        const uint32_t base = sb + (c % 3) * GBUF_SZ;
        const uint32_t aT = base, bH = base + GTILE_SZ;

        #pragma unroll
        for (int ks = 0; ks < 4; ++ks) {
            const uint32_t kb = ks * 32;
            uint32_t a[4][4], bh[2][4];
            #pragma unroll
            for (int mt = 0; mt < 4; ++mt) {
                int row = wm*64 + mt*16 + a_r;
                uint32_t off = (uint32_t)row*128 + (((kb + a_hi) ^ ((row & 7) << 4)));
                ldmatrix_x4(a[mt], aT + off);
            }
            #pragma unroll
            for (int ntp = 0; ntp < 2; ++ntp) {
                int row = wn*32 + ntp*16 + b_r;
                uint32_t off = (uint32_t)row*128 + (((kb + b_hi) ^ ((row & 7) << 4)));
                ldmatrix_x4(bh[ntp], bH + off);
            }
            #pragma unroll
            for (int mt = 0; mt < 4; ++mt) {
                #pragma unroll
                for (int nt = 0; nt < 4; ++nt) {
                    uint32_t b0 = bh[nt >> 1][(nt & 1)*2 + 0];
                    uint32_t b1 = bh[nt >> 1][(nt & 1)*2 + 1];
                    mma16816h(acc[mt][nt], a[mt], b0, b1);
                }
            }
        }
        __syncthreads();
    }

    #pragma unroll
    for (int mt = 0; mt < 4; ++mt) {
        int r0 = (int)rowA0 + wm*64 + mt*16 + (lane >> 2);
        #pragma unroll
        for (int nt = 0; nt < 4; ++nt) {
            int col = colBase + wn*32 + nt*8 + 2*(lane & 3);
            *(float2*)(C + (size_t)r0 * Cv + col)       = make_float2(acc[mt][nt][0], acc[mt][nt][1]);
            *(float2*)(C + (size_t)(r0 + 8) * Cv + col) = make_float2(acc[mt][nt][2], acc[mt][nt][3]);
        }
    }
}

// ---------------- Pass 1: per-chunk local state via fp16 mma ---------------
#define SPAD 72   // fp16 row stride (144 B) - conflict-free ldmatrix

__global__ __launch_bounds__(256)
void ret_pass1()
{
    __shared__ __align__(16) unsigned char sm[2*SPAD*64*2];  // 18432 B
    __half* sKdT = (__half*)sm;               // [dk][j]
    __half* sVt  = (__half*)(sm + SPAD*64*2); // [dv][j]
    float*  sG   = (float*)sm;                // overlay: [dv][dk] fp32 (16KB)

    const int blk = blockIdx.x;
    const int c   = blk & 31;
    const int h   = (blk >> 5) & 15;
    const int b   = blk >> 9;
    const int tid = threadIdx.x;
    const int lane = tid & 31;
    const int wid  = tid >> 5;
    const float gamma = 1.0f - exp2f(-5.0f - (float)h);
    const float lg = log2f(gamma);
    const size_t rowbase = ((size_t)(b*Tv + c*64))*Cv + (size_t)h*64;
    const int fq = tid & 15;

    // stage transposed fp16 (inputs already fp16)
    for (int r = tid >> 4; r < 64; r += 16) {
        float w = exp2f((float)(64 - r) * lg);
        uint2 kraw = *(const uint2*)(g_k16 + rowbase + (size_t)r*Cv + fq*4);
        uint2 vraw = *(const uint2*)(g_v16 + rowbase + (size_t)r*Cv + fq*4);
        float2 k01 = __half22float2(*(__half2*)&kraw.x);
        float2 k23 = __half22float2(*(__half2*)&kraw.y);
        __half va[4]; *(uint2*)va = vraw;
        int d0 = fq*4;
        sKdT[(d0+0)*SPAD + r] = __float2half_rn(k01.x * w);
        sKdT[(d0+1)*SPAD + r] = __float2half_rn(k01.y * w);
        sKdT[(d0+2)*SPAD + r] = __float2half_rn(k23.x * w);
        sKdT[(d0+3)*SPAD + r] = __float2half_rn(k23.y * w);
        sVt[(d0+0)*SPAD + r] = va[0];
        sVt[(d0+1)*SPAD + r] = va[1];
        sVt[(d0+2)*SPAD + r] = va[2];
        sVt[(d0+3)*SPAD + r] = va[3];
    }
    __syncthreads();

    const int wm = wid >> 1, wn = wid & 1;
    const int  aRow = wm*16 + (lane & 15);
    const uint32_t aOff = (uint32_t)(lane >> 4) * 16;
    const int  bRow = (lane & 7) + ((lane >> 4) << 3);
    const uint32_t bOff = (uint32_t)((lane >> 3) & 1) * 16;

    const uint32_t uA  = smem_to_u32(sKdT) + (uint32_t)aRow*(SPAD*2) + aOff;
    const uint32_t uB0 = smem_to_u32(sVt) + (uint32_t)(wn*32 + bRow)*(SPAD*2) + bOff;
    const uint32_t uB1 = uB0 + 16*(SPAD*2);

    float acc[4][4];
    #pragma unroll
    for (int nt = 0; nt < 4; ++nt)
        #pragma unroll
        for (int u = 0; u < 4; ++u) acc[nt][u] = 0.f;

    #pragma unroll
    for (int ks = 0; ks < 4; ++ks) {
        uint32_t a[4], b0[4], b1[4];
        ldmatrix_x4(a,  uA  + ks*32);
        ldmatrix_x4(b0, uB0 + ks*32);
        ldmatrix_x4(b1, uB1 + ks*32);
        mma16816h(acc[0], a, b0[0], b0[1]);
        mma16816h(acc[1], a, b0[2], b0[3]);
        mma16816h(acc[2], a, b1[0], b1[1]);
        mma16816h(acc[3], a, b1[2], b1[3]);
    }
    __syncthreads();

    // scatter to sG as [dv][dk]
    const int r0 = wm*16 + (lane >> 2), r1 = r0 + 8;   // dk
    #pragma unroll
    for (int nt = 0; nt < 4; ++nt) {
        int col = wn*32 + nt*8 + 2*(lane & 3);          // dv
        sG[col*64 + r0]     = acc[nt][0];
        sG[(col+1)*64 + r0] = acc[nt][1];
        sG[col*64 + r1]     = acc[nt][2];
        sG[(col+1)*64 + r1] = acc[nt][3];
    }
    __syncthreads();

    float* Gp = g_G + (size_t)blk*4096;
    #pragma unroll
    for (int u = 0; u < 4; ++u)
        *(float4*)(Gp + tid*16 + u*4) = *(const float4*)&sG[tid*16 + u*4];
}

// ---------------- Pass 2: parallel elementwise scan (fp16 S out) -----------
__global__ void ret_pass2()
{
    int el = blockIdx.x*blockDim.x + threadIdx.x;  // 0 .. 131071
    int bh  = el >> 12;
    int idx = el & 4095;
    int h   = bh & 15;
    const float gamma = 1.0f - exp2f(-5.0f - (float)h);
    const float gL = exp2f(64.0f * log2f(gamma));
    float s = 0.f;
    size_t e = (size_t)bh*NCHUNK*4096 + idx;
    #pragma unroll 8
    for (int c = 0; c < NCHUNK; ++c, e += 4096) {
        g_S16[e] = __float2half_rn(s);
        s = fmaf(gL, s, g_G[e]);
    }
}

// ---------------- Pass 3: retention core via fp16 mma + fused GroupNorm ----
__global__ __launch_bounds__(256)
void ret_pass3(const float* __restrict__ gnw, const float* __restrict__ gnb)
{
    __shared__ __align__(16) __half sQ[64*SPAD];   // [i][d] * 0.125
    __shared__ __align__(16) __half sK[64*SPAD];   // [j][d]
    __shared__ __align__(16) __half sVt[64*SPAD];  // [dv][j]
    __shared__ __align__(16) __half sS[64*SPAD];   // [dv][dk]  (S^T)
    __shared__ __align__(16) __half sA[64*SPAD];   // [i][j]
    __shared__ float sbuf[64][4];

    const int blk = blockIdx.x;
    const int c   = blk & 31;
    const int h   = (blk >> 5) & 15;
    const int b   = blk >> 9;
    const int tid = threadIdx.x;
    const int lane = tid & 31;
    const int wid  = tid >> 5;
    const float gamma = 1.0f - exp2f(-5.0f - (float)h);
    const float lg = log2f(gamma);
    const size_t rowbase = ((size_t)(b*Tv + c*64))*Cv + (size_t)h*64;

    // ---- staging (fp16 inputs; 0.125 scale is exact in fp16) ----
    {
        int r4 = tid >> 2, q4 = tid & 3;
        const uint4* qp = (const uint4*)(g_q16 + rowbase + (size_t)r4*Cv);
        const uint4* kp = (const uint4*)(g_k16 + rowbase + (size_t)r4*Cv);
        const __half2 sc = __half2half2(__float2half(0.125f));
        #pragma unroll
        for (int u = 0; u < 2; ++u) {
            uint4 qa = qp[q4*2 + u];
            __half2* qh = (__half2*)&qa;
            qh[0] = __hmul2(qh[0], sc); qh[1] = __hmul2(qh[1], sc);
            qh[2] = __hmul2(qh[2], sc); qh[3] = __hmul2(qh[3], sc);
            *(uint4*)&sQ[r4*SPAD + q4*16 + u*8] = qa;
            *(uint4*)&sK[r4*SPAD + q4*16 + u*8] = kp[q4*2 + u];
        }
        // S^T rows (fp16 direct copy)
        const uint4* sp = (const uint4*)(g_S16 + (size_t)blk*4096);
        *(uint4*)&sS[r4*SPAD + q4*16]     = sp[r4*8 + q4*2];
        *(uint4*)&sS[r4*SPAD + q4*16 + 8] = sp[r4*8 + q4*2 + 1];
    }
    {   // V transposed
        const int fq = tid & 15;
        for (int r = tid >> 4; r < 64; r += 16) {
            uint2 vraw = *(const uint2*)(g_v16 + rowbase + (size_t)r*Cv + fq*4);
            __half va[4]; *(uint2*)va = vraw;
            int d0 = fq*4;
            sVt[(d0+0)*SPAD + r] = va[0];
            sVt[(d0+1)*SPAD + r] = va[1];
            sVt[(d0+2)*SPAD + r] = va[2];
            sVt[(d0+3)*SPAD + r] = va[3];
        }
    }
    __syncthreads();

    const int wm = wid >> 1, wn = wid & 1;
    const int  aRow = wm*16 + (lane & 15);
    const uint32_t aOff = (uint32_t)(lane >> 4) * 16;
    const int  bRowI = (lane & 7) + ((lane >> 4) << 3);
    const uint32_t bOff = (uint32_t)((lane >> 3) & 1) * 16;
    const uint32_t bRowByte = (uint32_t)(wn*32 + bRowI)*(SPAD*2) + bOff;

    const uint32_t uQ = smem_to_u32(sQ) + (uint32_t)aRow*(SPAD*2) + aOff;
    const uint32_t uK = smem_to_u32(sK) + bRowByte;
    const uint32_t uS = smem_to_u32(sS) + bRowByte;
    const uint32_t uV = smem_to_u32(sVt) + bRowByte;
    const uint32_t uAa = smem_to_u32(sA) + (uint32_t)aRow*(SPAD*2) + aOff;

    float acc1[4][4], acc[4][4];
    #pragma unroll
    for (int nt = 0; nt < 4; ++nt)
        #pragma unroll
        for (int u = 0; u < 4; ++u) { acc1[nt][u] = 0.f; acc[nt][u] = 0.f; }

    // ---- matmul1 (QK^T) + matmul2 (Q @ S) fused over k=d ----
    #pragma unroll
    for (int ks = 0; ks < 4; ++ks) {
        uint32_t a[4], bk0[4], bk1[4], bs0[4], bs1[4];
        ldmatrix_x4(a,   uQ + ks*32);
        ldmatrix_x4(bk0, uK + ks*32);
        ldmatrix_x4(bk1, uK + 16*(SPAD*2) + ks*32);
        ldmatrix_x4(bs0, uS + ks*32);
        ldmatrix_x4(bs1, uS + 16*(SPAD*2) + ks*32);
        mma16816h(acc1[0], a, bk0[0], bk0[1]);
        mma16816h(acc1[1], a, bk0[2], bk0[3]);
        mma16816h(acc1[2], a, bk1[0], bk1[1]);
        mma16816h(acc1[3], a, bk1[2], bk1[3]);
        mma16816h(acc[0],  a, bs0[0], bs0[1]);
        mma16816h(acc[1],  a, bs0[2], bs0[3]);
        mma16816h(acc[2],  a, bs1[0], bs1[1]);
        mma16816h(acc[3],  a, bs1[2], bs1[3]);
    }

    // decay on A_att, store [i][j] fp16
    const int r0 = wm*16 + (lane >> 2), r1 = r0 + 8;
    #pragma unroll
    for (int nt = 0; nt < 4; ++nt) {
        int j0c = wn*32 + nt*8 + 2*(lane & 3);
        float v00 = (j0c   <= r0) ? acc1[nt][0]*exp2f((float)(r0-j0c)*lg)   : 0.f;
        float v01 = (j0c+1 <= r0) ? acc1[nt][1]*exp2f((float)(r0-j0c-1)*lg) : 0.f;
        float v10 = (j0c   <= r1) ? acc1[nt][2]*exp2f((float)(r1-j0c)*lg)   : 0.f;
        float v11 = (j0c+1 <= r1) ? acc1[nt][3]*exp2f((float)(r1-j0c-1)*lg) : 0.f;
        *(__half2*)&sA[r0*SPAD + j0c] = __floats2half2_rn(v00, v01);
        *(__half2*)&sA[r1*SPAD + j0c] = __floats2half2_rn(v10, v11);
    }
    // cross-term scale gamma^i
    {
        float cd0 = exp2f((float)r0 * lg);
        float cd1 = exp2f((float)r1 * lg);
        #pragma unroll
        for (int nt = 0; nt < 4; ++nt) {
            acc[nt][0] *= cd0; acc[nt][1] *= cd0;
            acc[nt][2] *= cd1; acc[nt][3] *= cd1;
        }
    }
    __syncthreads();   // sA visible to all

    // ---- matmul3: O += A_att @ V  (k = j) ----
    #pragma unroll
    for (int ks = 0; ks < 4; ++ks) {
        uint32_t a[4], bv0[4], bv1[4];
        ldmatrix_x4(a,   uAa + ks*32);
        ldmatrix_x4(bv0, uV + ks*32);
        ldmatrix_x4(bv1, uV + 16*(SPAD*2) + ks*32);
        mma16816h(acc[0], a, bv0[0], bv0[1]);
        mma16816h(acc[1], a, bv0[2], bv0[3]);
        mma16816h(acc[2], a, bv1[0], bv1[1]);
        mma16816h(acc[3], a, bv1[2], bv1[3]);
    }

    // ---- GroupNorm over 64 cols per row ----
    float s0 = 0.f, s1 = 0.f, q0 = 0.f, q1 = 0.f;
    #pragma unroll
    for (int nt = 0; nt < 4; ++nt) {
        s0 += acc[nt][0] + acc[nt][1];
        s1 += acc[nt][2] + acc[nt][3];
        q0 = fmaf(acc[nt][0], acc[nt][0], q0); q0 = fmaf(acc[nt][1], acc[nt][1], q0);
        q1 = fmaf(acc[nt][2], acc[nt][2], q1); q1 = fmaf(acc[nt][3], acc[nt][3], q1);
    }
    s0 += __shfl_xor_sync(0xffffffffu, s0, 1); s0 += __shfl_xor_sync(0xffffffffu, s0, 2);
    s1 += __shfl_xor_sync(0xffffffffu, s1, 1); s1 += __shfl_xor_sync(0xffffffffu, s1, 2);
    q0 += __shfl_xor_sync(0xffffffffu, q0, 1); q0 += __shfl_xor_sync(0xffffffffu, q0, 2);
    q1 += __shfl_xor_sync(0xffffffffu, q1, 1); q1 += __shfl_xor_sync(0xffffffffu, q1, 2);
    if ((lane & 3) == 0) {
        sbuf[r0][wn*2]   = s0; sbuf[r0][wn*2+1] = q0;
        sbuf[r1][wn*2]   = s1; sbuf[r1][wn*2+1] = q1;
    }
    __syncthreads();
    float mean0 = (sbuf[r0][0] + sbuf[r0][2]) * (1.0f/64.0f);
    float mq0   = (sbuf[r0][1] + sbuf[r0][3]) * (1.0f/64.0f);
    float mean1 = (sbuf[r1][0] + sbuf[r1][2]) * (1.0f/64.0f);
    float mq1   = (sbuf[r1][1] + sbuf[r1][3]) * (1.0f/64.0f);
    float rstd0 = rsqrtf(mq0 - mean0*mean0 + 1e-5f);
    float rstd1 = rsqrtf(mq1 - mean1*mean1 + 1e-5f);

    #pragma unroll
    for (int nt = 0; nt < 4; ++nt) {
        int colj = wn*32 + nt*8 + 2*(lane & 3);
        float2 w = *(const float2*)(gnw + h*64 + colj);
        float2 bb = *(const float2*)(gnb + h*64 + colj);
        float o00 = fmaf((acc[nt][0]-mean0)*rstd0, w.x, bb.x);
        float o01 = fmaf((acc[nt][1]-mean0)*rstd0, w.y, bb.y);
        float o10 = fmaf((acc[nt][2]-mean1)*rstd1, w.x, bb.x);
        float o11 = fmaf((acc[nt][3]-mean1)*rstd1, w.y, bb.y);
        __half* op0 = g_att16 + ((size_t)(b*Tv + c*64 + r0))*Cv + (size_t)h*64 + colj;
        __half* op1 = g_att16 + ((size_t)(b*Tv + c*64 + r1))*Cv + (size_t)h*64 + colj;
        *(__half2*)op0 = __floats2half2_rn(o00, o01);
        *(__half2*)op1 = __floats2half2_rn(o10, o11);
    }
}

// ---------------------------------------------------------------------------
extern "C" void kernel_launch(void* const* d_in, const int* in_sizes, int n_in,
                              void* d_out, int out_size)
{
    const float* x   = (const float*)d_in[0];
    const float* Wq  = (const float*)d_in[1];
    const float* Wk  = (const float*)d_in[2];
    const float* Wv  = (const float*)d_in[3];
    const float* Wo  = (const float*)d_in[4];
    const float* gnw = (const float*)d_in[5];
    const float* gnb = (const float*)d_in[6];
    float* out = (float*)d_out;

    __half *q16, *k16, *v16, *xh, *att16, *whi;
    cudaGetSymbolAddress((void**)&q16,   g_q16);
    cudaGetSymbolAddress((void**)&k16,   g_k16);
    cudaGetSymbolAddress((void**)&v16,   g_v16);
    cudaGetSymbolAddress((void**)&xh,    g_xh);
    cudaGetSymbolAddress((void**)&att16, g_att16);
    cudaGetSymbolAddress((void**)&whi,   g_whi);

    static bool attr_set = false;
    if (!attr_set) {
        cudaFuncSetAttribute(gemm_qkv,
                             cudaFuncAttributeMaxDynamicSharedMemorySize, GSMEM_TOTAL);
        cudaFuncSetAttribute(gemm_wo,
                             cudaFuncAttributeMaxDynamicSharedMemorySize, GSMEM_TOTAL);
        attr_set = true;
    }

    prep_all<<<8448, 256>>>(x, Wq, Wk, Wv, Wo);

    gemm_qkv<<<dim3(24, 32), 256, GSMEM_TOTAL>>>(xh, whi, q16, k16, v16);

    ret_pass1<<<Bv*Hv*NCHUNK, 256>>>();
    ret_pass2<<<(Bv*Hv*4096)/256, 256>>>();
    ret_pass3<<<Bv*Hv*NCHUNK, 256>>>(gnw, gnb);

    gemm_wo<<<dim3(8, 32), 256, GSMEM_TOTAL>>>(att16, whi + (size_t)3*CC, out);
}